// round 4
// baseline (speedup 1.0000x reference)
#include <cuda_runtime.h>
#include <math.h>

// ---------------------------------------------------------------------------
// Problem constants
// ---------------------------------------------------------------------------
#define B_  2
#define S_  2048
#define D_  1024
#define H_  16
#define DK_ 64
#define FF_ 4096
#define L_  6
#define M_  (B_*S_)          // 4096 rows

// ---------------------------------------------------------------------------
// Scratch (device globals — no allocations allowed)
// ---------------------------------------------------------------------------
__device__ float g_x[M_*D_];                 // running activation
__device__ float g_q[M_*D_];
__device__ float g_k[M_*D_];
__device__ float g_v[M_*D_];
__device__ float g_a[M_*D_];                 // attention concat output
__device__ float g_r[M_*D_];                 // proj / ff output (residual branch)
__device__ float g_h[M_*FF_];                // ff hidden
__device__ float g_s[134217728];             // scores  [B*H, S, S]  (512 MB)
__device__ float g_pe[B_*D_];                // positional encoding

// ---------------------------------------------------------------------------
// Reductions
// ---------------------------------------------------------------------------
__device__ __forceinline__ float warpSum(float v) {
    #pragma unroll
    for (int o = 16; o; o >>= 1) v += __shfl_xor_sync(0xffffffffu, v, o);
    return v;
}
__device__ __forceinline__ float warpMax(float v) {
    #pragma unroll
    for (int o = 16; o; o >>= 1) v = fmaxf(v, __shfl_xor_sync(0xffffffffu, v, o));
    return v;
}
// 256-thread block reduce (8 warps). sh must hold 8 floats.
__device__ __forceinline__ float blockSum(float v, float* sh) {
    int tid = threadIdx.x, lane = tid & 31, w = tid >> 5;
    v = warpSum(v);
    if (lane == 0) sh[w] = v;
    __syncthreads();
    float t = sh[0];
    #pragma unroll
    for (int i = 1; i < 8; i++) t += sh[i];
    __syncthreads();
    return t;
}
__device__ __forceinline__ float blockMax(float v, float* sh) {
    int tid = threadIdx.x, lane = tid & 31, w = tid >> 5;
    v = warpMax(v);
    if (lane == 0) sh[w] = v;
    __syncthreads();
    float t = sh[0];
    #pragma unroll
    for (int i = 1; i < 8; i++) t = fmaxf(t, sh[i]);
    __syncthreads();
    return t;
}

// ---------------------------------------------------------------------------
// Positional encoding.  Faithful to the reference fp32 chain:
//   div = fp32(exp(2i * (-ln(1e4)/D)));  angle = fp32(b / div);  sin/cos fp32.
// We round div to fp32 exactly (double exp then cast), form the fp32 angle,
// then take the *correctly rounded* sin/cos of that fp32 angle via double.
// ---------------------------------------------------------------------------
__global__ void pe_kernel(float* __restrict__ pe) {
    int idx = blockIdx.x * blockDim.x + threadIdx.x;
    if (idx >= B_*D_) return;
    int b = idx / D_, d = idx % D_;
    int i = d >> 1;
    double c = -log(10000.0) / (double)D_;
    float divf = (float)exp((double)(2*i) * c);
    float ang  = (float)b / divf;
    double ad  = (double)ang;
    pe[idx] = (d & 1) ? (float)cos(ad) : (float)sin(ad);
}

__global__ void embed_kernel(const int* __restrict__ src,
                             const float* __restrict__ emb,
                             const float* __restrict__ pe,
                             float* __restrict__ x) {
    int idx = blockIdx.x * blockDim.x + threadIdx.x;
    if (idx >= M_*D_) return;
    int d  = idx & (D_-1);
    int bs = idx >> 10;          // row in [0, B*S)
    int b  = bs >> 11;           // S = 2048
    x[idx] = emb[(size_t)src[bs]*D_ + d] + pe[b*D_ + d];
}

// ---------------------------------------------------------------------------
// SGEMM: C[M,N] = A[M,K] @ W[K,N] + bias[N], optional ReLU.
// 128x128 block tile, Kt=8, 256 threads, 8x8 per-thread register tile.
// Requires M%128==0, N%128==0, K%8==0 (true for all shapes here).
// ---------------------------------------------------------------------------
__global__ __launch_bounds__(256)
void sgemm(const float* __restrict__ A, const float* __restrict__ W,
           const float* __restrict__ bias, float* __restrict__ C,
           int M, int N, int K, int relu) {
    __shared__ float As[8][128];   // [k][m]
    __shared__ float Ws[8][128];   // [k][n]
    int tid = threadIdx.x;
    int m0 = blockIdx.y * 128, n0 = blockIdx.x * 128;

    int arow = tid >> 1;             // 0..127
    int acol = (tid & 1) * 4;        // 0 or 4
    int wrow = tid >> 5;             // 0..7
    int wcol = (tid & 31) * 4;       // 0..124
    const float* Aptr = A + (size_t)(m0 + arow) * K + acol;
    const float* Wptr = W + (size_t)wrow * N + n0 + wcol;

    int ty = tid >> 4, tx = tid & 15;
    float acc[8][8];
    #pragma unroll
    for (int i = 0; i < 8; i++)
        #pragma unroll
        for (int j = 0; j < 8; j++) acc[i][j] = 0.f;

    for (int k0 = 0; k0 < K; k0 += 8) {
        float4 av = *(const float4*)(Aptr + k0);
        float4 wv = *(const float4*)(Wptr + (size_t)k0 * N);
        As[acol+0][arow] = av.x; As[acol+1][arow] = av.y;
        As[acol+2][arow] = av.z; As[acol+3][arow] = av.w;
        *(float4*)&Ws[wrow][wcol] = wv;
        __syncthreads();
        #pragma unroll
        for (int kk = 0; kk < 8; kk++) {
            float4 a0 = *(const float4*)&As[kk][ty*8];
            float4 a1 = *(const float4*)&As[kk][ty*8+4];
            float4 b0 = *(const float4*)&Ws[kk][tx*8];
            float4 b1 = *(const float4*)&Ws[kk][tx*8+4];
            float a[8] = {a0.x,a0.y,a0.z,a0.w,a1.x,a1.y,a1.z,a1.w};
            float b[8] = {b0.x,b0.y,b0.z,b0.w,b1.x,b1.y,b1.z,b1.w};
            #pragma unroll
            for (int i = 0; i < 8; i++)
                #pragma unroll
                for (int j = 0; j < 8; j++)
                    acc[i][j] += a[i]*b[j];
        }
        __syncthreads();
    }

    float4 bb0 = *(const float4*)(bias + n0 + tx*8);
    float4 bb1 = *(const float4*)(bias + n0 + tx*8 + 4);
    #pragma unroll
    for (int i = 0; i < 8; i++) {
        int m = m0 + ty*8 + i;
        float4 o0, o1;
        o0.x = acc[i][0]+bb0.x; o0.y = acc[i][1]+bb0.y;
        o0.z = acc[i][2]+bb0.z; o0.w = acc[i][3]+bb0.w;
        o1.x = acc[i][4]+bb1.x; o1.y = acc[i][5]+bb1.y;
        o1.z = acc[i][6]+bb1.z; o1.w = acc[i][7]+bb1.w;
        if (relu) {
            o0.x = fmaxf(o0.x,0.f); o0.y = fmaxf(o0.y,0.f);
            o0.z = fmaxf(o0.z,0.f); o0.w = fmaxf(o0.w,0.f);
            o1.x = fmaxf(o1.x,0.f); o1.y = fmaxf(o1.y,0.f);
            o1.z = fmaxf(o1.z,0.f); o1.w = fmaxf(o1.w,0.f);
        }
        *(float4*)(C + (size_t)m*N + n0 + tx*8)     = o0;
        *(float4*)(C + (size_t)m*N + n0 + tx*8 + 4) = o1;
    }
}

// ---------------------------------------------------------------------------
// scores[bh, q, k] = (q . k)/32, masked.  64x64 output tile per block, K=64.
// Q,K stored as [B,S,D] with head h at columns [h*64, h*64+64).
// ---------------------------------------------------------------------------
__global__ __launch_bounds__(256)
void attn_scores(const float* __restrict__ Q, const float* __restrict__ Kt,
                 const int* __restrict__ mask, float* __restrict__ Sc) {
    __shared__ float Qs[64][65];   // [d][q]
    __shared__ float Ks[64][65];   // [d][k]
    int tid = threadIdx.x;
    int bh = blockIdx.z; int b = bh >> 4, h = bh & 15;
    int q0 = blockIdx.y * 64, k0 = blockIdx.x * 64;

    int r = tid >> 4, c4 = (tid & 15) * 4;
    #pragma unroll
    for (int j = 0; j < 4; j++) {
        int row = r + j*16;
        float4 qv = *(const float4*)(Q + (size_t)(b*S_ + q0 + row)*D_ + h*DK_ + c4);
        Qs[c4+0][row] = qv.x; Qs[c4+1][row] = qv.y;
        Qs[c4+2][row] = qv.z; Qs[c4+3][row] = qv.w;
        float4 kv = *(const float4*)(Kt + (size_t)(b*S_ + k0 + row)*D_ + h*DK_ + c4);
        Ks[c4+0][row] = kv.x; Ks[c4+1][row] = kv.y;
        Ks[c4+2][row] = kv.z; Ks[c4+3][row] = kv.w;
    }
    __syncthreads();

    int ty = tid >> 4, tx = tid & 15;
    float acc[4][4];
    #pragma unroll
    for (int i = 0; i < 4; i++)
        #pragma unroll
        for (int j = 0; j < 4; j++) acc[i][j] = 0.f;

    #pragma unroll 16
    for (int d = 0; d < 64; d++) {
        float a[4], bb[4];
        #pragma unroll
        for (int i = 0; i < 4; i++) a[i]  = Qs[d][ty*4+i];
        #pragma unroll
        for (int j = 0; j < 4; j++) bb[j] = Ks[d][tx*4+j];
        #pragma unroll
        for (int i = 0; i < 4; i++)
            #pragma unroll
            for (int j = 0; j < 4; j++) acc[i][j] += a[i]*bb[j];
    }

    const float inv = 1.0f / 32.0f;   // 1/sqrt(D), D=1024
    int kbase = k0 + tx*4;
    int msk0 = mask[b*S_ + kbase + 0];
    int msk1 = mask[b*S_ + kbase + 1];
    int msk2 = mask[b*S_ + kbase + 2];
    int msk3 = mask[b*S_ + kbase + 3];
    #pragma unroll
    for (int i = 0; i < 4; i++) {
        float4 o;
        o.x = (msk0 == 0) ? -1e9f : acc[i][0]*inv;
        o.y = (msk1 == 0) ? -1e9f : acc[i][1]*inv;
        o.z = (msk2 == 0) ? -1e9f : acc[i][2]*inv;
        o.w = (msk3 == 0) ? -1e9f : acc[i][3]*inv;
        *(float4*)(Sc + ((size_t)bh*S_ + q0 + ty*4 + i)*S_ + kbase) = o;
    }
}

// ---------------------------------------------------------------------------
// Row softmax over length 2048 (in place). One 256-thread block per row.
// ---------------------------------------------------------------------------
__global__ __launch_bounds__(256)
void softmax_rows(float* __restrict__ sc) {
    __shared__ float sh[8];
    size_t row = blockIdx.x;
    float* p = sc + row * (size_t)S_;
    int tid = threadIdx.x;
    float v[8];
    float mx = -INFINITY;
    #pragma unroll
    for (int j = 0; j < 8; j++) { v[j] = p[tid + j*256]; mx = fmaxf(mx, v[j]); }
    mx = blockMax(mx, sh);
    float s = 0.f;
    #pragma unroll
    for (int j = 0; j < 8; j++) { v[j] = expf(v[j] - mx); s += v[j]; }
    s = blockSum(s, sh);
    float inv = 1.0f / s;
    #pragma unroll
    for (int j = 0; j < 8; j++) p[tid + j*256] = v[j] * inv;
}

// ---------------------------------------------------------------------------
// O[b, q, h*64+d] = sum_k P[bh,q,k] * V[b,k,h*64+d].  64q x 64d tile, k-loop.
// ---------------------------------------------------------------------------
__global__ __launch_bounds__(256)
void attn_av(const float* __restrict__ P, const float* __restrict__ V,
             float* __restrict__ O) {
    __shared__ float Ps[64][65];  // [k][q]
    __shared__ float Vs[64][64];  // [k][d]
    int tid = threadIdx.x;
    int bh = blockIdx.z; int b = bh >> 4, h = bh & 15;
    int q0 = blockIdx.y * 64;
    int ty = tid >> 4, tx = tid & 15;
    int r = tid >> 4, c4 = (tid & 15) * 4;

    float acc[4][4];
    #pragma unroll
    for (int i = 0; i < 4; i++)
        #pragma unroll
        for (int j = 0; j < 4; j++) acc[i][j] = 0.f;

    for (int k0 = 0; k0 < S_; k0 += 64) {
        #pragma unroll
        for (int j = 0; j < 4; j++) {
            int row = r + j*16;
            float4 pv = *(const float4*)(P + ((size_t)bh*S_ + q0 + row)*S_ + k0 + c4);
            Ps[c4+0][row] = pv.x; Ps[c4+1][row] = pv.y;
            Ps[c4+2][row] = pv.z; Ps[c4+3][row] = pv.w;
            float4 vv = *(const float4*)(V + (size_t)(b*S_ + k0 + row)*D_ + h*DK_ + c4);
            *(float4*)&Vs[row][c4] = vv;
        }
        __syncthreads();
        #pragma unroll 16
        for (int kk = 0; kk < 64; kk++) {
            float a[4], bb[4];
            #pragma unroll
            for (int i = 0; i < 4; i++) a[i]  = Ps[kk][ty*4+i];
            #pragma unroll
            for (int j = 0; j < 4; j++) bb[j] = Vs[kk][tx*4+j];
            #pragma unroll
            for (int i = 0; i < 4; i++)
                #pragma unroll
                for (int j = 0; j < 4; j++) acc[i][j] += a[i]*bb[j];
        }
        __syncthreads();
    }
    #pragma unroll
    for (int i = 0; i < 4; i++) {
        float4 o = make_float4(acc[i][0], acc[i][1], acc[i][2], acc[i][3]);
        *(float4*)(O + (size_t)(b*S_ + q0 + ty*4 + i)*D_ + h*DK_ + tx*4) = o;
    }
}

// ---------------------------------------------------------------------------
// out[m,:] = LayerNorm(x[m,:] + r[m,:]) * g + be   (biased variance, eps 1e-5)
// One 256-thread block per row of 1024.
// ---------------------------------------------------------------------------
__global__ __launch_bounds__(256)
void add_ln(const float* __restrict__ x, const float* __restrict__ rr,
            const float* __restrict__ g, const float* __restrict__ be,
            float* __restrict__ out) {
    __shared__ float sh[8];
    int m = blockIdx.x, tid = threadIdx.x;
    float4 v = *(const float4*)(x + (size_t)m*D_ + tid*4);
    float4 rv = *(const float4*)(rr + (size_t)m*D_ + tid*4);
    v.x += rv.x; v.y += rv.y; v.z += rv.z; v.w += rv.w;
    float s = v.x + v.y + v.z + v.w;
    s = blockSum(s, sh);
    float mean = s * (1.0f / D_);
    float d0 = v.x - mean, d1 = v.y - mean, d2 = v.z - mean, d3 = v.w - mean;
    float sq = d0*d0 + d1*d1 + d2*d2 + d3*d3;
    sq = blockSum(sq, sh);
    float var = sq * (1.0f / D_);
    float rstd = rsqrtf(var + 1e-5f);
    float4 gg = *(const float4*)(g + tid*4);
    float4 bb = *(const float4*)(be + tid*4);
    float4 o;
    o.x = d0*rstd*gg.x + bb.x;
    o.y = d1*rstd*gg.y + bb.y;
    o.z = d2*rstd*gg.z + bb.z;
    o.w = d3*rstd*gg.w + bb.w;
    *(float4*)(out + (size_t)m*D_ + tid*4) = o;
}

// ---------------------------------------------------------------------------
// Launch
// ---------------------------------------------------------------------------
extern "C" void kernel_launch(void* const* d_in, const int* in_sizes, int n_in,
                              void* d_out, int out_size) {
    const int*   src  = (const int*)  d_in[0];
    const int*   mask = (const int*)  d_in[1];
    const float* emb  = (const float*)d_in[2];
    const float* Wq   = (const float*)d_in[3];
    const float* bq   = (const float*)d_in[4];
    const float* Wk   = (const float*)d_in[5];
    const float* bk   = (const float*)d_in[6];
    const float* Wv   = (const float*)d_in[7];
    const float* bv   = (const float*)d_in[8];
    const float* Wo   = (const float*)d_in[9];
    const float* bo   = (const float*)d_in[10];
    const float* W1   = (const float*)d_in[11];
    const float* b1   = (const float*)d_in[12];
    const float* W2   = (const float*)d_in[13];
    const float* b2   = (const float*)d_in[14];
    const float* g1   = (const float*)d_in[15];
    const float* be1  = (const float*)d_in[16];
    const float* g2   = (const float*)d_in[17];
    const float* be2  = (const float*)d_in[18];
    float* out = (float*)d_out;

    float *x, *q, *k, *v, *a, *r, *h, *s, *pe;
    cudaGetSymbolAddress((void**)&x,  g_x);
    cudaGetSymbolAddress((void**)&q,  g_q);
    cudaGetSymbolAddress((void**)&k,  g_k);
    cudaGetSymbolAddress((void**)&v,  g_v);
    cudaGetSymbolAddress((void**)&a,  g_a);
    cudaGetSymbolAddress((void**)&r,  g_r);
    cudaGetSymbolAddress((void**)&h,  g_h);
    cudaGetSymbolAddress((void**)&s,  g_s);
    cudaGetSymbolAddress((void**)&pe, g_pe);

    pe_kernel<<<(B_*D_ + 255)/256, 256>>>(pe);
    embed_kernel<<<(M_*D_ + 255)/256, 256>>>(src, emb, pe, x);

    dim3 gProj(D_/128,  M_/128);   // N=1024
    dim3 gFF1 (FF_/128, M_/128);   // N=4096
    dim3 gScore(S_/64, S_/64, B_*H_);
    dim3 gAV   (1,     S_/64, B_*H_);

    for (int l = 0; l < L_; l++) {
        const float* Wq_l = Wq + (size_t)l*D_*D_;
        const float* Wk_l = Wk + (size_t)l*D_*D_;
        const float* Wv_l = Wv + (size_t)l*D_*D_;
        const float* Wo_l = Wo + (size_t)l*D_*D_;
        const float* W1_l = W1 + (size_t)l*D_*FF_;
        const float* W2_l = W2 + (size_t)l*FF_*D_;
        const float* bq_l = bq + (size_t)l*D_;
        const float* bk_l = bk + (size_t)l*D_;
        const float* bv_l = bv + (size_t)l*D_;
        const float* bo_l = bo + (size_t)l*D_;
        const float* b1_l = b1 + (size_t)l*FF_;
        const float* b2_l = b2 + (size_t)l*D_;
        const float* g1_l = g1 + (size_t)l*D_;
        const float* be1_l= be1+ (size_t)l*D_;
        const float* g2_l = g2 + (size_t)l*D_;
        const float* be2_l= be2+ (size_t)l*D_;

        sgemm<<<gProj, 256>>>(x, Wq_l, bq_l, q, M_, D_, D_, 0);
        sgemm<<<gProj, 256>>>(x, Wk_l, bk_l, k, M_, D_, D_, 0);
        sgemm<<<gProj, 256>>>(x, Wv_l, bv_l, v, M_, D_, D_, 0);

        attn_scores<<<gScore, 256>>>(q, k, mask, s);
        softmax_rows<<<B_*H_*S_, 256>>>(s);
        attn_av<<<gAV, 256>>>(s, v, a);

        sgemm<<<gProj, 256>>>(a, Wo_l, bo_l, r, M_, D_, D_, 0);
        add_ln<<<M_, 256>>>(x, r, g1_l, be1_l, x);

        sgemm<<<gFF1,  256>>>(x, W1_l, b1_l, h, M_, FF_, D_, 1);   // ReLU
        sgemm<<<gProj, 256>>>(h, W2_l, b2_l, r, M_, D_, FF_, 0);

        float* dst = (l == L_-1) ? out : x;
        add_ln<<<M_, 256>>>(x, r, g2_l, be2_l, dst);
    }
}

// round 6
// speedup vs baseline: 1.0520x; 1.0520x over previous
#include <cuda_runtime.h>
#include <cuda_bf16.h>
#include <math.h>
#include <stdint.h>

// ---------------------------------------------------------------------------
// Problem constants
// ---------------------------------------------------------------------------
#define B_  2
#define S_  2048
#define D_  1024
#define H_  16
#define DK_ 64
#define FF_ 4096
#define L_  6
#define M_  (B_*S_)          // 4096 rows

// ---------------------------------------------------------------------------
// Scratch (device globals — no allocations allowed)
// ---------------------------------------------------------------------------
__device__ float g_x[M_*D_];                 // running activation
__device__ float g_q[M_*D_];
__device__ float g_k[M_*D_];
__device__ float g_v[M_*D_];
__device__ float g_a[M_*D_];                 // attention concat output
__device__ float g_r[M_*D_];                 // proj / ff output (residual branch)
__device__ float g_h[M_*FF_];                // ff hidden
__device__ float g_s[134217728];             // scores  [B*H, S, S]  (512 MB)
__device__ float g_pe[B_*D_];                // positional encoding

// bf16 split weights, transposed to [N,K]:  per layer 12M elems
//   q:+0  k:+1M  v:+2M  o:+3M  w1:+4M ([4096,1024])  w2:+8M ([1024,4096])
#define MB1 (1u<<20)
#define WL_ (12u*MB1)
__device__ __nv_bfloat16 g_wth[6*12*1024*1024];
__device__ __nv_bfloat16 g_wtl[6*12*1024*1024];
// bf16 split activations (reused sequentially; max = M*FF)
__device__ __nv_bfloat16 g_ah[M_*FF_];
__device__ __nv_bfloat16 g_al[M_*FF_];

// ---------------------------------------------------------------------------
// PTX helpers (portable sm_80-era only: cp.async, ldmatrix, mma.sync)
// ---------------------------------------------------------------------------
__device__ __forceinline__ uint32_t smem_u32(const void* p) {
    return (uint32_t)__cvta_generic_to_shared(p);
}
#define CP16(dst, src) \
    asm volatile("cp.async.cg.shared.global [%0], [%1], 16;" :: "r"(dst), "l"(src) : "memory")
#define CP_COMMIT() asm volatile("cp.async.commit_group;" ::: "memory")
#define CP_WAIT1()  asm volatile("cp.async.wait_group 1;" ::: "memory")
#define CP_WAIT0()  asm volatile("cp.async.wait_group 0;" ::: "memory")

#define LDSM4(r, addr) \
    asm volatile("ldmatrix.sync.aligned.m8n8.x4.shared.b16 {%0,%1,%2,%3}, [%4];" \
        : "=r"((r)[0]), "=r"((r)[1]), "=r"((r)[2]), "=r"((r)[3]) : "r"(addr))

#define MMA16816(c, a, b0, b1) \
    asm volatile("mma.sync.aligned.m16n8k16.row.col.f32.bf16.bf16.f32 " \
        "{%0,%1,%2,%3}, {%4,%5,%6,%7}, {%8,%9}, {%0,%1,%2,%3};" \
        : "+f"((c)[0]), "+f"((c)[1]), "+f"((c)[2]), "+f"((c)[3]) \
        : "r"((a)[0]), "r"((a)[1]), "r"((a)[2]), "r"((a)[3]), "r"(b0), "r"(b1))

// ---------------------------------------------------------------------------
// bf16x3 HMMA GEMM:  C[M,N] = fp32((Ah+Al)[M,K] @ (Bh+Bl)^T) + bias (opt ReLU)
// A*: bf16 [M,K] row-major.  B*: bf16 [N,K] row-major (i.e., W^T).
// 128x128 CTA tile, 8 warps (64x32 each), K-chunk 32, 2-stage cp.async.
// Smem pitch 40 bf16 (80B): r*5 mod 8 is a permutation -> conflict-free ldsm.
// ---------------------------------------------------------------------------
#define KC      32
#define PITCH_B 80                    // bytes per smem row (40 bf16)
#define TILE_B  (128*PITCH_B)         // 10240
#define STAGE_B (4*TILE_B)            // 40960: Ah, Al, Bh, Bl
#define GSMEM   (2*STAGE_B)           // 81920

extern __shared__ char dynsmem[];

__global__ __launch_bounds__(256, 2)
void hmma_gemm(const __nv_bfloat16* __restrict__ Ah, const __nv_bfloat16* __restrict__ Al,
               const __nv_bfloat16* __restrict__ Bh, const __nv_bfloat16* __restrict__ Bl,
               const float* __restrict__ bias, float* __restrict__ C,
               int M, int N, int K, int relu) {
    uint32_t sb = smem_u32(dynsmem);
    int tid = threadIdx.x, lane = tid & 31, wid = tid >> 5;
    int wm = wid >> 2, wn = wid & 3;                 // warp grid 2 x 4
    int m0 = blockIdx.y * 128, n0 = blockIdx.x * 128;

    float acc[4][4][4];
    #pragma unroll
    for (int i = 0; i < 4; i++)
        #pragma unroll
        for (int j = 0; j < 4; j++)
            #pragma unroll
            for (int q = 0; q < 4; q++) acc[i][j][q] = 0.f;

    // ---- cp.async mapping: 2048 16B segs/stage, 8 per thread ----
    int row_base = tid >> 2, seg = tid & 3;
    const __nv_bfloat16* gsrc[4];
    gsrc[0] = Ah + (size_t)m0 * K;
    gsrc[1] = Al + (size_t)m0 * K;
    gsrc[2] = Bh + (size_t)n0 * K;
    gsrc[3] = Bl + (size_t)n0 * K;

    // ---- ldmatrix per-lane addressing ----
    int lrow = lane & 15;
    int lk   = (lane >> 4) << 3;                     // 0 or 8
    uint32_t aoff = (uint32_t)((wm*64 + lrow) * PITCH_B + lk * 2);
    uint32_t boff = (uint32_t)((wn*32 + lrow) * PITCH_B + lk * 2);

    int nc = K / KC;

    // prologue: chunk 0 -> stage 0
    {
        #pragma unroll
        for (int i = 0; i < 8; i++) {
            int tile = i >> 1, row = row_base + (i & 1) * 64;
            uint32_t dst = sb + tile * TILE_B + (uint32_t)(row * PITCH_B + seg * 16);
            CP16(dst, (const char*)(gsrc[tile] + (size_t)row * K) + seg * 16);
        }
        CP_COMMIT();
    }

    for (int c = 0; c < nc; c++) {
        if (c + 1 < nc) {
            int ns = (c + 1) & 1;
            int k0 = (c + 1) * KC;
            #pragma unroll
            for (int i = 0; i < 8; i++) {
                int tile = i >> 1, row = row_base + (i & 1) * 64;
                uint32_t dst = sb + ns * STAGE_B + tile * TILE_B
                             + (uint32_t)(row * PITCH_B + seg * 16);
                CP16(dst, (const char*)(gsrc[tile] + (size_t)row * K + k0) + seg * 16);
            }
            CP_COMMIT();
            CP_WAIT1();
        } else {
            CP_WAIT0();
        }
        __syncthreads();

        uint32_t base = sb + (c & 1) * STAGE_B;
        #pragma unroll
        for (int kk = 0; kk < KC; kk += 16) {
            uint32_t ah[4][4], bh[2][4];
            #pragma unroll
            for (int mt = 0; mt < 4; mt++)
                LDSM4(ah[mt], base + 0*TILE_B + aoff + mt*(16*PITCH_B) + kk*2);
            #pragma unroll
            for (int nt2 = 0; nt2 < 2; nt2++)
                LDSM4(bh[nt2], base + 2*TILE_B + boff + nt2*(16*PITCH_B) + kk*2);
            // pass 1: Ah * Bh
            #pragma unroll
            for (int mt = 0; mt < 4; mt++)
                #pragma unroll
                for (int nt = 0; nt < 4; nt++)
                    MMA16816(acc[mt][nt], ah[mt], bh[nt>>1][nt&1], bh[nt>>1][2+(nt&1)]);
            // pass 2: Ah * Bl
            {
                uint32_t bl[2][4];
                #pragma unroll
                for (int nt2 = 0; nt2 < 2; nt2++)
                    LDSM4(bl[nt2], base + 3*TILE_B + boff + nt2*(16*PITCH_B) + kk*2);
                #pragma unroll
                for (int mt = 0; mt < 4; mt++)
                    #pragma unroll
                    for (int nt = 0; nt < 4; nt++)
                        MMA16816(acc[mt][nt], ah[mt], bl[nt>>1][nt&1], bl[nt>>1][2+(nt&1)]);
            }
            // pass 3: Al * Bh
            {
                uint32_t al4[4][4];
                #pragma unroll
                for (int mt = 0; mt < 4; mt++)
                    LDSM4(al4[mt], base + 1*TILE_B + aoff + mt*(16*PITCH_B) + kk*2);
                #pragma unroll
                for (int mt = 0; mt < 4; mt++)
                    #pragma unroll
                    for (int nt = 0; nt < 4; nt++)
                        MMA16816(acc[mt][nt], al4[mt], bh[nt>>1][nt&1], bh[nt>>1][2+(nt&1)]);
            }
        }
        __syncthreads();
    }

    // ---- epilogue: bias (+ReLU), float2 stores ----
    int r0 = lane >> 2, cl = (lane & 3) * 2;
    #pragma unroll
    for (int nt = 0; nt < 4; nt++) {
        int col = n0 + wn*32 + nt*8 + cl;
        float bx = bias[col], by = bias[col+1];
        #pragma unroll
        for (int mt = 0; mt < 4; mt++) {
            int row = m0 + wm*64 + mt*16 + r0;
            float v0 = acc[mt][nt][0] + bx, v1 = acc[mt][nt][1] + by;
            float v2 = acc[mt][nt][2] + bx, v3 = acc[mt][nt][3] + by;
            if (relu) {
                v0 = fmaxf(v0, 0.f); v1 = fmaxf(v1, 0.f);
                v2 = fmaxf(v2, 0.f); v3 = fmaxf(v3, 0.f);
            }
            *(float2*)(C + (size_t)row * N + col)       = make_float2(v0, v1);
            *(float2*)(C + (size_t)(row + 8) * N + col) = make_float2(v2, v3);
        }
    }
}

// ---------------------------------------------------------------------------
// fp32 -> (bf16 hi, bf16 lo) split, vectorized by 4
// ---------------------------------------------------------------------------
__global__ void split_bf16(const float* __restrict__ x,
                           __nv_bfloat16* __restrict__ hi,
                           __nv_bfloat16* __restrict__ lo, int n4) {
    int i = blockIdx.x * blockDim.x + threadIdx.x;
    if (i >= n4) return;
    float4 v = ((const float4*)x)[i];
    __nv_bfloat16 h0 = __float2bfloat16(v.x);
    __nv_bfloat16 h1 = __float2bfloat16(v.y);
    __nv_bfloat16 h2 = __float2bfloat16(v.z);
    __nv_bfloat16 h3 = __float2bfloat16(v.w);
    __nv_bfloat16 l0 = __float2bfloat16(v.x - __bfloat162float(h0));
    __nv_bfloat16 l1 = __float2bfloat16(v.y - __bfloat162float(h1));
    __nv_bfloat16 l2 = __float2bfloat16(v.z - __bfloat162float(h2));
    __nv_bfloat16 l3 = __float2bfloat16(v.w - __bfloat162float(h3));
    ((__nv_bfloat162*)hi)[i*2]   = __nv_bfloat162(h0, h1);
    ((__nv_bfloat162*)hi)[i*2+1] = __nv_bfloat162(h2, h3);
    ((__nv_bfloat162*)lo)[i*2]   = __nv_bfloat162(l0, l1);
    ((__nv_bfloat162*)lo)[i*2+1] = __nv_bfloat162(l2, l3);
}

// ---------------------------------------------------------------------------
// Weight transpose + split:  W fp32 [K,N]  ->  th/tl bf16 [N,K]
// ---------------------------------------------------------------------------
__global__ void wsplit_t(const float* __restrict__ W,
                         __nv_bfloat16* __restrict__ th,
                         __nv_bfloat16* __restrict__ tl, int K, int N) {
    __shared__ float sh[32][33];
    int n0 = blockIdx.x * 32, k0 = blockIdx.y * 32;
    int tx = threadIdx.x, ty = threadIdx.y;
    #pragma unroll
    for (int i = 0; i < 4; i++)
        sh[ty + i*8][tx] = W[(size_t)(k0 + ty + i*8) * N + n0 + tx];
    __syncthreads();
    #pragma unroll
    for (int i = 0; i < 4; i++) {
        int n = n0 + ty + i*8;
        float v = sh[tx][ty + i*8];
        __nv_bfloat16 h = __float2bfloat16(v);
        __nv_bfloat16 l = __float2bfloat16(v - __bfloat162float(h));
        th[(size_t)n * K + k0 + tx] = h;
        tl[(size_t)n * K + k0 + tx] = l;
    }
}

// ---------------------------------------------------------------------------
// Reductions
// ---------------------------------------------------------------------------
__device__ __forceinline__ float warpSum(float v) {
    #pragma unroll
    for (int o = 16; o; o >>= 1) v += __shfl_xor_sync(0xffffffffu, v, o);
    return v;
}
__device__ __forceinline__ float warpMax(float v) {
    #pragma unroll
    for (int o = 16; o; o >>= 1) v = fmaxf(v, __shfl_xor_sync(0xffffffffu, v, o));
    return v;
}
__device__ __forceinline__ float blockSum(float v, float* sh) {
    int tid = threadIdx.x, lane = tid & 31, w = tid >> 5;
    v = warpSum(v);
    if (lane == 0) sh[w] = v;
    __syncthreads();
    float t = sh[0];
    #pragma unroll
    for (int i = 1; i < 8; i++) t += sh[i];
    __syncthreads();
    return t;
}
__device__ __forceinline__ float blockMax(float v, float* sh) {
    int tid = threadIdx.x, lane = tid & 31, w = tid >> 5;
    v = warpMax(v);
    if (lane == 0) sh[w] = v;
    __syncthreads();
    float t = sh[0];
    #pragma unroll
    for (int i = 1; i < 8; i++) t = fmaxf(t, sh[i]);
    __syncthreads();
    return t;
}

// ---------------------------------------------------------------------------
// Positional encoding (faithful fp32 chain)
// ---------------------------------------------------------------------------
__global__ void pe_kernel(float* __restrict__ pe) {
    int idx = blockIdx.x * blockDim.x + threadIdx.x;
    if (idx >= B_*D_) return;
    int b = idx / D_, d = idx % D_;
    int i = d >> 1;
    double c = -log(10000.0) / (double)D_;
    float divf = (float)exp((double)(2*i) * c);
    float ang  = (float)b / divf;
    double ad  = (double)ang;
    pe[idx] = (d & 1) ? (float)cos(ad) : (float)sin(ad);
}

__global__ void embed_kernel(const int* __restrict__ src,
                             const float* __restrict__ emb,
                             const float* __restrict__ pe,
                             float* __restrict__ x) {
    int idx = blockIdx.x * blockDim.x + threadIdx.x;
    if (idx >= M_*D_) return;
    int d  = idx & (D_-1);
    int bs = idx >> 10;
    int b  = bs >> 11;
    x[idx] = emb[(size_t)src[bs]*D_ + d] + pe[b*D_ + d];
}

// ---------------------------------------------------------------------------
// Attention (fp32, unchanged this round)
// ---------------------------------------------------------------------------
__global__ __launch_bounds__(256)
void attn_scores(const float* __restrict__ Q, const float* __restrict__ Kt,
                 const int* __restrict__ mask, float* __restrict__ Sc) {
    __shared__ float Qs[64][65];
    __shared__ float Ks[64][65];
    int tid = threadIdx.x;
    int bh = blockIdx.z; int b = bh >> 4, h = bh & 15;
    int q0 = blockIdx.y * 64, k0 = blockIdx.x * 64;

    int r = tid >> 4, c4 = (tid & 15) * 4;
    #pragma unroll
    for (int j = 0; j < 4; j++) {
        int row = r + j*16;
        float4 qv = *(const float4*)(Q + (size_t)(b*S_ + q0 + row)*D_ + h*DK_ + c4);
        Qs[c4+0][row] = qv.x; Qs[c4+1][row] = qv.y;
        Qs[c4+2][row] = qv.z; Qs[c4+3][row] = qv.w;
        float4 kv = *(const float4*)(Kt + (size_t)(b*S_ + k0 + row)*D_ + h*DK_ + c4);
        Ks[c4+0][row] = kv.x; Ks[c4+1][row] = kv.y;
        Ks[c4+2][row] = kv.z; Ks[c4+3][row] = kv.w;
    }
    __syncthreads();

    int ty = tid >> 4, tx = tid & 15;
    float acc[4][4];
    #pragma unroll
    for (int i = 0; i < 4; i++)
        #pragma unroll
        for (int j = 0; j < 4; j++) acc[i][j] = 0.f;

    #pragma unroll 16
    for (int d = 0; d < 64; d++) {
        float a[4], bb[4];
        #pragma unroll
        for (int i = 0; i < 4; i++) a[i]  = Qs[d][ty*4+i];
        #pragma unroll
        for (int j = 0; j < 4; j++) bb[j] = Ks[d][tx*4+j];
        #pragma unroll
        for (int i = 0; i < 4; i++)
            #pragma unroll
            for (int j = 0; j < 4; j++) acc[i][j] += a[i]*bb[j];
    }

    const float inv = 1.0f / 32.0f;
    int kbase = k0 + tx*4;
    int msk0 = mask[b*S_ + kbase + 0];
    int msk1 = mask[b*S_ + kbase + 1];
    int msk2 = mask[b*S_ + kbase + 2];
    int msk3 = mask[b*S_ + kbase + 3];
    #pragma unroll
    for (int i = 0; i < 4; i++) {
        float4 o;
        o.x = (msk0 == 0) ? -1e9f : acc[i][0]*inv;
        o.y = (msk1 == 0) ? -1e9f : acc[i][1]*inv;
        o.z = (msk2 == 0) ? -1e9f : acc[i][2]*inv;
        o.w = (msk3 == 0) ? -1e9f : acc[i][3]*inv;
        *(float4*)(Sc + ((size_t)bh*S_ + q0 + ty*4 + i)*S_ + kbase) = o;
    }
}

__global__ __launch_bounds__(256)
void softmax_rows(float* __restrict__ sc) {
    __shared__ float sh[8];
    size_t row = blockIdx.x;
    float* p = sc + row * (size_t)S_;
    int tid = threadIdx.x;
    float v[8];
    float mx = -INFINITY;
    #pragma unroll
    for (int j = 0; j < 8; j++) { v[j] = p[tid + j*256]; mx = fmaxf(mx, v[j]); }
    mx = blockMax(mx, sh);
    float s = 0.f;
    #pragma unroll
    for (int j = 0; j < 8; j++) { v[j] = expf(v[j] - mx); s += v[j]; }
    s = blockSum(s, sh);
    float inv = 1.0f / s;
    #pragma unroll
    for (int j = 0; j < 8; j++) p[tid + j*256] = v[j] * inv;
}

__global__ __launch_bounds__(256)
void attn_av(const float* __restrict__ P, const float* __restrict__ V,
             float* __restrict__ O) {
    __shared__ float Ps[64][65];
    __shared__ float Vs[64][64];
    int tid = threadIdx.x;
    int bh = blockIdx.z; int b = bh >> 4, h = bh & 15;
    int q0 = blockIdx.y * 64;
    int ty = tid >> 4, tx = tid & 15;
    int r = tid >> 4, c4 = (tid & 15) * 4;

    float acc[4][4];
    #pragma unroll
    for (int i = 0; i < 4; i++)
        #pragma unroll
        for (int j = 0; j < 4; j++) acc[i][j] = 0.f;

    for (int k0 = 0; k0 < S_; k0 += 64) {
        #pragma unroll
        for (int j = 0; j < 4; j++) {
            int row = r + j*16;
            float4 pv = *(const float4*)(P + ((size_t)bh*S_ + q0 + row)*S_ + k0 + c4);
            Ps[c4+0][row] = pv.x; Ps[c4+1][row] = pv.y;
            Ps[c4+2][row] = pv.z; Ps[c4+3][row] = pv.w;
            float4 vv = *(const float4*)(V + (size_t)(b*S_ + k0 + row)*D_ + h*DK_ + c4);
            *(float4*)&Vs[row][c4] = vv;
        }
        __syncthreads();
        #pragma unroll 16
        for (int kk = 0; kk < 64; kk++) {
            float a[4], bb[4];
            #pragma unroll
            for (int i = 0; i < 4; i++) a[i]  = Ps[kk][ty*4+i];
            #pragma unroll
            for (int j = 0; j < 4; j++) bb[j] = Vs[kk][tx*4+j];
            #pragma unroll
            for (int i = 0; i < 4; i++)
                #pragma unroll
                for (int j = 0; j < 4; j++) acc[i][j] += a[i]*bb[j];
        }
        __syncthreads();
    }
    #pragma unroll
    for (int i = 0; i < 4; i++) {
        float4 o = make_float4(acc[i][0], acc[i][1], acc[i][2], acc[i][3]);
        *(float4*)(O + (size_t)(b*S_ + q0 + ty*4 + i)*D_ + h*DK_ + tx*4) = o;
    }
}

// ---------------------------------------------------------------------------
// out = LayerNorm(x + r) * g + be
// ---------------------------------------------------------------------------
__global__ __launch_bounds__(256)
void add_ln(const float* __restrict__ x, const float* __restrict__ rr,
            const float* __restrict__ g, const float* __restrict__ be,
            float* __restrict__ out) {
    __shared__ float sh[8];
    int m = blockIdx.x, tid = threadIdx.x;
    float4 v = *(const float4*)(x + (size_t)m*D_ + tid*4);
    float4 rv = *(const float4*)(rr + (size_t)m*D_ + tid*4);
    v.x += rv.x; v.y += rv.y; v.z += rv.z; v.w += rv.w;
    float s = v.x + v.y + v.z + v.w;
    s = blockSum(s, sh);
    float mean = s * (1.0f / D_);
    float d0 = v.x - mean, d1 = v.y - mean, d2 = v.z - mean, d3 = v.w - mean;
    float sq = d0*d0 + d1*d1 + d2*d2 + d3*d3;
    sq = blockSum(sq, sh);
    float var = sq * (1.0f / D_);
    float rstd = rsqrtf(var + 1e-5f);
    float4 gg = *(const float4*)(g + tid*4);
    float4 bb = *(const float4*)(be + tid*4);
    float4 o;
    o.x = d0*rstd*gg.x + bb.x;
    o.y = d1*rstd*gg.y + bb.y;
    o.z = d2*rstd*gg.z + bb.z;
    o.w = d3*rstd*gg.w + bb.w;
    *(float4*)(out + (size_t)m*D_ + tid*4) = o;
}

// ---------------------------------------------------------------------------
// Launch
// ---------------------------------------------------------------------------
extern "C" void kernel_launch(void* const* d_in, const int* in_sizes, int n_in,
                              void* d_out, int out_size) {
    const int*   src  = (const int*)  d_in[0];
    const int*   mask = (const int*)  d_in[1];
    const float* emb  = (const float*)d_in[2];
    const float* Wq   = (const float*)d_in[3];
    const float* bq   = (const float*)d_in[4];
    const float* Wk   = (const float*)d_in[5];
    const float* bk   = (const float*)d_in[6];
    const float* Wv   = (const float*)d_in[7];
    const float* bv   = (const float*)d_in[8];
    const float* Wo   = (const float*)d_in[9];
    const float* bo   = (const float*)d_in[10];
    const float* W1   = (const float*)d_in[11];
    const float* b1   = (const float*)d_in[12];
    const float* W2   = (const float*)d_in[13];
    const float* b2   = (const float*)d_in[14];
    const float* g1   = (const float*)d_in[15];
    const float* be1  = (const float*)d_in[16];
    const float* g2   = (const float*)d_in[17];
    const float* be2  = (const float*)d_in[18];
    float* out = (float*)d_out;

    float *x, *q, *k, *v, *a, *r, *h, *s, *pe;
    __nv_bfloat16 *wth, *wtl, *ah, *al;
    cudaGetSymbolAddress((void**)&x,  g_x);
    cudaGetSymbolAddress((void**)&q,  g_q);
    cudaGetSymbolAddress((void**)&k,  g_k);
    cudaGetSymbolAddress((void**)&v,  g_v);
    cudaGetSymbolAddress((void**)&a,  g_a);
    cudaGetSymbolAddress((void**)&r,  g_r);
    cudaGetSymbolAddress((void**)&h,  g_h);
    cudaGetSymbolAddress((void**)&s,  g_s);
    cudaGetSymbolAddress((void**)&pe, g_pe);
    cudaGetSymbolAddress((void**)&wth, g_wth);
    cudaGetSymbolAddress((void**)&wtl, g_wtl);
    cudaGetSymbolAddress((void**)&ah, g_ah);
    cudaGetSymbolAddress((void**)&al, g_al);

    cudaFuncSetAttribute(hmma_gemm, cudaFuncAttributeMaxDynamicSharedMemorySize, GSMEM);

    pe_kernel<<<(B_*D_ + 255)/256, 256>>>(pe);
    embed_kernel<<<(M_*D_ + 255)/256, 256>>>(src, emb, pe, x);

    // one-time (per launch) weight transpose+split
    dim3 tb(32, 8);
    for (int l = 0; l < L_; l++) {
        size_t wb = (size_t)l * WL_;
        wsplit_t<<<dim3(D_/32,  D_/32),  tb>>>(Wq + (size_t)l*D_*D_,  wth + wb,         wtl + wb,         D_, D_);
        wsplit_t<<<dim3(D_/32,  D_/32),  tb>>>(Wk + (size_t)l*D_*D_,  wth + wb + MB1,   wtl + wb + MB1,   D_, D_);
        wsplit_t<<<dim3(D_/32,  D_/32),  tb>>>(Wv + (size_t)l*D_*D_,  wth + wb + 2*MB1, wtl + wb + 2*MB1, D_, D_);
        wsplit_t<<<dim3(D_/32,  D_/32),  tb>>>(Wo + (size_t)l*D_*D_,  wth + wb + 3*MB1, wtl + wb + 3*MB1, D_, D_);
        wsplit_t<<<dim3(FF_/32, D_/32),  tb>>>(W1 + (size_t)l*D_*FF_, wth + wb + 4*MB1, wtl + wb + 4*MB1, D_, FF_);
        wsplit_t<<<dim3(D_/32,  FF_/32), tb>>>(W2 + (size_t)l*FF_*D_, wth + wb + 8*MB1, wtl + wb + 8*MB1, FF_, D_);
    }

    dim3 gProj(D_/128,  M_/128);
    dim3 gFF1 (FF_/128, M_/128);
    dim3 gScore(S_/64, S_/64, B_*H_);
    dim3 gAV   (1,     S_/64, B_*H_);
    const int nXD4 = M_*D_/4, nXF4 = M_*FF_/4;

    for (int l = 0; l < L_; l++) {
        size_t wb = (size_t)l * WL_;
        const float* bq_l = bq + (size_t)l*D_;
        const float* bk_l = bk + (size_t)l*D_;
        const float* bv_l = bv + (size_t)l*D_;
        const float* bo_l = bo + (size_t)l*D_;
        const float* b1_l = b1 + (size_t)l*FF_;
        const float* b2_l = b2 + (size_t)l*D_;
        const float* g1_l = g1 + (size_t)l*D_;
        const float* be1_l= be1+ (size_t)l*D_;
        const float* g2_l = g2 + (size_t)l*D_;
        const float* be2_l= be2+ (size_t)l*D_;

        // q,k,v = x @ W{q,k,v} + b
        split_bf16<<<(nXD4 + 255)/256, 256>>>(x, ah, al, nXD4);
        hmma_gemm<<<gProj, 256, GSMEM>>>(ah, al, wth + wb,         wtl + wb,         bq_l, q, M_, D_, D_, 0);
        hmma_gemm<<<gProj, 256, GSMEM>>>(ah, al, wth + wb + MB1,   wtl + wb + MB1,   bk_l, k, M_, D_, D_, 0);
        hmma_gemm<<<gProj, 256, GSMEM>>>(ah, al, wth + wb + 2*MB1, wtl + wb + 2*MB1, bv_l, v, M_, D_, D_, 0);

        attn_scores<<<gScore, 256>>>(q, k, mask, s);
        softmax_rows<<<B_*H_*S_, 256>>>(s);
        attn_av<<<gAV, 256>>>(s, v, a);

        // out proj
        split_bf16<<<(nXD4 + 255)/256, 256>>>(a, ah, al, nXD4);
        hmma_gemm<<<gProj, 256, GSMEM>>>(ah, al, wth + wb + 3*MB1, wtl + wb + 3*MB1, bo_l, r, M_, D_, D_, 0);
        add_ln<<<M_, 256>>>(x, r, g1_l, be1_l, x);

        // FF
        split_bf16<<<(nXD4 + 255)/256, 256>>>(x, ah, al, nXD4);
        hmma_gemm<<<gFF1, 256, GSMEM>>>(ah, al, wth + wb + 4*MB1, wtl + wb + 4*MB1, b1_l, h, M_, FF_, D_, 1);
        split_bf16<<<(nXF4 + 255)/256, 256>>>(h, ah, al, nXF4);
        hmma_gemm<<<gProj, 256, GSMEM>>>(ah, al, wth + wb + 8*MB1, wtl + wb + 8*MB1, b2_l, r, M_, D_, FF_, 0);

        float* dst = (l == L_-1) ? out : x;
        add_ln<<<M_, 256>>>(x, r, g2_l, be2_l, dst);
    }
}

// round 8
// speedup vs baseline: 2.5765x; 2.4492x over previous
#include <cuda_runtime.h>
#include <cuda_bf16.h>
#include <math.h>
#include <stdint.h>

// ---------------------------------------------------------------------------
// Problem constants
// ---------------------------------------------------------------------------
#define B_  2
#define S_  2048
#define D_  1024
#define H_  16
#define DK_ 64
#define FF_ 4096
#define L_  6
#define M_  (B_*S_)          // 4096 rows
#define BH_ (B_*H_)          // 32

// ---------------------------------------------------------------------------
// Scratch (device globals — no allocations allowed)
// ---------------------------------------------------------------------------
__device__ float g_x[M_*D_];
__device__ float g_q[M_*D_];
__device__ float g_k[M_*D_];
__device__ float g_v[M_*D_];
__device__ float g_a[M_*D_];
__device__ float g_r[M_*D_];
__device__ float g_h[M_*FF_];
__device__ float g_s[134217728];             // scores fp32 [BH, S, S] (512 MB)
__device__ __nv_bfloat16 g_p[134217728];     // probs  bf16 [BH, S, S] (256 MB)
__device__ float g_pe[B_*D_];

// bf16 split weights, transposed to [N,K]
#define MB1 (1u<<20)
#define WL_ (12u*MB1)
__device__ __nv_bfloat16 g_wth[6*12*1024*1024];
__device__ __nv_bfloat16 g_wtl[6*12*1024*1024];
__device__ __nv_bfloat16 g_ah[M_*FF_];
__device__ __nv_bfloat16 g_al[M_*FF_];
// attention bf16 operands
__device__ __nv_bfloat16 g_qh[M_*D_];        // [BH, S, 64]
__device__ __nv_bfloat16 g_kh[M_*D_];        // [BH, S, 64]
__device__ __nv_bfloat16 g_vt[M_*D_];        // [BH, 64, S]

// ---------------------------------------------------------------------------
// PTX helpers (portable: cp.async, ldmatrix, mma.sync)
// ---------------------------------------------------------------------------
__device__ __forceinline__ uint32_t smem_u32(const void* p) {
    return (uint32_t)__cvta_generic_to_shared(p);
}
#define CP16(dst, src) \
    asm volatile("cp.async.cg.shared.global [%0], [%1], 16;" :: "r"(dst), "l"(src) : "memory")
#define CP_COMMIT() asm volatile("cp.async.commit_group;" ::: "memory")
#define CP_WAIT1()  asm volatile("cp.async.wait_group 1;" ::: "memory")
#define CP_WAIT0()  asm volatile("cp.async.wait_group 0;" ::: "memory")

#define LDSM4(r, addr) \
    asm volatile("ldmatrix.sync.aligned.m8n8.x4.shared.b16 {%0,%1,%2,%3}, [%4];" \
        : "=r"((r)[0]), "=r"((r)[1]), "=r"((r)[2]), "=r"((r)[3]) : "r"(addr))

#define MMA16816(c, a, b0, b1) \
    asm volatile("mma.sync.aligned.m16n8k16.row.col.f32.bf16.bf16.f32 " \
        "{%0,%1,%2,%3}, {%4,%5,%6,%7}, {%8,%9}, {%0,%1,%2,%3};" \
        : "+f"((c)[0]), "+f"((c)[1]), "+f"((c)[2]), "+f"((c)[3]) \
        : "r"((a)[0]), "r"((a)[1]), "r"((a)[2]), "r"((a)[3]), "r"(b0), "r"(b1))

// ---------------------------------------------------------------------------
// bf16x3 HMMA GEMM:  C = fp32((Ah+Al) @ (Bh+Bl)^T) + bias (opt ReLU)
// A*: bf16 [M,K] rm.  B*: bf16 [N,K] rm.  128x128 CTA tile, 8 warps (64x32),
// K-chunk 64, pitch 144B, 2-stage cp.async, 144KB smem, 1 CTA/SM, no reg cap.
// ---------------------------------------------------------------------------
#define KC      64
#define PITCHB  144
#define TILEB   (128*PITCHB)          // 18432
#define STAGEB  (4*TILEB)             // 73728: Ah, Al, Bh, Bl
#define GSMEM   (2*STAGEB)            // 147456

extern __shared__ char dynsmem[];

__global__ __launch_bounds__(256, 1)
void hmma_gemm(const __nv_bfloat16* __restrict__ Ah, const __nv_bfloat16* __restrict__ Al,
               const __nv_bfloat16* __restrict__ Bh, const __nv_bfloat16* __restrict__ Bl,
               const float* __restrict__ bias, float* __restrict__ C,
               int M, int N, int K, int relu) {
    uint32_t sb = smem_u32(dynsmem);
    int tid = threadIdx.x, lane = tid & 31, wid = tid >> 5;
    int wm = wid >> 2, wn = wid & 3;
    int m0 = blockIdx.y * 128, n0 = blockIdx.x * 128;

    float acc[4][4][4];
    #pragma unroll
    for (int i = 0; i < 4; i++)
        #pragma unroll
        for (int j = 0; j < 4; j++)
            #pragma unroll
            for (int q = 0; q < 4; q++) acc[i][j][q] = 0.f;

    int seg = tid & 7, rb = tid >> 3;          // 8 segs/row, 32 row-groups
    const __nv_bfloat16* gsrc[4];
    gsrc[0] = Ah + (size_t)m0 * K;
    gsrc[1] = Al + (size_t)m0 * K;
    gsrc[2] = Bh + (size_t)n0 * K;
    gsrc[3] = Bl + (size_t)n0 * K;

    int lrow = lane & 15, lk = (lane >> 4) << 3;
    uint32_t aoff = (uint32_t)((wm*64 + lrow) * PITCHB + lk * 2);
    uint32_t boff = (uint32_t)((wn*32 + lrow) * PITCHB + lk * 2);

    int nc = K / KC;

    // prologue: chunk 0 -> stage 0
    #pragma unroll
    for (int t = 0; t < 4; t++)
        #pragma unroll
        for (int i = 0; i < 4; i++) {
            int row = rb + i * 32;
            uint32_t dst = sb + t*TILEB + (uint32_t)(row * PITCHB + seg * 16);
            CP16(dst, (const char*)(gsrc[t] + (size_t)row * K) + seg * 16);
        }
    CP_COMMIT();

    for (int c = 0; c < nc; c++) {
        if (c + 1 < nc) {
            int ns = (c + 1) & 1;
            int k0 = (c + 1) * KC;
            #pragma unroll
            for (int t = 0; t < 4; t++)
                #pragma unroll
                for (int i = 0; i < 4; i++) {
                    int row = rb + i * 32;
                    uint32_t dst = sb + ns*STAGEB + t*TILEB
                                 + (uint32_t)(row * PITCHB + seg * 16);
                    CP16(dst, (const char*)(gsrc[t] + (size_t)row * K + k0) + seg * 16);
                }
            CP_COMMIT();
            CP_WAIT1();
        } else {
            CP_WAIT0();
        }
        __syncthreads();

        uint32_t base = sb + (c & 1) * STAGEB;
        #pragma unroll
        for (int kk = 0; kk < KC; kk += 16) {
            uint32_t ah4[4][4], al4[4][4], bb[2][4];
            #pragma unroll
            for (int mt = 0; mt < 4; mt++)
                LDSM4(ah4[mt], base + aoff + mt*(16*PITCHB) + kk*2);
            #pragma unroll
            for (int mt = 0; mt < 4; mt++)
                LDSM4(al4[mt], base + TILEB + aoff + mt*(16*PITCHB) + kk*2);
            #pragma unroll
            for (int nt2 = 0; nt2 < 2; nt2++)
                LDSM4(bb[nt2], base + 2*TILEB + boff + nt2*(16*PITCHB) + kk*2);
            #pragma unroll
            for (int mt = 0; mt < 4; mt++)               // Ah*Bh
                #pragma unroll
                for (int nt = 0; nt < 4; nt++)
                    MMA16816(acc[mt][nt], ah4[mt], bb[nt>>1][nt&1], bb[nt>>1][2+(nt&1)]);
            #pragma unroll
            for (int mt = 0; mt < 4; mt++)               // Al*Bh
                #pragma unroll
                for (int nt = 0; nt < 4; nt++)
                    MMA16816(acc[mt][nt], al4[mt], bb[nt>>1][nt&1], bb[nt>>1][2+(nt&1)]);
            #pragma unroll
            for (int nt2 = 0; nt2 < 2; nt2++)            // reuse bb regs for Bl
                LDSM4(bb[nt2], base + 3*TILEB + boff + nt2*(16*PITCHB) + kk*2);
            #pragma unroll
            for (int mt = 0; mt < 4; mt++)               // Ah*Bl
                #pragma unroll
                for (int nt = 0; nt < 4; nt++)
                    MMA16816(acc[mt][nt], ah4[mt], bb[nt>>1][nt&1], bb[nt>>1][2+(nt&1)]);
        }
        __syncthreads();
    }

    int r0 = lane >> 2, cl = (lane & 3) * 2;
    #pragma unroll
    for (int nt = 0; nt < 4; nt++) {
        int col = n0 + wn*32 + nt*8 + cl;
        float bx = bias[col], by = bias[col+1];
        #pragma unroll
        for (int mt = 0; mt < 4; mt++) {
            int row = m0 + wm*64 + mt*16 + r0;
            float v0 = acc[mt][nt][0] + bx, v1 = acc[mt][nt][1] + by;
            float v2 = acc[mt][nt][2] + bx, v3 = acc[mt][nt][3] + by;
            if (relu) {
                v0 = fmaxf(v0, 0.f); v1 = fmaxf(v1, 0.f);
                v2 = fmaxf(v2, 0.f); v3 = fmaxf(v3, 0.f);
            }
            *(float2*)(C + (size_t)row * N + col)       = make_float2(v0, v1);
            *(float2*)(C + (size_t)(row + 8) * N + col) = make_float2(v2, v3);
        }
    }
}

// ---------------------------------------------------------------------------
// Attention scores (bf16 HMMA): S[bh,q,k] = (Q . K)/32, masked. fp32 out.
// CTA tile 128q x 128k, K=64 single shot. 36KB static smem.
// ---------------------------------------------------------------------------
__global__ __launch_bounds__(256)
void attn_scores_hmma(const __nv_bfloat16* __restrict__ qh,
                      const __nv_bfloat16* __restrict__ kh,
                      const int* __restrict__ mask, float* __restrict__ Sc) {
    __shared__ char smem2[2*18432];
    uint32_t sb = smem_u32(smem2);
    int tid = threadIdx.x, lane = tid & 31, wid = tid >> 5;
    int wm = wid >> 2, wn = wid & 3;
    int bh = blockIdx.z, q0 = blockIdx.y * 128, k0 = blockIdx.x * 128;
    int b = bh >> 4;

    int seg = tid & 7, rb = tid >> 3;
    const __nv_bfloat16* qg = qh + ((size_t)bh*S_ + q0) * 64;
    const __nv_bfloat16* kg = kh + ((size_t)bh*S_ + k0) * 64;
    #pragma unroll
    for (int i = 0; i < 4; i++) {
        int row = rb + i * 32;
        CP16(sb +         (uint32_t)(row*PITCHB + seg*16), (const char*)(qg + (size_t)row*64) + seg*16);
        CP16(sb + 18432 + (uint32_t)(row*PITCHB + seg*16), (const char*)(kg + (size_t)row*64) + seg*16);
    }
    CP_COMMIT(); CP_WAIT0();
    __syncthreads();

    int lrow = lane & 15, lk = (lane >> 4) << 3;
    uint32_t aoff = (uint32_t)((wm*64 + lrow)*PITCHB + lk*2);
    uint32_t boff = 18432u + (uint32_t)((wn*32 + lrow)*PITCHB + lk*2);

    float acc[4][4][4];
    #pragma unroll
    for (int i = 0; i < 4; i++)
        #pragma unroll
        for (int j = 0; j < 4; j++)
            #pragma unroll
            for (int q = 0; q < 4; q++) acc[i][j][q] = 0.f;

    #pragma unroll
    for (int kk = 0; kk < 64; kk += 16) {
        uint32_t ah4[4][4], bb[2][4];
        #pragma unroll
        for (int mt = 0; mt < 4; mt++)
            LDSM4(ah4[mt], sb + aoff + mt*(16*PITCHB) + kk*2);
        #pragma unroll
        for (int nt2 = 0; nt2 < 2; nt2++)
            LDSM4(bb[nt2], sb + boff + nt2*(16*PITCHB) + kk*2);
        #pragma unroll
        for (int mt = 0; mt < 4; mt++)
            #pragma unroll
            for (int nt = 0; nt < 4; nt++)
                MMA16816(acc[mt][nt], ah4[mt], bb[nt>>1][nt&1], bb[nt>>1][2+(nt&1)]);
    }

    const float inv = 1.0f / 32.0f;
    int r0 = lane >> 2, cl = (lane & 3) * 2;
    #pragma unroll
    for (int nt = 0; nt < 4; nt++) {
        int col = k0 + wn*32 + nt*8 + cl;
        int mk0 = mask[b*S_ + col], mk1 = mask[b*S_ + col + 1];
        #pragma unroll
        for (int mt = 0; mt < 4; mt++) {
            int qrow = q0 + wm*64 + mt*16 + r0;
            float2 o0, o1;
            o0.x = mk0 ? acc[mt][nt][0]*inv : -1e9f;
            o0.y = mk1 ? acc[mt][nt][1]*inv : -1e9f;
            o1.x = mk0 ? acc[mt][nt][2]*inv : -1e9f;
            o1.y = mk1 ? acc[mt][nt][3]*inv : -1e9f;
            *(float2*)(Sc + ((size_t)bh*S_ + qrow)*S_ + col)     = o0;
            *(float2*)(Sc + ((size_t)bh*S_ + qrow + 8)*S_ + col) = o1;
        }
    }
}

// ---------------------------------------------------------------------------
// AV (bf16 HMMA): O[b,q,h*64+d] = sum_s P[bh,q,s] * Vt[bh,d,s].
// CTA tile 256q x 64d, 8 warps (4x2, warp 64x32), k-chunk 64, 2-stage.
// ---------------------------------------------------------------------------
#define AV_PT   (256*PITCHB)          // 36864
#define AV_VT   (64*PITCHB)           // 9216
#define AV_ST   (AV_PT + AV_VT)       // 46080
#define AV_SMEM (2*AV_ST)             // 92160

__global__ __launch_bounds__(256)
void attn_av_hmma(const __nv_bfloat16* __restrict__ P,
                  const __nv_bfloat16* __restrict__ Vt,
                  float* __restrict__ O) {
    uint32_t sb = smem_u32(dynsmem);
    int tid = threadIdx.x, lane = tid & 31, wid = tid >> 5;
    int wm = wid >> 1, wn = wid & 1;
    int bh = blockIdx.z, q0 = blockIdx.y * 256;
    int b = bh >> 4, h = bh & 15;

    float acc[4][4][4];
    #pragma unroll
    for (int i = 0; i < 4; i++)
        #pragma unroll
        for (int j = 0; j < 4; j++)
            #pragma unroll
            for (int q = 0; q < 4; q++) acc[i][j][q] = 0.f;

    int seg = tid & 7, rb = tid >> 3;
    const __nv_bfloat16* pg = P  + ((size_t)bh*S_ + q0) * S_;
    const __nv_bfloat16* vg = Vt + (size_t)bh * 64 * S_;

    int lrow = lane & 15, lk = (lane >> 4) << 3;
    uint32_t aoff = (uint32_t)((wm*64 + lrow)*PITCHB + lk*2);
    uint32_t boff = (uint32_t)AV_PT + (uint32_t)((wn*32 + lrow)*PITCHB + lk*2);

    // prologue chunk 0
    #pragma unroll
    for (int i = 0; i < 8; i++) {
        int row = rb + i * 32;
        CP16(sb + (uint32_t)(row*PITCHB + seg*16), (const char*)(pg + (size_t)row*S_) + seg*16);
    }
    #pragma unroll
    for (int i = 0; i < 2; i++) {
        int row = rb + i * 32;
        CP16(sb + AV_PT + (uint32_t)(row*PITCHB + seg*16), (const char*)(vg + (size_t)row*S_) + seg*16);
    }
    CP_COMMIT();

    for (int c = 0; c < S_/KC; c++) {
        if (c + 1 < S_/KC) {
            int ns = (c + 1) & 1;
            int k0 = (c + 1) * KC;
            #pragma unroll
            for (int i = 0; i < 8; i++) {
                int row = rb + i * 32;
                CP16(sb + ns*AV_ST + (uint32_t)(row*PITCHB + seg*16),
                     (const char*)(pg + (size_t)row*S_ + k0) + seg*16);
            }
            #pragma unroll
            for (int i = 0; i < 2; i++) {
                int row = rb + i * 32;
                CP16(sb + ns*AV_ST + AV_PT + (uint32_t)(row*PITCHB + seg*16),
                     (const char*)(vg + (size_t)row*S_ + k0) + seg*16);
            }
            CP_COMMIT();
            CP_WAIT1();
        } else {
            CP_WAIT0();
        }
        __syncthreads();

        uint32_t base = sb + (c & 1) * AV_ST;
        #pragma unroll
        for (int kk = 0; kk < KC; kk += 16) {
            uint32_t ah4[4][4], bb[2][4];
            #pragma unroll
            for (int mt = 0; mt < 4; mt++)
                LDSM4(ah4[mt], base + aoff + mt*(16*PITCHB) + kk*2);
            #pragma unroll
            for (int nt2 = 0; nt2 < 2; nt2++)
                LDSM4(bb[nt2], base + boff + nt2*(16*PITCHB) + kk*2);
            #pragma unroll
            for (int mt = 0; mt < 4; mt++)
                #pragma unroll
                for (int nt = 0; nt < 4; nt++)
                    MMA16816(acc[mt][nt], ah4[mt], bb[nt>>1][nt&1], bb[nt>>1][2+(nt&1)]);
        }
        __syncthreads();
    }

    int r0 = lane >> 2, cl = (lane & 3) * 2;
    #pragma unroll
    for (int nt = 0; nt < 4; nt++) {
        int col = h*64 + wn*32 + nt*8 + cl;
        #pragma unroll
        for (int mt = 0; mt < 4; mt++) {
            int qrow = q0 + wm*64 + mt*16 + r0;
            *(float2*)(O + (size_t)(b*S_ + qrow)*D_ + col)
                = make_float2(acc[mt][nt][0], acc[mt][nt][1]);
            *(float2*)(O + (size_t)(b*S_ + qrow + 8)*D_ + col)
                = make_float2(acc[mt][nt][2], acc[mt][nt][3]);
        }
    }
}

// ---------------------------------------------------------------------------
// q,k,v fp32 [M,D] -> bf16 head layouts: qh,kh [BH,S,64];  vt [BH,64,S]
// ---------------------------------------------------------------------------
__global__ void conv_qkv(const float* __restrict__ q, const float* __restrict__ k,
                         const float* __restrict__ v,
                         __nv_bfloat16* __restrict__ qh, __nv_bfloat16* __restrict__ kh,
                         __nv_bfloat16* __restrict__ vt) {
    int idx = blockIdx.x * blockDim.x + threadIdx.x;
    if (idx >= M_*D_) return;
    int row = idx >> 10, d = idx & 1023;
    int b = row >> 11, s = row & 2047;
    int hh = d >> 6, dd = d & 63;
    size_t bh = (size_t)b*16 + hh;
    size_t dst = (bh*S_ + s)*64 + dd;
    qh[dst] = __float2bfloat16(q[idx]);
    kh[dst] = __float2bfloat16(k[idx]);
    vt[(bh*64 + dd)*S_ + s] = __float2bfloat16(v[idx]);
}

// ---------------------------------------------------------------------------
// fp32 -> (bf16 hi, lo) split
// ---------------------------------------------------------------------------
__global__ void split_bf16(const float* __restrict__ x,
                           __nv_bfloat16* __restrict__ hi,
                           __nv_bfloat16* __restrict__ lo, int n4) {
    int i = blockIdx.x * blockDim.x + threadIdx.x;
    if (i >= n4) return;
    float4 v = ((const float4*)x)[i];
    __nv_bfloat16 h0 = __float2bfloat16(v.x);
    __nv_bfloat16 h1 = __float2bfloat16(v.y);
    __nv_bfloat16 h2 = __float2bfloat16(v.z);
    __nv_bfloat16 h3 = __float2bfloat16(v.w);
    __nv_bfloat16 l0 = __float2bfloat16(v.x - __bfloat162float(h0));
    __nv_bfloat16 l1 = __float2bfloat16(v.y - __bfloat162float(h1));
    __nv_bfloat16 l2 = __float2bfloat16(v.z - __bfloat162float(h2));
    __nv_bfloat16 l3 = __float2bfloat16(v.w - __bfloat162float(h3));
    ((__nv_bfloat162*)hi)[i*2]   = __nv_bfloat162(h0, h1);
    ((__nv_bfloat162*)hi)[i*2+1] = __nv_bfloat162(h2, h3);
    ((__nv_bfloat162*)lo)[i*2]   = __nv_bfloat162(l0, l1);
    ((__nv_bfloat162*)lo)[i*2+1] = __nv_bfloat162(l2, l3);
}

// ---------------------------------------------------------------------------
// Weight transpose + split:  W fp32 [K,N] -> th/tl bf16 [N,K]
// ---------------------------------------------------------------------------
__global__ void wsplit_t(const float* __restrict__ W,
                         __nv_bfloat16* __restrict__ th,
                         __nv_bfloat16* __restrict__ tl, int K, int N) {
    __shared__ float sh[32][33];
    int n0 = blockIdx.x * 32, k0 = blockIdx.y * 32;
    int tx = threadIdx.x, ty = threadIdx.y;
    #pragma unroll
    for (int i = 0; i < 4; i++)
        sh[ty + i*8][tx] = W[(size_t)(k0 + ty + i*8) * N + n0 + tx];
    __syncthreads();
    #pragma unroll
    for (int i = 0; i < 4; i++) {
        int n = n0 + ty + i*8;
        float v = sh[tx][ty + i*8];
        __nv_bfloat16 h = __float2bfloat16(v);
        __nv_bfloat16 l = __float2bfloat16(v - __bfloat162float(h));
        th[(size_t)n * K + k0 + tx] = h;
        tl[(size_t)n * K + k0 + tx] = l;
    }
}

// ---------------------------------------------------------------------------
// Reductions
// ---------------------------------------------------------------------------
__device__ __forceinline__ float warpSum(float v) {
    #pragma unroll
    for (int o = 16; o; o >>= 1) v += __shfl_xor_sync(0xffffffffu, v, o);
    return v;
}
__device__ __forceinline__ float warpMax(float v) {
    #pragma unroll
    for (int o = 16; o; o >>= 1) v = fmaxf(v, __shfl_xor_sync(0xffffffffu, v, o));
    return v;
}
__device__ __forceinline__ float blockSum(float v, float* sh) {
    int tid = threadIdx.x, lane = tid & 31, w = tid >> 5;
    v = warpSum(v);
    if (lane == 0) sh[w] = v;
    __syncthreads();
    float t = sh[0];
    #pragma unroll
    for (int i = 1; i < 8; i++) t += sh[i];
    __syncthreads();
    return t;
}
__device__ __forceinline__ float blockMax(float v, float* sh) {
    int tid = threadIdx.x, lane = tid & 31, w = tid >> 5;
    v = warpMax(v);
    if (lane == 0) sh[w] = v;
    __syncthreads();
    float t = sh[0];
    #pragma unroll
    for (int i = 1; i < 8; i++) t = fmaxf(t, sh[i]);
    __syncthreads();
    return t;
}

// ---------------------------------------------------------------------------
// PE + embed
// ---------------------------------------------------------------------------
__global__ void pe_kernel(float* __restrict__ pe) {
    int idx = blockIdx.x * blockDim.x + threadIdx.x;
    if (idx >= B_*D_) return;
    int b = idx / D_, d = idx % D_;
    int i = d >> 1;
    double c = -log(10000.0) / (double)D_;
    float divf = (float)exp((double)(2*i) * c);
    float ang  = (float)b / divf;
    double ad  = (double)ang;
    pe[idx] = (d & 1) ? (float)cos(ad) : (float)sin(ad);
}

__global__ void embed_kernel(const int* __restrict__ src,
                             const float* __restrict__ emb,
                             const float* __restrict__ pe,
                             float* __restrict__ x) {
    int idx = blockIdx.x * blockDim.x + threadIdx.x;
    if (idx >= M_*D_) return;
    int d  = idx & (D_-1);
    int bs = idx >> 10;
    int b  = bs >> 11;
    x[idx] = emb[(size_t)src[bs]*D_ + d] + pe[b*D_ + d];
}

// ---------------------------------------------------------------------------
// Row softmax: read fp32 scores, write bf16 probs.
// ---------------------------------------------------------------------------
__global__ __launch_bounds__(256)
void softmax_rows(const float* __restrict__ sc, __nv_bfloat16* __restrict__ p) {
    __shared__ float sh[8];
    size_t row = blockIdx.x;
    const float* in = sc + row * (size_t)S_;
    __nv_bfloat16* outp = p + row * (size_t)S_;
    int tid = threadIdx.x;
    float v[8];
    float mx = -INFINITY;
    #pragma unroll
    for (int j = 0; j < 8; j++) { v[j] = in[tid + j*256]; mx = fmaxf(mx, v[j]); }
    mx = blockMax(mx, sh);
    float s = 0.f;
    #pragma unroll
    for (int j = 0; j < 8; j++) { v[j] = expf(v[j] - mx); s += v[j]; }
    s = blockSum(s, sh);
    float inv = 1.0f / s;
    #pragma unroll
    for (int j = 0; j < 8; j++) outp[tid + j*256] = __float2bfloat16(v[j] * inv);
}

// ---------------------------------------------------------------------------
// out = LayerNorm(x + r) * g + be
// ---------------------------------------------------------------------------
__global__ __launch_bounds__(256)
void add_ln(const float* __restrict__ x, const float* __restrict__ rr,
            const float* __restrict__ g, const float* __restrict__ be,
            float* __restrict__ out) {
    __shared__ float sh[8];
    int m = blockIdx.x, tid = threadIdx.x;
    float4 v = *(const float4*)(x + (size_t)m*D_ + tid*4);
    float4 rv = *(const float4*)(rr + (size_t)m*D_ + tid*4);
    v.x += rv.x; v.y += rv.y; v.z += rv.z; v.w += rv.w;
    float s = v.x + v.y + v.z + v.w;
    s = blockSum(s, sh);
    float mean = s * (1.0f / D_);
    float d0 = v.x - mean, d1 = v.y - mean, d2 = v.z - mean, d3 = v.w - mean;
    float sq = d0*d0 + d1*d1 + d2*d2 + d3*d3;
    sq = blockSum(sq, sh);
    float var = sq * (1.0f / D_);
    float rstd = rsqrtf(var + 1e-5f);
    float4 gg = *(const float4*)(g + tid*4);
    float4 bb = *(const float4*)(be + tid*4);
    float4 o;
    o.x = d0*rstd*gg.x + bb.x;
    o.y = d1*rstd*gg.y + bb.y;
    o.z = d2*rstd*gg.z + bb.z;
    o.w = d3*rstd*gg.w + bb.w;
    *(float4*)(out + (size_t)m*D_ + tid*4) = o;
}

// ---------------------------------------------------------------------------
// Launch
// ---------------------------------------------------------------------------
extern "C" void kernel_launch(void* const* d_in, const int* in_sizes, int n_in,
                              void* d_out, int out_size) {
    const int*   src  = (const int*)  d_in[0];
    const int*   mask = (const int*)  d_in[1];
    const float* emb  = (const float*)d_in[2];
    const float* Wq   = (const float*)d_in[3];
    const float* bq   = (const float*)d_in[4];
    const float* Wk   = (const float*)d_in[5];
    const float* bk   = (const float*)d_in[6];
    const float* Wv   = (const float*)d_in[7];
    const float* bv   = (const float*)d_in[8];
    const float* Wo   = (const float*)d_in[9];
    const float* bo   = (const float*)d_in[10];
    const float* W1   = (const float*)d_in[11];
    const float* b1   = (const float*)d_in[12];
    const float* W2   = (const float*)d_in[13];
    const float* b2   = (const float*)d_in[14];
    const float* g1   = (const float*)d_in[15];
    const float* be1  = (const float*)d_in[16];
    const float* g2   = (const float*)d_in[17];
    const float* be2  = (const float*)d_in[18];
    float* out = (float*)d_out;

    float *x, *q, *k, *v, *a, *r, *h, *s, *pe;
    __nv_bfloat16 *wth, *wtl, *ah, *al, *qh, *kh, *vt, *p;
    cudaGetSymbolAddress((void**)&x,  g_x);
    cudaGetSymbolAddress((void**)&q,  g_q);
    cudaGetSymbolAddress((void**)&k,  g_k);
    cudaGetSymbolAddress((void**)&v,  g_v);
    cudaGetSymbolAddress((void**)&a,  g_a);
    cudaGetSymbolAddress((void**)&r,  g_r);
    cudaGetSymbolAddress((void**)&h,  g_h);
    cudaGetSymbolAddress((void**)&s,  g_s);
    cudaGetSymbolAddress((void**)&pe, g_pe);
    cudaGetSymbolAddress((void**)&wth, g_wth);
    cudaGetSymbolAddress((void**)&wtl, g_wtl);
    cudaGetSymbolAddress((void**)&ah, g_ah);
    cudaGetSymbolAddress((void**)&al, g_al);
    cudaGetSymbolAddress((void**)&qh, g_qh);
    cudaGetSymbolAddress((void**)&kh, g_kh);
    cudaGetSymbolAddress((void**)&vt, g_vt);
    cudaGetSymbolAddress((void**)&p,  g_p);

    cudaFuncSetAttribute(hmma_gemm,    cudaFuncAttributeMaxDynamicSharedMemorySize, GSMEM);
    cudaFuncSetAttribute(attn_av_hmma, cudaFuncAttributeMaxDynamicSharedMemorySize, AV_SMEM);

    pe_kernel<<<(B_*D_ + 255)/256, 256>>>(pe);
    embed_kernel<<<(M_*D_ + 255)/256, 256>>>(src, emb, pe, x);

    dim3 tb(32, 8);
    for (int l = 0; l < L_; l++) {
        size_t wb = (size_t)l * WL_;
        wsplit_t<<<dim3(D_/32,  D_/32),  tb>>>(Wq + (size_t)l*D_*D_,  wth + wb,         wtl + wb,         D_, D_);
        wsplit_t<<<dim3(D_/32,  D_/32),  tb>>>(Wk + (size_t)l*D_*D_,  wth + wb + MB1,   wtl + wb + MB1,   D_, D_);
        wsplit_t<<<dim3(D_/32,  D_/32),  tb>>>(Wv + (size_t)l*D_*D_,  wth + wb + 2*MB1, wtl + wb + 2*MB1, D_, D_);
        wsplit_t<<<dim3(D_/32,  D_/32),  tb>>>(Wo + (size_t)l*D_*D_,  wth + wb + 3*MB1, wtl + wb + 3*MB1, D_, D_);
        wsplit_t<<<dim3(FF_/32, D_/32),  tb>>>(W1 + (size_t)l*D_*FF_, wth + wb + 4*MB1, wtl + wb + 4*MB1, D_, FF_);
        wsplit_t<<<dim3(D_/32,  FF_/32), tb>>>(W2 + (size_t)l*FF_*D_, wth + wb + 8*MB1, wtl + wb + 8*MB1, FF_, D_);
    }

    dim3 gProj(D_/128,  M_/128);
    dim3 gFF1 (FF_/128, M_/128);
    dim3 gScore(S_/128, S_/128, BH_);
    dim3 gAV   (1,      S_/256, BH_);
    const int nXD4 = M_*D_/4, nXF4 = M_*FF_/4;

    for (int l = 0; l < L_; l++) {
        size_t wb = (size_t)l * WL_;
        const float* bq_l = bq + (size_t)l*D_;
        const float* bk_l = bk + (size_t)l*D_;
        const float* bv_l = bv + (size_t)l*D_;
        const float* bo_l = bo + (size_t)l*D_;
        const float* b1_l = b1 + (size_t)l*FF_;
        const float* b2_l = b2 + (size_t)l*D_;
        const float* g1_l = g1 + (size_t)l*D_;
        const float* be1_l= be1+ (size_t)l*D_;
        const float* g2_l = g2 + (size_t)l*D_;
        const float* be2_l= be2+ (size_t)l*D_;

        split_bf16<<<(nXD4 + 255)/256, 256>>>(x, ah, al, nXD4);
        hmma_gemm<<<gProj, 256, GSMEM>>>(ah, al, wth + wb,         wtl + wb,         bq_l, q, M_, D_, D_, 0);
        hmma_gemm<<<gProj, 256, GSMEM>>>(ah, al, wth + wb + MB1,   wtl + wb + MB1,   bk_l, k, M_, D_, D_, 0);
        hmma_gemm<<<gProj, 256, GSMEM>>>(ah, al, wth + wb + 2*MB1, wtl + wb + 2*MB1, bv_l, v, M_, D_, D_, 0);

        conv_qkv<<<(M_*D_ + 255)/256, 256>>>(q, k, v, qh, kh, vt);
        attn_scores_hmma<<<gScore, 256>>>(qh, kh, mask, s);
        softmax_rows<<<BH_*S_, 256>>>(s, p);
        attn_av_hmma<<<gAV, 256, AV_SMEM>>>(p, vt, a);

        split_bf16<<<(nXD4 + 255)/256, 256>>>(a, ah, al, nXD4);
        hmma_gemm<<<gProj, 256, GSMEM>>>(ah, al, wth + wb + 3*MB1, wtl + wb + 3*MB1, bo_l, r, M_, D_, D_, 0);
        add_ln<<<M_, 256>>>(x, r, g1_l, be1_l, x);

        split_bf16<<<(nXD4 + 255)/256, 256>>>(x, ah, al, nXD4);
        hmma_gemm<<<gFF1, 256, GSMEM>>>(ah, al, wth + wb + 4*MB1, wtl + wb + 4*MB1, b1_l, h, M_, FF_, D_, 1);
        split_bf16<<<(nXF4 + 255)/256, 256>>>(h, ah, al, nXF4);
        hmma_gemm<<<gProj, 256, GSMEM>>>(ah, al, wth + wb + 8*MB1, wtl + wb + 8*MB1, b2_l, r, M_, D_, FF_, 0);

        float* dst = (l == L_-1) ? out : x;
        add_ln<<<M_, 256>>>(x, r, g2_l, be2_l, dst);
    }
}

// round 10
// speedup vs baseline: 2.9187x; 1.1328x over previous
#include <cuda_runtime.h>
#include <cuda_bf16.h>
#include <math.h>
#include <stdint.h>

// ---------------------------------------------------------------------------
// Problem constants
// ---------------------------------------------------------------------------
#define B_  2
#define S_  2048
#define D_  1024
#define H_  16
#define DK_ 64
#define FF_ 4096
#define L_  6
#define M_  (B_*S_)          // 4096 rows
#define BH_ (B_*H_)          // 32

// ---------------------------------------------------------------------------
// Scratch (device globals — no allocations allowed)
// ---------------------------------------------------------------------------
__device__ float g_x[M_*D_];                 // running activation (fp32)
__device__ float g_r[M_*D_];                 // residual branch (fp32)
__device__ float g_v[M_*D_];                 // V projection (fp32)
__device__ float g_pe[B_*D_];

__device__ __nv_bfloat16 g_xh[M_*D_];        // split of x
__device__ __nv_bfloat16 g_xl[M_*D_];
__device__ __nv_bfloat16 g_oh[M_*D_];        // split of attention output
__device__ __nv_bfloat16 g_ol[M_*D_];
__device__ __nv_bfloat16 g_hh[M_*FF_];       // split of FF hidden
__device__ __nv_bfloat16 g_hl[M_*FF_];

__device__ __nv_bfloat16 g_qh[M_*D_];        // Q  [BH, S, 64]
__device__ __nv_bfloat16 g_kh[M_*D_];        // K  [BH, S, 64]
__device__ __nv_bfloat16 g_vt[M_*D_];        // V^T [BH, 64, S]

// bf16 split weights, transposed to [N,K]
#define MB1 (1u<<20)
#define WL_ (12u*MB1)
__device__ __nv_bfloat16 g_wth[6*12*1024*1024];
__device__ __nv_bfloat16 g_wtl[6*12*1024*1024];

// ---------------------------------------------------------------------------
// PTX helpers (portable: cp.async, ldmatrix, mma.sync)
// ---------------------------------------------------------------------------
__device__ __forceinline__ uint32_t smem_u32(const void* p) {
    return (uint32_t)__cvta_generic_to_shared(p);
}
#define CP16(dst, src) \
    asm volatile("cp.async.cg.shared.global [%0], [%1], 16;" :: "r"(dst), "l"(src) : "memory")
#define CP_COMMIT() asm volatile("cp.async.commit_group;" ::: "memory")
#define CP_WAIT1()  asm volatile("cp.async.wait_group 1;" ::: "memory")
#define CP_WAIT0()  asm volatile("cp.async.wait_group 0;" ::: "memory")

#define LDSM4(r, addr) \
    asm volatile("ldmatrix.sync.aligned.m8n8.x4.shared.b16 {%0,%1,%2,%3}, [%4];" \
        : "=r"((r)[0]), "=r"((r)[1]), "=r"((r)[2]), "=r"((r)[3]) : "r"(addr))

#define MMA16816(c, a, b0, b1) \
    asm volatile("mma.sync.aligned.m16n8k16.row.col.f32.bf16.bf16.f32 " \
        "{%0,%1,%2,%3}, {%4,%5,%6,%7}, {%8,%9}, {%0,%1,%2,%3};" \
        : "+f"((c)[0]), "+f"((c)[1]), "+f"((c)[2]), "+f"((c)[3]) \
        : "r"((a)[0]), "r"((a)[1]), "r"((a)[2]), "r"((a)[3]), "r"(b0), "r"(b1))

__device__ __forceinline__ uint32_t f2bf2(float lo, float hi) {
    __nv_bfloat162 t = __floats2bfloat162_rn(lo, hi);
    return *(uint32_t*)&t;
}
__device__ __forceinline__ __nv_bfloat162 split_hi2(float a, float b,
                                                    __nv_bfloat162* lo2) {
    __nv_bfloat16 ha = __float2bfloat16(a), hb = __float2bfloat16(b);
    *lo2 = __nv_bfloat162(__float2bfloat16(a - __bfloat162float(ha)),
                          __float2bfloat16(b - __bfloat162float(hb)));
    return __nv_bfloat162(ha, hb);
}

// ---------------------------------------------------------------------------
// bf16x3 HMMA GEMM with fused epilogues.
// A*: bf16 [M,K] rm.  B*: bf16 [N,K] rm (W^T).  128x128 tile, 8 warps (64x32),
// K-chunk 64, pitch 144B, 2-stage cp.async, 144KB smem, 1 CTA/SM.
// mode: 0 = fp32 C;  1 = ReLU + hi/lo bf16 split;  2 = bf16 head-layout [BH,S,64]
// ---------------------------------------------------------------------------
#define OUT_F32   0
#define OUT_SPLIT 1
#define OUT_HEAD  2

#define KC      64
#define PITCHB  144
#define TILEB   (128*PITCHB)          // 18432
#define STAGEB  (4*TILEB)             // 73728
#define GSMEM   (2*STAGEB)            // 147456

extern __shared__ char dynsmem[];

__global__ __launch_bounds__(256, 1)
void hmma_gemm(const __nv_bfloat16* __restrict__ Ah, const __nv_bfloat16* __restrict__ Al,
               const __nv_bfloat16* __restrict__ Bh, const __nv_bfloat16* __restrict__ Bl,
               const float* __restrict__ bias, float* __restrict__ C,
               __nv_bfloat16* __restrict__ Chi, __nv_bfloat16* __restrict__ Clo,
               int M, int N, int K, int mode) {
    uint32_t sb = smem_u32(dynsmem);
    int tid = threadIdx.x, lane = tid & 31, wid = tid >> 5;
    int wm = wid >> 2, wn = wid & 3;
    int m0 = blockIdx.y * 128, n0 = blockIdx.x * 128;

    float acc[4][4][4];
    #pragma unroll
    for (int i = 0; i < 4; i++)
        #pragma unroll
        for (int j = 0; j < 4; j++)
            #pragma unroll
            for (int q = 0; q < 4; q++) acc[i][j][q] = 0.f;

    int seg = tid & 7, rb = tid >> 3;
    const __nv_bfloat16* gsrc[4];
    gsrc[0] = Ah + (size_t)m0 * K;
    gsrc[1] = Al + (size_t)m0 * K;
    gsrc[2] = Bh + (size_t)n0 * K;
    gsrc[3] = Bl + (size_t)n0 * K;

    int lrow = lane & 15, lk16 = (lane >> 4) * 16;
    uint32_t aoff = (uint32_t)((wm*64 + lrow) * PITCHB) + lk16;
    uint32_t boff = (uint32_t)((wn*32 + lrow) * PITCHB) + lk16;

    int nc = K / KC;

    #pragma unroll
    for (int t = 0; t < 4; t++)
        #pragma unroll
        for (int i = 0; i < 4; i++) {
            int row = rb + i * 32;
            CP16(sb + t*TILEB + (uint32_t)(row * PITCHB + seg * 16),
                 (const char*)(gsrc[t] + (size_t)row * K) + seg * 16);
        }
    CP_COMMIT();

    for (int c = 0; c < nc; c++) {
        if (c + 1 < nc) {
            int ns = (c + 1) & 1;
            int k0 = (c + 1) * KC;
            #pragma unroll
            for (int t = 0; t < 4; t++)
                #pragma unroll
                for (int i = 0; i < 4; i++) {
                    int row = rb + i * 32;
                    CP16(sb + ns*STAGEB + t*TILEB + (uint32_t)(row * PITCHB + seg * 16),
                         (const char*)(gsrc[t] + (size_t)row * K + k0) + seg * 16);
                }
            CP_COMMIT();
            CP_WAIT1();
        } else {
            CP_WAIT0();
        }
        __syncthreads();

        uint32_t base = sb + (c & 1) * STAGEB;
        #pragma unroll
        for (int kk = 0; kk < KC; kk += 16) {
            uint32_t ah4[4][4], al4[4][4], bb[2][4];
            #pragma unroll
            for (int mt = 0; mt < 4; mt++)
                LDSM4(ah4[mt], base + aoff + mt*(16*PITCHB) + kk*2);
            #pragma unroll
            for (int mt = 0; mt < 4; mt++)
                LDSM4(al4[mt], base + TILEB + aoff + mt*(16*PITCHB) + kk*2);
            #pragma unroll
            for (int nt2 = 0; nt2 < 2; nt2++)
                LDSM4(bb[nt2], base + 2*TILEB + boff + nt2*(16*PITCHB) + kk*2);
            #pragma unroll
            for (int mt = 0; mt < 4; mt++)               // Ah*Bh
                #pragma unroll
                for (int nt = 0; nt < 4; nt++)
                    MMA16816(acc[mt][nt], ah4[mt], bb[nt>>1][nt&1], bb[nt>>1][2+(nt&1)]);
            #pragma unroll
            for (int mt = 0; mt < 4; mt++)               // Al*Bh
                #pragma unroll
                for (int nt = 0; nt < 4; nt++)
                    MMA16816(acc[mt][nt], al4[mt], bb[nt>>1][nt&1], bb[nt>>1][2+(nt&1)]);
            #pragma unroll
            for (int nt2 = 0; nt2 < 2; nt2++)            // reuse bb for Bl
                LDSM4(bb[nt2], base + 3*TILEB + boff + nt2*(16*PITCHB) + kk*2);
            #pragma unroll
            for (int mt = 0; mt < 4; mt++)               // Ah*Bl
                #pragma unroll
                for (int nt = 0; nt < 4; nt++)
                    MMA16816(acc[mt][nt], ah4[mt], bb[nt>>1][nt&1], bb[nt>>1][2+(nt&1)]);
        }
        __syncthreads();
    }

    int r0 = lane >> 2, cl = (lane & 3) * 2;
    #pragma unroll
    for (int nt = 0; nt < 4; nt++) {
        int col = n0 + wn*32 + nt*8 + cl;
        float bx = bias[col], by = bias[col+1];
        #pragma unroll
        for (int mt = 0; mt < 4; mt++) {
            int row = m0 + wm*64 + mt*16 + r0;
            float v0 = acc[mt][nt][0] + bx, v1 = acc[mt][nt][1] + by;
            float v2 = acc[mt][nt][2] + bx, v3 = acc[mt][nt][3] + by;
            if (mode == OUT_F32) {
                *(float2*)(C + (size_t)row * N + col)       = make_float2(v0, v1);
                *(float2*)(C + (size_t)(row + 8) * N + col) = make_float2(v2, v3);
            } else if (mode == OUT_SPLIT) {
                v0 = fmaxf(v0, 0.f); v1 = fmaxf(v1, 0.f);
                v2 = fmaxf(v2, 0.f); v3 = fmaxf(v3, 0.f);
                __nv_bfloat162 lo2;
                __nv_bfloat162 hi2 = split_hi2(v0, v1, &lo2);
                *(__nv_bfloat162*)(Chi + (size_t)row * N + col) = hi2;
                *(__nv_bfloat162*)(Clo + (size_t)row * N + col) = lo2;
                hi2 = split_hi2(v2, v3, &lo2);
                *(__nv_bfloat162*)(Chi + (size_t)(row+8) * N + col) = hi2;
                *(__nv_bfloat162*)(Clo + (size_t)(row+8) * N + col) = lo2;
            } else {                                     // OUT_HEAD
                int b = row >> 11, sidx = row & 2047;
                int hh = col >> 6, dd = col & 63;
                size_t base0 = (((size_t)b*H_ + hh)*S_ + sidx)*64 + dd;
                *(__nv_bfloat162*)(Chi + base0) =
                    __nv_bfloat162(__float2bfloat16(v0), __float2bfloat16(v1));
                *(__nv_bfloat162*)(Chi + base0 + 8*64) =
                    __nv_bfloat162(__float2bfloat16(v2), __float2bfloat16(v3));
            }
        }
    }
}

// ---------------------------------------------------------------------------
// Fused flash attention.  Q,K: [BH,S,64] bf16.  Vt: [BH,64,S] bf16.
// Out: hi/lo bf16 split of attention output, layout [M, D].
// CTA: 128 q rows, 8 warps x 16 rows; k-tiles of 128, 2-stage cp.async.
// ---------------------------------------------------------------------------
#define FQP 144
#define QSZ (128*FQP)                 // 18432 (also K tile size)
#define FVP 272
#define VSZ (64*FVP)                  // 17408
#define MSZ 512
#define STG (QSZ + VSZ + MSZ)         // 36352
#define FSMEM (QSZ + 2*STG)           // 91136

__global__ __launch_bounds__(256, 1)
void flash_attn(const __nv_bfloat16* __restrict__ qh,
                const __nv_bfloat16* __restrict__ kh,
                const __nv_bfloat16* __restrict__ vt,
                const int* __restrict__ mask,
                __nv_bfloat16* __restrict__ Ohi, __nv_bfloat16* __restrict__ Olo) {
    uint32_t sb = smem_u32(dynsmem);
    int tid = threadIdx.x, lane = tid & 31, w = tid >> 5;
    int bh = blockIdx.y, q0 = blockIdx.x * 128;
    int b = bh >> 4, h = bh & 15;

    const __nv_bfloat16* qg = qh + ((size_t)bh*S_ + q0) * 64;
    const __nv_bfloat16* kg = kh + (size_t)bh*S_ * 64;
    const __nv_bfloat16* vg = vt + (size_t)bh*64 * S_;
    const int* mg = mask + b*S_;

    int seg = tid & 7,  rb  = tid >> 3;     // K/Q: 128 rows x 8 segs
    int vseg = tid & 15, vrb = tid >> 4;    // V: 64 rows x 16 segs

    // Q + stage 0
    #pragma unroll
    for (int i = 0; i < 4; i++) {
        int row = rb + i * 32;
        CP16(sb + (uint32_t)(row*FQP + seg*16),
             (const char*)(qg + (size_t)row*64) + seg*16);
        CP16(sb + QSZ + (uint32_t)(row*FQP + seg*16),
             (const char*)(kg + (size_t)row*64) + seg*16);
    }
    #pragma unroll
    for (int i = 0; i < 4; i++) {
        int row = vrb + i * 16;
        CP16(sb + QSZ + QSZ + (uint32_t)(row*FVP + vseg*16),
             (const char*)(vg + (size_t)row*S_) + vseg*16);
    }
    if (tid < 32) CP16(sb + QSZ + QSZ + VSZ + tid*16, (const char*)mg + tid*16);
    CP_COMMIT();

    uint32_t aoffQ = (uint32_t)((w*16 + (lane&15))*FQP) + (lane>>4)*16;
    uint32_t koff  = (uint32_t)((lane&15)*FQP) + (lane>>4)*16;
    uint32_t voff  = (uint32_t)((lane&15)*FVP) + (lane>>4)*16;

    float m0 = -INFINITY, m1 = -INFINITY, l0 = 0.f, l1 = 0.f;
    float oacc[8][4];
    #pragma unroll
    for (int i = 0; i < 8; i++)
        #pragma unroll
        for (int q = 0; q < 4; q++) oacc[i][q] = 0.f;

    const float INV32 = 1.0f / 32.0f;

    for (int j = 0; j < S_/128; j++) {
        if (j + 1 < S_/128) {
            uint32_t stg2 = sb + QSZ + ((j+1)&1)*STG;
            const char* ks = (const char*)(kg + (size_t)(j+1)*128*64);
            #pragma unroll
            for (int i = 0; i < 4; i++) {
                int row = rb + i * 32;
                CP16(stg2 + (uint32_t)(row*FQP + seg*16), ks + (size_t)row*128 + seg*16);
            }
            #pragma unroll
            for (int i = 0; i < 4; i++) {
                int row = vrb + i * 16;
                CP16(stg2 + QSZ + (uint32_t)(row*FVP + vseg*16),
                     (const char*)(vg + (size_t)row*S_ + (j+1)*128) + vseg*16);
            }
            if (tid < 32) CP16(stg2 + QSZ + VSZ + tid*16,
                               (const char*)(mg + (j+1)*128) + tid*16);
            CP_COMMIT();
            CP_WAIT1();
        } else {
            CP_WAIT0();
        }
        __syncthreads();

        uint32_t stg = sb + QSZ + (j&1)*STG;
        const int* msk = (const int*)(dynsmem + QSZ + (j&1)*STG + QSZ + VSZ);

        // S = Q K^T for this k-tile
        float sacc[16][4];
        #pragma unroll
        for (int i = 0; i < 16; i++)
            #pragma unroll
            for (int q = 0; q < 4; q++) sacc[i][q] = 0.f;

        #pragma unroll
        for (int kk = 0; kk < 64; kk += 16) {
            uint32_t af[4];
            LDSM4(af, sb + aoffQ + kk*2);
            #pragma unroll
            for (int nt2 = 0; nt2 < 8; nt2++) {
                uint32_t bf4[4];
                LDSM4(bf4, stg + koff + nt2*(16*FQP) + kk*2);
                MMA16816(sacc[2*nt2],   af, bf4[0], bf4[2]);
                MMA16816(sacc[2*nt2+1], af, bf4[1], bf4[3]);
            }
        }

        // scale + mask + row-max
        float rm0 = -INFINITY, rm1 = -INFINITY;
        #pragma unroll
        for (int nt = 0; nt < 16; nt++) {
            int col = nt*8 + (lane&3)*2;
            int2 mk = *(const int2*)(msk + col);
            float s0 = mk.x ? sacc[nt][0]*INV32 : -1e9f;
            float s1 = mk.y ? sacc[nt][1]*INV32 : -1e9f;
            float s2 = mk.x ? sacc[nt][2]*INV32 : -1e9f;
            float s3 = mk.y ? sacc[nt][3]*INV32 : -1e9f;
            sacc[nt][0] = s0; sacc[nt][1] = s1; sacc[nt][2] = s2; sacc[nt][3] = s3;
            rm0 = fmaxf(rm0, fmaxf(s0, s1));
            rm1 = fmaxf(rm1, fmaxf(s2, s3));
        }
        rm0 = fmaxf(rm0, __shfl_xor_sync(0xffffffffu, rm0, 1));
        rm0 = fmaxf(rm0, __shfl_xor_sync(0xffffffffu, rm0, 2));
        rm1 = fmaxf(rm1, __shfl_xor_sync(0xffffffffu, rm1, 1));
        rm1 = fmaxf(rm1, __shfl_xor_sync(0xffffffffu, rm1, 2));

        float mn0 = fmaxf(m0, rm0), mn1 = fmaxf(m1, rm1);
        float f0 = __expf(m0 - mn0), f1 = __expf(m1 - mn1);
        m0 = mn0; m1 = mn1;
        l0 *= f0; l1 *= f1;
        #pragma unroll
        for (int i = 0; i < 8; i++) {
            oacc[i][0] *= f0; oacc[i][1] *= f0;
            oacc[i][2] *= f1; oacc[i][3] *= f1;
        }

        // P = exp(S - m);  O += P V  (per 16-wide k-chunk)
        float sum0 = 0.f, sum1 = 0.f;
        #pragma unroll
        for (int t = 0; t < 8; t++) {
            float p00 = __expf(sacc[2*t][0] - m0),   p01 = __expf(sacc[2*t][1] - m0);
            float p02 = __expf(sacc[2*t][2] - m1),   p03 = __expf(sacc[2*t][3] - m1);
            float p10 = __expf(sacc[2*t+1][0] - m0), p11 = __expf(sacc[2*t+1][1] - m0);
            float p12 = __expf(sacc[2*t+1][2] - m1), p13 = __expf(sacc[2*t+1][3] - m1);
            sum0 += p00 + p01 + p10 + p11;
            sum1 += p02 + p03 + p12 + p13;
            uint32_t pa[4];
            pa[0] = f2bf2(p00, p01); pa[1] = f2bf2(p02, p03);
            pa[2] = f2bf2(p10, p11); pa[3] = f2bf2(p12, p13);
            #pragma unroll
            for (int nt2 = 0; nt2 < 4; nt2++) {
                uint32_t vf4[4];
                LDSM4(vf4, stg + QSZ + voff + nt2*(16*FVP) + t*32);
                MMA16816(oacc[2*nt2],   pa, vf4[0], vf4[2]);
                MMA16816(oacc[2*nt2+1], pa, vf4[1], vf4[3]);
            }
        }
        sum0 += __shfl_xor_sync(0xffffffffu, sum0, 1);
        sum0 += __shfl_xor_sync(0xffffffffu, sum0, 2);
        sum1 += __shfl_xor_sync(0xffffffffu, sum1, 1);
        sum1 += __shfl_xor_sync(0xffffffffu, sum1, 2);
        l0 += sum0; l1 += sum1;

        __syncthreads();
    }

    // epilogue: normalize, split hi/lo, store [M, D]
    float il0 = 1.f / l0, il1 = 1.f / l1;
    int r0 = lane >> 2, cl = (lane & 3) * 2;
    int qrow = q0 + w*16 + r0;
    size_t gr0 = (size_t)(b*S_ + qrow) * D_;
    size_t gr1 = gr0 + (size_t)8 * D_;
    #pragma unroll
    for (int nt2 = 0; nt2 < 8; nt2++) {
        int col = h*64 + nt2*8 + cl;
        float o0 = oacc[nt2][0]*il0, o1 = oacc[nt2][1]*il0;
        float o2 = oacc[nt2][2]*il1, o3 = oacc[nt2][3]*il1;
        __nv_bfloat162 lo2;
        __nv_bfloat162 hi2 = split_hi2(o0, o1, &lo2);
        *(__nv_bfloat162*)(Ohi + gr0 + col) = hi2;
        *(__nv_bfloat162*)(Olo + gr0 + col) = lo2;
        hi2 = split_hi2(o2, o3, &lo2);
        *(__nv_bfloat162*)(Ohi + gr1 + col) = hi2;
        *(__nv_bfloat162*)(Olo + gr1 + col) = lo2;
    }
}

// ---------------------------------------------------------------------------
// V fp32 [M,D] -> Vt bf16 [BH,64,S]
// ---------------------------------------------------------------------------
__global__ void conv_v(const float* __restrict__ v, __nv_bfloat16* __restrict__ vt) {
    int idx = blockIdx.x * blockDim.x + threadIdx.x;
    if (idx >= M_*D_) return;
    int row = idx >> 10, d = idx & 1023;
    int b = row >> 11, s = row & 2047;
    int hh = d >> 6, dd = d & 63;
    vt[(((size_t)b*H_ + hh)*64 + dd)*S_ + s] = __float2bfloat16(v[idx]);
}

// ---------------------------------------------------------------------------
// Weight transpose + split:  W fp32 [K,N] -> th/tl bf16 [N,K]
// ---------------------------------------------------------------------------
__global__ void wsplit_t(const float* __restrict__ W,
                         __nv_bfloat16* __restrict__ th,
                         __nv_bfloat16* __restrict__ tl, int K, int N) {
    __shared__ float sh[32][33];
    int n0 = blockIdx.x * 32, k0 = blockIdx.y * 32;
    int tx = threadIdx.x, ty = threadIdx.y;
    #pragma unroll
    for (int i = 0; i < 4; i++)
        sh[ty + i*8][tx] = W[(size_t)(k0 + ty + i*8) * N + n0 + tx];
    __syncthreads();
    #pragma unroll
    for (int i = 0; i < 4; i++) {
        int n = n0 + ty + i*8;
        float v = sh[tx][ty + i*8];
        __nv_bfloat16 hb = __float2bfloat16(v);
        __nv_bfloat16 lb = __float2bfloat16(v - __bfloat162float(hb));
        th[(size_t)n * K + k0 + tx] = hb;
        tl[(size_t)n * K + k0 + tx] = lb;
    }
}

// ---------------------------------------------------------------------------
// Reductions
// ---------------------------------------------------------------------------
__device__ __forceinline__ float warpSum(float v) {
    #pragma unroll
    for (int o = 16; o; o >>= 1) v += __shfl_xor_sync(0xffffffffu, v, o);
    return v;
}
__device__ __forceinline__ float blockSum(float v, float* sh) {
    int tid = threadIdx.x, lane = tid & 31, w = tid >> 5;
    v = warpSum(v);
    if (lane == 0) sh[w] = v;
    __syncthreads();
    float t = sh[0];
    #pragma unroll
    for (int i = 1; i < 8; i++) t += sh[i];
    __syncthreads();
    return t;
}

// ---------------------------------------------------------------------------
// PE + fused embed/split
// ---------------------------------------------------------------------------
__global__ void pe_kernel(float* __restrict__ pe) {
    int idx = blockIdx.x * blockDim.x + threadIdx.x;
    if (idx >= B_*D_) return;
    int b = idx / D_, d = idx % D_;
    int i = d >> 1;
    double c = -log(10000.0) / (double)D_;
    float divf = (float)exp((double)(2*i) * c);
    float ang  = (float)b / divf;
    double ad  = (double)ang;
    pe[idx] = (d & 1) ? (float)cos(ad) : (float)sin(ad);
}

__global__ void embed_split(const int* __restrict__ src,
                            const float* __restrict__ emb,
                            const float* __restrict__ pe,
                            float* __restrict__ x,
                            __nv_bfloat16* __restrict__ hi,
                            __nv_bfloat16* __restrict__ lo) {
    int idx = blockIdx.x * blockDim.x + threadIdx.x;
    if (idx >= M_*D_) return;
    int d  = idx & (D_-1);
    int bs = idx >> 10;
    int b  = bs >> 11;
    float v = emb[(size_t)src[bs]*D_ + d] + pe[b*D_ + d];
    x[idx] = v;
    __nv_bfloat16 hb = __float2bfloat16(v);
    hi[idx] = hb;
    lo[idx] = __float2bfloat16(v - __bfloat162float(hb));
}

// ---------------------------------------------------------------------------
// out = LayerNorm(x + r) * g + be, with fused hi/lo split
// ---------------------------------------------------------------------------
__global__ __launch_bounds__(256)
void add_ln_split(const float* __restrict__ x, const float* __restrict__ rr,
                  const float* __restrict__ g, const float* __restrict__ be,
                  float* __restrict__ out,
                  __nv_bfloat16* __restrict__ hi, __nv_bfloat16* __restrict__ lo,
                  int do_split) {
    __shared__ float sh[8];
    int m = blockIdx.x, tid = threadIdx.x;
    float4 v = *(const float4*)(x + (size_t)m*D_ + tid*4);
    float4 rv = *(const float4*)(rr + (size_t)m*D_ + tid*4);
    v.x += rv.x; v.y += rv.y; v.z += rv.z; v.w += rv.w;
    float s = v.x + v.y + v.z + v.w;
    s = blockSum(s, sh);
    float mean = s * (1.0f / D_);
    float d0 = v.x - mean, d1 = v.y - mean, d2 = v.z - mean, d3 = v.w - mean;
    float sq = d0*d0 + d1*d1 + d2*d2 + d3*d3;
    sq = blockSum(sq, sh);
    float var = sq * (1.0f / D_);
    float rstd = rsqrtf(var + 1e-5f);
    float4 gg = *(const float4*)(g + tid*4);
    float4 bb = *(const float4*)(be + tid*4);
    float4 o;
    o.x = d0*rstd*gg.x + bb.x;
    o.y = d1*rstd*gg.y + bb.y;
    o.z = d2*rstd*gg.z + bb.z;
    o.w = d3*rstd*gg.w + bb.w;
    *(float4*)(out + (size_t)m*D_ + tid*4) = o;
    if (do_split) {
        size_t p = (size_t)m*D_ + tid*4;
        __nv_bfloat162 lo2;
        __nv_bfloat162 hi2 = split_hi2(o.x, o.y, &lo2);
        *(__nv_bfloat162*)(hi + p)     = hi2;
        *(__nv_bfloat162*)(lo + p)     = lo2;
        hi2 = split_hi2(o.z, o.w, &lo2);
        *(__nv_bfloat162*)(hi + p + 2) = hi2;
        *(__nv_bfloat162*)(lo + p + 2) = lo2;
    }
}

// ---------------------------------------------------------------------------
// Launch
// ---------------------------------------------------------------------------
extern "C" void kernel_launch(void* const* d_in, const int* in_sizes, int n_in,
                              void* d_out, int out_size) {
    const int*   src  = (const int*)  d_in[0];
    const int*   mask = (const int*)  d_in[1];
    const float* emb  = (const float*)d_in[2];
    const float* Wq   = (const float*)d_in[3];
    const float* bq   = (const float*)d_in[4];
    const float* Wk   = (const float*)d_in[5];
    const float* bk   = (const float*)d_in[6];
    const float* Wv   = (const float*)d_in[7];
    const float* bv   = (const float*)d_in[8];
    const float* Wo   = (const float*)d_in[9];
    const float* bo   = (const float*)d_in[10];
    const float* W1   = (const float*)d_in[11];
    const float* b1   = (const float*)d_in[12];
    const float* W2   = (const float*)d_in[13];
    const float* b2   = (const float*)d_in[14];
    const float* g1   = (const float*)d_in[15];
    const float* be1  = (const float*)d_in[16];
    const float* g2   = (const float*)d_in[17];
    const float* be2  = (const float*)d_in[18];
    float* out = (float*)d_out;

    float *x, *r, *v, *pe;
    __nv_bfloat16 *wth, *wtl, *xh, *xl, *oh, *ol, *hh, *hl, *qh, *kh, *vt;
    cudaGetSymbolAddress((void**)&x,  g_x);
    cudaGetSymbolAddress((void**)&r,  g_r);
    cudaGetSymbolAddress((void**)&v,  g_v);
    cudaGetSymbolAddress((void**)&pe, g_pe);
    cudaGetSymbolAddress((void**)&wth, g_wth);
    cudaGetSymbolAddress((void**)&wtl, g_wtl);
    cudaGetSymbolAddress((void**)&xh, g_xh);
    cudaGetSymbolAddress((void**)&xl, g_xl);
    cudaGetSymbolAddress((void**)&oh, g_oh);
    cudaGetSymbolAddress((void**)&ol, g_ol);
    cudaGetSymbolAddress((void**)&hh, g_hh);
    cudaGetSymbolAddress((void**)&hl, g_hl);
    cudaGetSymbolAddress((void**)&qh, g_qh);
    cudaGetSymbolAddress((void**)&kh, g_kh);
    cudaGetSymbolAddress((void**)&vt, g_vt);

    cudaFuncSetAttribute(hmma_gemm,  cudaFuncAttributeMaxDynamicSharedMemorySize, GSMEM);
    cudaFuncSetAttribute(flash_attn, cudaFuncAttributeMaxDynamicSharedMemorySize, FSMEM);

    pe_kernel<<<(B_*D_ + 255)/256, 256>>>(pe);
    embed_split<<<(M_*D_ + 255)/256, 256>>>(src, emb, pe, x, xh, xl);

    dim3 tb(32, 8);
    for (int l = 0; l < L_; l++) {
        size_t wb = (size_t)l * WL_;
        wsplit_t<<<dim3(D_/32,  D_/32),  tb>>>(Wq + (size_t)l*D_*D_,  wth + wb,         wtl + wb,         D_, D_);
        wsplit_t<<<dim3(D_/32,  D_/32),  tb>>>(Wk + (size_t)l*D_*D_,  wth + wb + MB1,   wtl + wb + MB1,   D_, D_);
        wsplit_t<<<dim3(D_/32,  D_/32),  tb>>>(Wv + (size_t)l*D_*D_,  wth + wb + 2*MB1, wtl + wb + 2*MB1, D_, D_);
        wsplit_t<<<dim3(D_/32,  D_/32),  tb>>>(Wo + (size_t)l*D_*D_,  wth + wb + 3*MB1, wtl + wb + 3*MB1, D_, D_);
        wsplit_t<<<dim3(FF_/32, D_/32),  tb>>>(W1 + (size_t)l*D_*FF_, wth + wb + 4*MB1, wtl + wb + 4*MB1, D_, FF_);
        wsplit_t<<<dim3(D_/32,  FF_/32), tb>>>(W2 + (size_t)l*FF_*D_, wth + wb + 8*MB1, wtl + wb + 8*MB1, FF_, D_);
    }

    dim3 gProj(D_/128,  M_/128);
    dim3 gFF1 (FF_/128, M_/128);
    dim3 gFlash(S_/128, BH_);

    for (int l = 0; l < L_; l++) {
        size_t wb = (size_t)l * WL_;
        const float* bq_l = bq + (size_t)l*D_;
        const float* bk_l = bk + (size_t)l*D_;
        const float* bv_l = bv + (size_t)l*D_;
        const float* bo_l = bo + (size_t)l*D_;
        const float* b1_l = b1 + (size_t)l*FF_;
        const float* b2_l = b2 + (size_t)l*D_;
        const float* g1_l = g1 + (size_t)l*D_;
        const float* be1_l= be1+ (size_t)l*D_;
        const float* g2_l = g2 + (size_t)l*D_;
        const float* be2_l= be2+ (size_t)l*D_;

        // Q, K -> bf16 head layout directly; V -> fp32 then transpose
        hmma_gemm<<<gProj, 256, GSMEM>>>(xh, xl, wth + wb,         wtl + wb,
                                         bq_l, nullptr, qh, nullptr, M_, D_, D_, OUT_HEAD);
        hmma_gemm<<<gProj, 256, GSMEM>>>(xh, xl, wth + wb + MB1,   wtl + wb + MB1,
                                         bk_l, nullptr, kh, nullptr, M_, D_, D_, OUT_HEAD);
        hmma_gemm<<<gProj, 256, GSMEM>>>(xh, xl, wth + wb + 2*MB1, wtl + wb + 2*MB1,
                                         bv_l, v, nullptr, nullptr, M_, D_, D_, OUT_F32);
        conv_v<<<(M_*D_ + 255)/256, 256>>>(v, vt);

        flash_attn<<<gFlash, 256, FSMEM>>>(qh, kh, vt, mask, oh, ol);

        hmma_gemm<<<gProj, 256, GSMEM>>>(oh, ol, wth + wb + 3*MB1, wtl + wb + 3*MB1,
                                         bo_l, r, nullptr, nullptr, M_, D_, D_, OUT_F32);
        add_ln_split<<<M_, 256>>>(x, r, g1_l, be1_l, x, xh, xl, 1);

        hmma_gemm<<<gFF1, 256, GSMEM>>>(xh, xl, wth + wb + 4*MB1, wtl + wb + 4*MB1,
                                        b1_l, nullptr, hh, hl, M_, FF_, D_, OUT_SPLIT);
        hmma_gemm<<<gProj, 256, GSMEM>>>(hh, hl, wth + wb + 8*MB1, wtl + wb + 8*MB1,
                                         b2_l, r, nullptr, nullptr, M_, D_, FF_, OUT_F32);

        float* dst = (l == L_-1) ? out : x;
        add_ln_split<<<M_, 256>>>(x, r, g2_l, be2_l, dst, xh, xl, (l < L_-1) ? 1 : 0);
    }
}

// round 11
// speedup vs baseline: 3.0401x; 1.0416x over previous
#include <cuda_runtime.h>
#include <cuda_bf16.h>
#include <cuda_fp16.h>
#include <math.h>
#include <stdint.h>

// ---------------------------------------------------------------------------
// Problem constants
// ---------------------------------------------------------------------------
#define B_  2
#define S_  2048
#define D_  1024
#define H_  16
#define DK_ 64
#define FF_ 4096
#define L_  6
#define M_  (B_*S_)          // 4096 rows
#define BH_ (B_*H_)          // 32

// ---------------------------------------------------------------------------
// Scratch (device globals — no allocations allowed)
// ---------------------------------------------------------------------------
__device__ float g_x[M_*D_];                 // running activation (fp32)
__device__ float g_r[M_*D_];                 // residual branch (fp32)
__device__ float g_pe[B_*D_];

__device__ __nv_bfloat16 g_xh[M_*D_];        // split of x
__device__ __nv_bfloat16 g_xl[M_*D_];
__device__ __nv_bfloat16 g_oh[M_*D_];        // split of attention output
__device__ __nv_bfloat16 g_ol[M_*D_];
__device__ __nv_bfloat16 g_hh[M_*FF_];       // split of FF hidden
__device__ __nv_bfloat16 g_hl[M_*FF_];

__device__ __nv_bfloat16 g_qh[M_*D_];        // Q  [BH, S, 64] bf16
__device__ __nv_bfloat16 g_kh[M_*D_];        // K  [BH, S, 64] bf16
__device__ __half        g_vh[M_*D_];        // V  [BH, S, 64] f16
__device__ __half        g_vt[M_*D_];        // V^T [BH, 64, S] f16

// bf16 split weights, transposed to [N,K]
#define MB1 (1u<<20)
#define WL_ (12u*MB1)
__device__ __nv_bfloat16 g_wth[6*12*1024*1024];
__device__ __nv_bfloat16 g_wtl[6*12*1024*1024];

// ---------------------------------------------------------------------------
// PTX helpers (portable: cp.async, ldmatrix, mma.sync, ex2.approx)
// ---------------------------------------------------------------------------
__device__ __forceinline__ uint32_t smem_u32(const void* p) {
    return (uint32_t)__cvta_generic_to_shared(p);
}
#define CP16(dst, src) \
    asm volatile("cp.async.cg.shared.global [%0], [%1], 16;" :: "r"(dst), "l"(src) : "memory")
#define CP_COMMIT() asm volatile("cp.async.commit_group;" ::: "memory")
#define CP_WAIT1()  asm volatile("cp.async.wait_group 1;" ::: "memory")
#define CP_WAIT0()  asm volatile("cp.async.wait_group 0;" ::: "memory")

#define LDSM4(r, addr) \
    asm volatile("ldmatrix.sync.aligned.m8n8.x4.shared.b16 {%0,%1,%2,%3}, [%4];" \
        : "=r"((r)[0]), "=r"((r)[1]), "=r"((r)[2]), "=r"((r)[3]) : "r"(addr))

#define MMA16816(c, a, b0, b1) \
    asm volatile("mma.sync.aligned.m16n8k16.row.col.f32.bf16.bf16.f32 " \
        "{%0,%1,%2,%3}, {%4,%5,%6,%7}, {%8,%9}, {%0,%1,%2,%3};" \
        : "+f"((c)[0]), "+f"((c)[1]), "+f"((c)[2]), "+f"((c)[3]) \
        : "r"((a)[0]), "r"((a)[1]), "r"((a)[2]), "r"((a)[3]), "r"(b0), "r"(b1))

#define MMA16816H(c, a, b0, b1) \
    asm volatile("mma.sync.aligned.m16n8k16.row.col.f32.f16.f16.f32 " \
        "{%0,%1,%2,%3}, {%4,%5,%6,%7}, {%8,%9}, {%0,%1,%2,%3};" \
        : "+f"((c)[0]), "+f"((c)[1]), "+f"((c)[2]), "+f"((c)[3]) \
        : "r"((a)[0]), "r"((a)[1]), "r"((a)[2]), "r"((a)[3]), "r"(b0), "r"(b1))

// pack(lo,hi) -> f16x2 -> 2^x per half
__device__ __forceinline__ uint32_t exp2_f16x2(float lo, float hi) {
    uint32_t t, d;
    asm("cvt.rn.f16x2.f32 %0, %1, %2;" : "=r"(t) : "f"(hi), "f"(lo));
    asm("ex2.approx.f16x2 %0, %1;" : "=r"(d) : "r"(t));
    return d;
}
__device__ __forceinline__ float exp2f_fast(float x) {
    float y; asm("ex2.approx.f32 %0, %1;" : "=f"(y) : "f"(x)); return y;
}
__device__ __forceinline__ __nv_bfloat162 split_hi2(float a, float b,
                                                    __nv_bfloat162* lo2) {
    __nv_bfloat16 ha = __float2bfloat16(a), hb = __float2bfloat16(b);
    *lo2 = __nv_bfloat162(__float2bfloat16(a - __bfloat162float(ha)),
                          __float2bfloat16(b - __bfloat162float(hb)));
    return __nv_bfloat162(ha, hb);
}

// ---------------------------------------------------------------------------
// bf16x3 HMMA GEMM with fused epilogues.
// A*: bf16 [M,K] rm.  B*: bf16 [N,K] rm (W^T).  128x128 tile, 8 warps (64x32),
// K-chunk 64, pitch 144B, 2-stage cp.async, 144KB smem, 1 CTA/SM.
// modes: OUT_F32 fp32 C;  OUT_SPLIT ReLU + hi/lo split;
//        OUT_QKV  per-block: n<1024 -> Q bf16 head, <2048 -> K bf16 head,
//                 else V f16 head layout.
// ---------------------------------------------------------------------------
#define OUT_F32   0
#define OUT_SPLIT 1
#define OUT_QKV   2

#define KC      64
#define PITCHB  144
#define TILEB   (128*PITCHB)          // 18432
#define STAGEB  (4*TILEB)             // 73728
#define GSMEM   (2*STAGEB)            // 147456

extern __shared__ char dynsmem[];

__global__ __launch_bounds__(256, 1)
void hmma_gemm(const __nv_bfloat16* __restrict__ Ah, const __nv_bfloat16* __restrict__ Al,
               const __nv_bfloat16* __restrict__ Bh, const __nv_bfloat16* __restrict__ Bl,
               const float* __restrict__ bias0, const float* __restrict__ bias1,
               const float* __restrict__ bias2,
               float* __restrict__ C,
               __nv_bfloat16* __restrict__ Chi, __nv_bfloat16* __restrict__ Clo,
               __half* __restrict__ Vh,
               int M, int N, int K, int mode) {
    uint32_t sb = smem_u32(dynsmem);
    int tid = threadIdx.x, lane = tid & 31, wid = tid >> 5;
    int wm = wid >> 2, wn = wid & 3;
    int m0 = blockIdx.y * 128, n0 = blockIdx.x * 128;

    float acc[4][4][4];
    #pragma unroll
    for (int i = 0; i < 4; i++)
        #pragma unroll
        for (int j = 0; j < 4; j++)
            #pragma unroll
            for (int q = 0; q < 4; q++) acc[i][j][q] = 0.f;

    int seg = tid & 7, rb = tid >> 3;
    const __nv_bfloat16* gsrc[4];
    gsrc[0] = Ah + (size_t)m0 * K;
    gsrc[1] = Al + (size_t)m0 * K;
    gsrc[2] = Bh + (size_t)n0 * K;
    gsrc[3] = Bl + (size_t)n0 * K;

    int lrow = lane & 15, lk16 = (lane >> 4) * 16;
    uint32_t aoff = (uint32_t)((wm*64 + lrow) * PITCHB) + lk16;
    uint32_t boff = (uint32_t)((wn*32 + lrow) * PITCHB) + lk16;

    int nc = K / KC;

    #pragma unroll
    for (int t = 0; t < 4; t++)
        #pragma unroll
        for (int i = 0; i < 4; i++) {
            int row = rb + i * 32;
            CP16(sb + t*TILEB + (uint32_t)(row * PITCHB + seg * 16),
                 (const char*)(gsrc[t] + (size_t)row * K) + seg * 16);
        }
    CP_COMMIT();

    for (int c = 0; c < nc; c++) {
        if (c + 1 < nc) {
            int ns = (c + 1) & 1;
            int k0 = (c + 1) * KC;
            #pragma unroll
            for (int t = 0; t < 4; t++)
                #pragma unroll
                for (int i = 0; i < 4; i++) {
                    int row = rb + i * 32;
                    CP16(sb + ns*STAGEB + t*TILEB + (uint32_t)(row * PITCHB + seg * 16),
                         (const char*)(gsrc[t] + (size_t)row * K + k0) + seg * 16);
                }
            CP_COMMIT();
            CP_WAIT1();
        } else {
            CP_WAIT0();
        }
        __syncthreads();

        uint32_t base = sb + (c & 1) * STAGEB;
        #pragma unroll
        for (int kk = 0; kk < KC; kk += 16) {
            uint32_t ah4[4][4], al4[4][4], bb[2][4];
            #pragma unroll
            for (int mt = 0; mt < 4; mt++)
                LDSM4(ah4[mt], base + aoff + mt*(16*PITCHB) + kk*2);
            #pragma unroll
            for (int mt = 0; mt < 4; mt++)
                LDSM4(al4[mt], base + TILEB + aoff + mt*(16*PITCHB) + kk*2);
            #pragma unroll
            for (int nt2 = 0; nt2 < 2; nt2++)
                LDSM4(bb[nt2], base + 2*TILEB + boff + nt2*(16*PITCHB) + kk*2);
            #pragma unroll
            for (int mt = 0; mt < 4; mt++)               // Ah*Bh
                #pragma unroll
                for (int nt = 0; nt < 4; nt++)
                    MMA16816(acc[mt][nt], ah4[mt], bb[nt>>1][nt&1], bb[nt>>1][2+(nt&1)]);
            #pragma unroll
            for (int mt = 0; mt < 4; mt++)               // Al*Bh
                #pragma unroll
                for (int nt = 0; nt < 4; nt++)
                    MMA16816(acc[mt][nt], al4[mt], bb[nt>>1][nt&1], bb[nt>>1][2+(nt&1)]);
            #pragma unroll
            for (int nt2 = 0; nt2 < 2; nt2++)            // reuse bb for Bl
                LDSM4(bb[nt2], base + 3*TILEB + boff + nt2*(16*PITCHB) + kk*2);
            #pragma unroll
            for (int mt = 0; mt < 4; mt++)               // Ah*Bl
                #pragma unroll
                for (int nt = 0; nt < 4; nt++)
                    MMA16816(acc[mt][nt], ah4[mt], bb[nt>>1][nt&1], bb[nt>>1][2+(nt&1)]);
        }
        __syncthreads();
    }

    int r0 = lane >> 2, cl = (lane & 3) * 2;
    int msel = n0 >> 10;                                 // for OUT_QKV
    const float* bias = (mode != OUT_QKV) ? bias0
                      : (msel == 0 ? bias0 : (msel == 1 ? bias1 : bias2));
    #pragma unroll
    for (int nt = 0; nt < 4; nt++) {
        int col  = n0 + wn*32 + nt*8 + cl;
        int ncol = (mode == OUT_QKV) ? (col & 1023) : col;
        float bx = bias[ncol], by = bias[ncol+1];
        #pragma unroll
        for (int mt = 0; mt < 4; mt++) {
            int row = m0 + wm*64 + mt*16 + r0;
            float v0 = acc[mt][nt][0] + bx, v1 = acc[mt][nt][1] + by;
            float v2 = acc[mt][nt][2] + bx, v3 = acc[mt][nt][3] + by;
            if (mode == OUT_F32) {
                *(float2*)(C + (size_t)row * N + col)       = make_float2(v0, v1);
                *(float2*)(C + (size_t)(row + 8) * N + col) = make_float2(v2, v3);
            } else if (mode == OUT_SPLIT) {
                v0 = fmaxf(v0, 0.f); v1 = fmaxf(v1, 0.f);
                v2 = fmaxf(v2, 0.f); v3 = fmaxf(v3, 0.f);
                __nv_bfloat162 lo2;
                __nv_bfloat162 hi2 = split_hi2(v0, v1, &lo2);
                *(__nv_bfloat162*)(Chi + (size_t)row * N + col) = hi2;
                *(__nv_bfloat162*)(Clo + (size_t)row * N + col) = lo2;
                hi2 = split_hi2(v2, v3, &lo2);
                *(__nv_bfloat162*)(Chi + (size_t)(row+8) * N + col) = hi2;
                *(__nv_bfloat162*)(Clo + (size_t)(row+8) * N + col) = lo2;
            } else {                                     // OUT_QKV
                int b = row >> 11, sidx = row & 2047;
                int hh = ncol >> 6, dd = ncol & 63;
                size_t base0 = (((size_t)b*H_ + hh)*S_ + sidx)*64 + dd;
                if (msel == 0) {
                    *(__nv_bfloat162*)(Chi + base0) =
                        __nv_bfloat162(__float2bfloat16(v0), __float2bfloat16(v1));
                    *(__nv_bfloat162*)(Chi + base0 + 8*64) =
                        __nv_bfloat162(__float2bfloat16(v2), __float2bfloat16(v3));
                } else if (msel == 1) {
                    *(__nv_bfloat162*)(Clo + base0) =
                        __nv_bfloat162(__float2bfloat16(v0), __float2bfloat16(v1));
                    *(__nv_bfloat162*)(Clo + base0 + 8*64) =
                        __nv_bfloat162(__float2bfloat16(v2), __float2bfloat16(v3));
                } else {
                    *(__half2*)(Vh + base0) = __floats2half2_rn(v0, v1);
                    *(__half2*)(Vh + base0 + 8*64) = __floats2half2_rn(v2, v3);
                }
            }
        }
    }
}

// ---------------------------------------------------------------------------
// V transpose: [BH,S,64] f16 -> [BH,64,S] f16, coalesced both sides.
// ---------------------------------------------------------------------------
__global__ __launch_bounds__(256)
void vtrans(const __half* __restrict__ vh, __half* __restrict__ vt) {
    __shared__ __half sh[64][65];
    int bh = blockIdx.y, s0 = blockIdx.x * 64;
    int tx = threadIdx.x & 31, ty = threadIdx.x >> 5;   // 32 x 8
    const __half* src = vh + ((size_t)bh*S_ + s0) * 64;
    #pragma unroll
    for (int i = 0; i < 8; i++) {
        int row = ty + i*8;
        __half2 v2 = *(const __half2*)(src + (size_t)row*64 + tx*2);
        sh[row][tx*2]   = __low2half(v2);
        sh[row][tx*2+1] = __high2half(v2);
    }
    __syncthreads();
    __half* dst = vt + (size_t)bh*64*S_ + s0;
    #pragma unroll
    for (int i = 0; i < 8; i++) {
        int dcol = ty + i*8;
        __half2 o = __halves2half2(sh[tx*2][dcol], sh[tx*2+1][dcol]);
        *(__half2*)(dst + (size_t)dcol*S_ + tx*2) = o;
    }
}

// ---------------------------------------------------------------------------
// Fused flash attention.  Q,K: [BH,S,64] bf16.  Vt: [BH,64,S] f16.
// log2-domain online softmax, f16x2 ex2, row sums via ones-column f16 MMA.
// CTA: 128 q rows, 8 warps x 16 rows; k-tiles of 128, 2-stage cp.async.
// ---------------------------------------------------------------------------
#define FQP 144
#define QSZ (128*FQP)                 // 18432 (also K tile size)
#define FVP 272
#define VSZ (64*FVP)                  // 17408
#define MSZ 512
#define STG (QSZ + VSZ + MSZ)         // 36352
#define FSMEM (QSZ + 2*STG)           // 91136

#define ONES_H2 0x3C003C00u

__global__ __launch_bounds__(256, 1)
void flash_attn(const __nv_bfloat16* __restrict__ qh,
                const __nv_bfloat16* __restrict__ kh,
                const __half* __restrict__ vt,
                const int* __restrict__ mask,
                __nv_bfloat16* __restrict__ Ohi, __nv_bfloat16* __restrict__ Olo) {
    uint32_t sb = smem_u32(dynsmem);
    int tid = threadIdx.x, lane = tid & 31, w = tid >> 5;
    int bh = blockIdx.y, q0 = blockIdx.x * 128;
    int b = bh >> 4, h = bh & 15;

    const __nv_bfloat16* qg = qh + ((size_t)bh*S_ + q0) * 64;
    const __nv_bfloat16* kg = kh + (size_t)bh*S_ * 64;
    const __half*        vg = vt + (size_t)bh*64 * S_;
    const int* mg = mask + b*S_;

    int seg = tid & 7,  rb  = tid >> 3;
    int vseg = tid & 15, vrb = tid >> 4;

    #pragma unroll
    for (int i = 0; i < 4; i++) {
        int row = rb + i * 32;
        CP16(sb + (uint32_t)(row*FQP + seg*16),
             (const char*)(qg + (size_t)row*64) + seg*16);
        CP16(sb + QSZ + (uint32_t)(row*FQP + seg*16),
             (const char*)(kg + (size_t)row*64) + seg*16);
    }
    #pragma unroll
    for (int i = 0; i < 4; i++) {
        int row = vrb + i * 16;
        CP16(sb + QSZ + QSZ + (uint32_t)(row*FVP + vseg*16),
             (const char*)(vg + (size_t)row*S_) + vseg*16);
    }
    if (tid < 32) CP16(sb + QSZ + QSZ + VSZ + tid*16, (const char*)mg + tid*16);
    CP_COMMIT();

    uint32_t aoffQ = (uint32_t)((w*16 + (lane&15))*FQP) + (lane>>4)*16;
    uint32_t koff  = (uint32_t)((lane&15)*FQP) + (lane>>4)*16;
    uint32_t voff  = (uint32_t)((lane&15)*FVP) + (lane>>4)*16;

    float m0 = -INFINITY, m1 = -INFINITY;
    float oacc[8][4], lacc[4];
    #pragma unroll
    for (int i = 0; i < 8; i++)
        #pragma unroll
        for (int q = 0; q < 4; q++) oacc[i][q] = 0.f;
    #pragma unroll
    for (int q = 0; q < 4; q++) lacc[q] = 0.f;

    const float SCALE = 0.0450842201736734f;   // log2(e)/32  (log2 domain)
    const float MASKNEG = -4.5e7f;

    for (int j = 0; j < S_/128; j++) {
        if (j + 1 < S_/128) {
            uint32_t stg2 = sb + QSZ + ((j+1)&1)*STG;
            const char* ks = (const char*)(kg + (size_t)(j+1)*128*64);
            #pragma unroll
            for (int i = 0; i < 4; i++) {
                int row = rb + i * 32;
                CP16(stg2 + (uint32_t)(row*FQP + seg*16), ks + (size_t)row*128 + seg*16);
            }
            #pragma unroll
            for (int i = 0; i < 4; i++) {
                int row = vrb + i * 16;
                CP16(stg2 + QSZ + (uint32_t)(row*FVP + vseg*16),
                     (const char*)(vg + (size_t)row*S_ + (j+1)*128) + vseg*16);
            }
            if (tid < 32) CP16(stg2 + QSZ + VSZ + tid*16,
                               (const char*)(mg + (j+1)*128) + tid*16);
            CP_COMMIT();
            CP_WAIT1();
        } else {
            CP_WAIT0();
        }
        __syncthreads();

        uint32_t stg = sb + QSZ + (j&1)*STG;
        const int* msk = (const int*)(dynsmem + QSZ + (j&1)*STG + QSZ + VSZ);

        float sacc[16][4];
        #pragma unroll
        for (int i = 0; i < 16; i++)
            #pragma unroll
            for (int q = 0; q < 4; q++) sacc[i][q] = 0.f;

        #pragma unroll
        for (int kk = 0; kk < 64; kk += 16) {
            uint32_t af[4];
            LDSM4(af, sb + aoffQ + kk*2);
            #pragma unroll
            for (int nt2 = 0; nt2 < 8; nt2++) {
                uint32_t bf4[4];
                LDSM4(bf4, stg + koff + nt2*(16*FQP) + kk*2);
                MMA16816(sacc[2*nt2],   af, bf4[0], bf4[2]);
                MMA16816(sacc[2*nt2+1], af, bf4[1], bf4[3]);
            }
        }

        // scale into log2 domain + mask + row-max
        float rm0 = -INFINITY, rm1 = -INFINITY;
        #pragma unroll
        for (int nt = 0; nt < 16; nt++) {
            int col = nt*8 + (lane&3)*2;
            int2 mk = *(const int2*)(msk + col);
            float s0 = mk.x ? sacc[nt][0]*SCALE : MASKNEG;
            float s1 = mk.y ? sacc[nt][1]*SCALE : MASKNEG;
            float s2 = mk.x ? sacc[nt][2]*SCALE : MASKNEG;
            float s3 = mk.y ? sacc[nt][3]*SCALE : MASKNEG;
            sacc[nt][0] = s0; sacc[nt][1] = s1; sacc[nt][2] = s2; sacc[nt][3] = s3;
            rm0 = fmaxf(rm0, fmaxf(s0, s1));
            rm1 = fmaxf(rm1, fmaxf(s2, s3));
        }
        rm0 = fmaxf(rm0, __shfl_xor_sync(0xffffffffu, rm0, 1));
        rm0 = fmaxf(rm0, __shfl_xor_sync(0xffffffffu, rm0, 2));
        rm1 = fmaxf(rm1, __shfl_xor_sync(0xffffffffu, rm1, 1));
        rm1 = fmaxf(rm1, __shfl_xor_sync(0xffffffffu, rm1, 2));

        float mn0 = fmaxf(m0, rm0), mn1 = fmaxf(m1, rm1);
        float f0 = exp2f_fast(m0 - mn0), f1 = exp2f_fast(m1 - mn1);
        m0 = mn0; m1 = mn1;
        lacc[0] *= f0; lacc[1] *= f0; lacc[2] *= f1; lacc[3] *= f1;
        #pragma unroll
        for (int i = 0; i < 8; i++) {
            oacc[i][0] *= f0; oacc[i][1] *= f0;
            oacc[i][2] *= f1; oacc[i][3] *= f1;
        }

        // P = 2^(t - m) via f16x2 ex2;  l += P·1;  O += P V
        #pragma unroll
        for (int t = 0; t < 8; t++) {
            uint32_t pa[4];
            pa[0] = exp2_f16x2(sacc[2*t][0] - m0,   sacc[2*t][1] - m0);
            pa[1] = exp2_f16x2(sacc[2*t][2] - m1,   sacc[2*t][3] - m1);
            pa[2] = exp2_f16x2(sacc[2*t+1][0] - m0, sacc[2*t+1][1] - m0);
            pa[3] = exp2_f16x2(sacc[2*t+1][2] - m1, sacc[2*t+1][3] - m1);
            MMA16816H(lacc, pa, ONES_H2, ONES_H2);
            #pragma unroll
            for (int nt2 = 0; nt2 < 4; nt2++) {
                uint32_t vf4[4];
                LDSM4(vf4, stg + QSZ + voff + nt2*(16*FVP) + t*32);
                MMA16816H(oacc[2*nt2],   pa, vf4[0], vf4[2]);
                MMA16816H(oacc[2*nt2+1], pa, vf4[1], vf4[3]);
            }
        }
        __syncthreads();
    }

    // epilogue: normalize, split hi/lo, store [M, D]
    float il0 = 1.f / lacc[0], il1 = 1.f / lacc[2];
    int r0 = lane >> 2, cl = (lane & 3) * 2;
    int qrow = q0 + w*16 + r0;
    size_t gr0 = (size_t)(b*S_ + qrow) * D_;
    size_t gr1 = gr0 + (size_t)8 * D_;
    #pragma unroll
    for (int nt2 = 0; nt2 < 8; nt2++) {
        int col = h*64 + nt2*8 + cl;
        float o0 = oacc[nt2][0]*il0, o1 = oacc[nt2][1]*il0;
        float o2 = oacc[nt2][2]*il1, o3 = oacc[nt2][3]*il1;
        __nv_bfloat162 lo2;
        __nv_bfloat162 hi2 = split_hi2(o0, o1, &lo2);
        *(__nv_bfloat162*)(Ohi + gr0 + col) = hi2;
        *(__nv_bfloat162*)(Olo + gr0 + col) = lo2;
        hi2 = split_hi2(o2, o3, &lo2);
        *(__nv_bfloat162*)(Ohi + gr1 + col) = hi2;
        *(__nv_bfloat162*)(Olo + gr1 + col) = lo2;
    }
}

// ---------------------------------------------------------------------------
// Weight transpose + split:  W fp32 [K,N] -> th/tl bf16 [N,K]
// ---------------------------------------------------------------------------
__global__ void wsplit_t(const float* __restrict__ W,
                         __nv_bfloat16* __restrict__ th,
                         __nv_bfloat16* __restrict__ tl, int K, int N) {
    __shared__ float sh[32][33];
    int n0 = blockIdx.x * 32, k0 = blockIdx.y * 32;
    int tx = threadIdx.x, ty = threadIdx.y;
    #pragma unroll
    for (int i = 0; i < 4; i++)
        sh[ty + i*8][tx] = W[(size_t)(k0 + ty + i*8) * N + n0 + tx];
    __syncthreads();
    #pragma unroll
    for (int i = 0; i < 4; i++) {
        int n = n0 + ty + i*8;
        float v = sh[tx][ty + i*8];
        __nv_bfloat16 hb = __float2bfloat16(v);
        __nv_bfloat16 lb = __float2bfloat16(v - __bfloat162float(hb));
        th[(size_t)n * K + k0 + tx] = hb;
        tl[(size_t)n * K + k0 + tx] = lb;
    }
}

// ---------------------------------------------------------------------------
// Reductions
// ---------------------------------------------------------------------------
__device__ __forceinline__ float warpSum(float v) {
    #pragma unroll
    for (int o = 16; o; o >>= 1) v += __shfl_xor_sync(0xffffffffu, v, o);
    return v;
}
__device__ __forceinline__ float blockSum(float v, float* sh) {
    int tid = threadIdx.x, lane = tid & 31, w = tid >> 5;
    v = warpSum(v);
    if (lane == 0) sh[w] = v;
    __syncthreads();
    float t = sh[0];
    #pragma unroll
    for (int i = 1; i < 8; i++) t += sh[i];
    __syncthreads();
    return t;
}

// ---------------------------------------------------------------------------
// PE + fused embed/split
// ---------------------------------------------------------------------------
__global__ void pe_kernel(float* __restrict__ pe) {
    int idx = blockIdx.x * blockDim.x + threadIdx.x;
    if (idx >= B_*D_) return;
    int b = idx / D_, d = idx % D_;
    int i = d >> 1;
    double c = -log(10000.0) / (double)D_;
    float divf = (float)exp((double)(2*i) * c);
    float ang  = (float)b / divf;
    double ad  = (double)ang;
    pe[idx] = (d & 1) ? (float)cos(ad) : (float)sin(ad);
}

__global__ void embed_split(const int* __restrict__ src,
                            const float* __restrict__ emb,
                            const float* __restrict__ pe,
                            float* __restrict__ x,
                            __nv_bfloat16* __restrict__ hi,
                            __nv_bfloat16* __restrict__ lo) {
    int idx = blockIdx.x * blockDim.x + threadIdx.x;
    if (idx >= M_*D_) return;
    int d  = idx & (D_-1);
    int bs = idx >> 10;
    int b  = bs >> 11;
    float v = emb[(size_t)src[bs]*D_ + d] + pe[b*D_ + d];
    x[idx] = v;
    __nv_bfloat16 hb = __float2bfloat16(v);
    hi[idx] = hb;
    lo[idx] = __float2bfloat16(v - __bfloat162float(hb));
}

// ---------------------------------------------------------------------------
// out = LayerNorm(x + r) * g + be, with fused hi/lo split
// ---------------------------------------------------------------------------
__global__ __launch_bounds__(256)
void add_ln_split(const float* __restrict__ x, const float* __restrict__ rr,
                  const float* __restrict__ g, const float* __restrict__ be,
                  float* __restrict__ out,
                  __nv_bfloat16* __restrict__ hi, __nv_bfloat16* __restrict__ lo,
                  int do_split) {
    __shared__ float sh[8];
    int m = blockIdx.x, tid = threadIdx.x;
    float4 v = *(const float4*)(x + (size_t)m*D_ + tid*4);
    float4 rv = *(const float4*)(rr + (size_t)m*D_ + tid*4);
    v.x += rv.x; v.y += rv.y; v.z += rv.z; v.w += rv.w;
    float s = v.x + v.y + v.z + v.w;
    s = blockSum(s, sh);
    float mean = s * (1.0f / D_);
    float d0 = v.x - mean, d1 = v.y - mean, d2 = v.z - mean, d3 = v.w - mean;
    float sq = d0*d0 + d1*d1 + d2*d2 + d3*d3;
    sq = blockSum(sq, sh);
    float var = sq * (1.0f / D_);
    float rstd = rsqrtf(var + 1e-5f);
    float4 gg = *(const float4*)(g + tid*4);
    float4 bb = *(const float4*)(be + tid*4);
    float4 o;
    o.x = d0*rstd*gg.x + bb.x;
    o.y = d1*rstd*gg.y + bb.y;
    o.z = d2*rstd*gg.z + bb.z;
    o.w = d3*rstd*gg.w + bb.w;
    *(float4*)(out + (size_t)m*D_ + tid*4) = o;
    if (do_split) {
        size_t p = (size_t)m*D_ + tid*4;
        __nv_bfloat162 lo2;
        __nv_bfloat162 hi2 = split_hi2(o.x, o.y, &lo2);
        *(__nv_bfloat162*)(hi + p)     = hi2;
        *(__nv_bfloat162*)(lo + p)     = lo2;
        hi2 = split_hi2(o.z, o.w, &lo2);
        *(__nv_bfloat162*)(hi + p + 2) = hi2;
        *(__nv_bfloat162*)(lo + p + 2) = lo2;
    }
}

// ---------------------------------------------------------------------------
// Launch
// ---------------------------------------------------------------------------
extern "C" void kernel_launch(void* const* d_in, const int* in_sizes, int n_in,
                              void* d_out, int out_size) {
    const int*   src  = (const int*)  d_in[0];
    const int*   mask = (const int*)  d_in[1];
    const float* emb  = (const float*)d_in[2];
    const float* Wq   = (const float*)d_in[3];
    const float* bq   = (const float*)d_in[4];
    const float* Wk   = (const float*)d_in[5];
    const float* bk   = (const float*)d_in[6];
    const float* Wv   = (const float*)d_in[7];
    const float* bv   = (const float*)d_in[8];
    const float* Wo   = (const float*)d_in[9];
    const float* bo   = (const float*)d_in[10];
    const float* W1   = (const float*)d_in[11];
    const float* b1   = (const float*)d_in[12];
    const float* W2   = (const float*)d_in[13];
    const float* b2   = (const float*)d_in[14];
    const float* g1   = (const float*)d_in[15];
    const float* be1  = (const float*)d_in[16];
    const float* g2   = (const float*)d_in[17];
    const float* be2  = (const float*)d_in[18];
    float* out = (float*)d_out;

    float *x, *r, *pe;
    __nv_bfloat16 *wth, *wtl, *xh, *xl, *oh, *ol, *hh, *hl, *qh, *kh;
    __half *vh, *vt;
    cudaGetSymbolAddress((void**)&x,  g_x);
    cudaGetSymbolAddress((void**)&r,  g_r);
    cudaGetSymbolAddress((void**)&pe, g_pe);
    cudaGetSymbolAddress((void**)&wth, g_wth);
    cudaGetSymbolAddress((void**)&wtl, g_wtl);
    cudaGetSymbolAddress((void**)&xh, g_xh);
    cudaGetSymbolAddress((void**)&xl, g_xl);
    cudaGetSymbolAddress((void**)&oh, g_oh);
    cudaGetSymbolAddress((void**)&ol, g_ol);
    cudaGetSymbolAddress((void**)&hh, g_hh);
    cudaGetSymbolAddress((void**)&hl, g_hl);
    cudaGetSymbolAddress((void**)&qh, g_qh);
    cudaGetSymbolAddress((void**)&kh, g_kh);
    cudaGetSymbolAddress((void**)&vh, g_vh);
    cudaGetSymbolAddress((void**)&vt, g_vt);

    cudaFuncSetAttribute(hmma_gemm,  cudaFuncAttributeMaxDynamicSharedMemorySize, GSMEM);
    cudaFuncSetAttribute(flash_attn, cudaFuncAttributeMaxDynamicSharedMemorySize, FSMEM);

    pe_kernel<<<(B_*D_ + 255)/256, 256>>>(pe);                     // launch 1
    embed_split<<<(M_*D_ + 255)/256, 256>>>(src, emb, pe, x, xh, xl); // 2

    dim3 tb(32, 8);
    dim3 gQKV (3*D_/128, M_/128);      // 24 x 32
    dim3 gProj(D_/128,   M_/128);
    dim3 gFF1 (FF_/128,  M_/128);
    dim3 gFlash(S_/128, BH_);
    dim3 gVT  (S_/64, BH_);

    for (int l = 0; l < L_; l++) {
        size_t wb = (size_t)l * WL_;
        const float* bq_l = bq + (size_t)l*D_;
        const float* bk_l = bk + (size_t)l*D_;
        const float* bv_l = bv + (size_t)l*D_;
        const float* bo_l = bo + (size_t)l*D_;
        const float* b1_l = b1 + (size_t)l*FF_;
        const float* b2_l = b2 + (size_t)l*D_;
        const float* g1_l = g1 + (size_t)l*D_;
        const float* be1_l= be1+ (size_t)l*D_;
        const float* g2_l = g2 + (size_t)l*D_;
        const float* be2_l= be2+ (size_t)l*D_;

        // weight prep for this layer (QKV first so launch #6 is the big GEMM)
        wsplit_t<<<dim3(D_/32, D_/32), tb>>>(Wq + (size_t)l*D_*D_, wth + wb,         wtl + wb,         D_, D_);
        wsplit_t<<<dim3(D_/32, D_/32), tb>>>(Wk + (size_t)l*D_*D_, wth + wb + MB1,   wtl + wb + MB1,   D_, D_);
        wsplit_t<<<dim3(D_/32, D_/32), tb>>>(Wv + (size_t)l*D_*D_, wth + wb + 2*MB1, wtl + wb + 2*MB1, D_, D_);

        // fused QKV GEMM: N = 3072, epilogue routes Q/K (bf16 head) and V (f16 head)
        hmma_gemm<<<gQKV, 256, GSMEM>>>(xh, xl, wth + wb, wtl + wb,
                                        bq_l, bk_l, bv_l,
                                        nullptr, qh, kh, vh, M_, 3*D_, D_, OUT_QKV);
        vtrans<<<gVT, 256>>>(vh, vt);
        flash_attn<<<gFlash, 256, FSMEM>>>(qh, kh, vt, mask, oh, ol);

        wsplit_t<<<dim3(D_/32, D_/32), tb>>>(Wo + (size_t)l*D_*D_, wth + wb + 3*MB1, wtl + wb + 3*MB1, D_, D_);
        hmma_gemm<<<gProj, 256, GSMEM>>>(oh, ol, wth + wb + 3*MB1, wtl + wb + 3*MB1,
                                         bo_l, nullptr, nullptr,
                                         r, nullptr, nullptr, nullptr, M_, D_, D_, OUT_F32);
        add_ln_split<<<M_, 256>>>(x, r, g1_l, be1_l, x, xh, xl, 1);

        wsplit_t<<<dim3(FF_/32, D_/32), tb>>>(W1 + (size_t)l*D_*FF_, wth + wb + 4*MB1, wtl + wb + 4*MB1, D_, FF_);
        hmma_gemm<<<gFF1, 256, GSMEM>>>(xh, xl, wth + wb + 4*MB1, wtl + wb + 4*MB1,
                                        b1_l, nullptr, nullptr,
                                        nullptr, hh, hl, nullptr, M_, FF_, D_, OUT_SPLIT);
        wsplit_t<<<dim3(D_/32, FF_/32), tb>>>(W2 + (size_t)l*FF_*D_, wth + wb + 8*MB1, wtl + wb + 8*MB1, FF_, D_);
        hmma_gemm<<<gProj, 256, GSMEM>>>(hh, hl, wth + wb + 8*MB1, wtl + wb + 8*MB1,
                                         b2_l, nullptr, nullptr,
                                         r, nullptr, nullptr, nullptr, M_, D_, FF_, OUT_F32);

        float* dst = (l == L_-1) ? out : x;
        add_ln_split<<<M_, 256>>>(x, r, g2_l, be2_l, dst, xh, xl, (l < L_-1) ? 1 : 0);
    }
}

// round 13
// speedup vs baseline: 4.0597x; 1.3354x over previous
#include <cuda_runtime.h>
#include <cuda_bf16.h>
#include <cuda_fp16.h>
#include <math.h>
#include <stdint.h>

// ---------------------------------------------------------------------------
// Problem constants
// ---------------------------------------------------------------------------
#define B_  2
#define S_  2048
#define D_  1024
#define H_  16
#define DK_ 64
#define FF_ 4096
#define L_  6
#define M_  (B_*S_)          // 4096 rows
#define BH_ (B_*H_)          // 32

// ---------------------------------------------------------------------------
// Scratch (device globals — no allocations allowed)
// ---------------------------------------------------------------------------
__device__ float g_x[M_*D_];                 // running activation (fp32)
__device__ float g_r[M_*D_];                 // residual branch (fp32)
__device__ float g_pe[B_*D_];

__device__ __half        g_xa[M_*D_];        // x as fp16 (GEMM A input)
__device__ __half        g_ha[M_*FF_];       // FF hidden as fp16
__device__ __nv_bfloat16 g_oh[M_*D_];        // attention out hi (bf16)
__device__ __nv_bfloat16 g_ol[M_*D_];        // attention out lo (bf16)

__device__ __nv_bfloat16 g_qh[M_*D_];        // Q  [BH, S, 64] bf16
__device__ __nv_bfloat16 g_kh[M_*D_];        // K  [BH, S, 64] bf16
__device__ __half        g_vh[M_*D_];        // V  [BH, S, 64] f16
__device__ __half        g_vt[M_*D_];        // V^T [BH, 64, S] f16

// split weights, transposed to [N,K].  fp16 pairs for QKV/W1/W2, bf16 for Wo.
#define MB1 (1u<<20)
#define WL_ (12u*MB1)
__device__ __nv_bfloat16 g_wth[6*12*1024*1024];
__device__ __nv_bfloat16 g_wtl[6*12*1024*1024];

// ---------------------------------------------------------------------------
// PTX helpers
// ---------------------------------------------------------------------------
__device__ __forceinline__ uint32_t smem_u32(const void* p) {
    return (uint32_t)__cvta_generic_to_shared(p);
}
#define CP16(dst, src) \
    asm volatile("cp.async.cg.shared.global [%0], [%1], 16;" :: "r"(dst), "l"(src) : "memory")
#define CP_COMMIT() asm volatile("cp.async.commit_group;" ::: "memory")
#define CP_WAIT2()  asm volatile("cp.async.wait_group 2;" ::: "memory")
#define CP_WAIT1()  asm volatile("cp.async.wait_group 1;" ::: "memory")
#define CP_WAIT0()  asm volatile("cp.async.wait_group 0;" ::: "memory")

#define LDSM4(r, addr) \
    asm volatile("ldmatrix.sync.aligned.m8n8.x4.shared.b16 {%0,%1,%2,%3}, [%4];" \
        : "=r"((r)[0]), "=r"((r)[1]), "=r"((r)[2]), "=r"((r)[3]) : "r"(addr))

#define MMA16816(c, a, b0, b1) \
    asm volatile("mma.sync.aligned.m16n8k16.row.col.f32.bf16.bf16.f32 " \
        "{%0,%1,%2,%3}, {%4,%5,%6,%7}, {%8,%9}, {%0,%1,%2,%3};" \
        : "+f"((c)[0]), "+f"((c)[1]), "+f"((c)[2]), "+f"((c)[3]) \
        : "r"((a)[0]), "r"((a)[1]), "r"((a)[2]), "r"((a)[3]), "r"(b0), "r"(b1))

#define MMA16816H(c, a, b0, b1) \
    asm volatile("mma.sync.aligned.m16n8k16.row.col.f32.f16.f16.f32 " \
        "{%0,%1,%2,%3}, {%4,%5,%6,%7}, {%8,%9}, {%0,%1,%2,%3};" \
        : "+f"((c)[0]), "+f"((c)[1]), "+f"((c)[2]), "+f"((c)[3]) \
        : "r"((a)[0]), "r"((a)[1]), "r"((a)[2]), "r"((a)[3]), "r"(b0), "r"(b1))

__device__ __forceinline__ uint32_t exp2_f16x2(float lo, float hi) {
    uint32_t t, d;
    asm("cvt.rn.f16x2.f32 %0, %1, %2;" : "=r"(t) : "f"(hi), "f"(lo));
    asm("ex2.approx.f16x2 %0, %1;" : "=r"(d) : "r"(t));
    return d;
}
__device__ __forceinline__ float exp2f_fast(float x) {
    float y; asm("ex2.approx.f32 %0, %1;" : "=f"(y) : "f"(x)); return y;
}
__device__ __forceinline__ __nv_bfloat162 split_hi2(float a, float b,
                                                    __nv_bfloat162* lo2) {
    __nv_bfloat16 ha = __float2bfloat16(a), hb = __float2bfloat16(b);
    *lo2 = __nv_bfloat162(__float2bfloat16(a - __bfloat162float(ha)),
                          __float2bfloat16(b - __bfloat162float(hb)));
    return __nv_bfloat162(ha, hb);
}

// ---------------------------------------------------------------------------
// Shared GEMM geometry
// ---------------------------------------------------------------------------
#define KC      64
#define PITCHB  144
#define TILEB   (128*PITCHB)          // 18432
#define STG3F   (3*TILEB)             // 55296  (fp16: A, Bh, Bl)
#define F16SMEM (3*STG3F)             // 165888 (3 stages)
#define STG3B   (4*TILEB)             // 73728  (bf16: Ah, Al, Bh, Bl)
#define BF3SMEM (3*STG3B)             // 221184 (3 stages)

extern __shared__ char dynsmem[];

// ---------------------------------------------------------------------------
// fp16 2-pass GEMM:  C = A[M,K] @ (Bh+Bl)^T[N,K] + bias.
// modes: 0 = QKV head layouts (N=3072); 1 = ReLU -> f16; 2 = fp32 C.
// 128x128 tile, 8 warps (64x32), K-chunk 64, 3-stage cp.async.
// ---------------------------------------------------------------------------
#define QKV_MODE  0
#define RELU_MODE 1
#define F32_MODE  2

__global__ __launch_bounds__(256, 1)
void gemm_f16(const __half* __restrict__ A,
              const __half* __restrict__ Bh, const __half* __restrict__ Bl,
              const float* __restrict__ bias0, const float* __restrict__ bias1,
              const float* __restrict__ bias2,
              float* __restrict__ C, __half* __restrict__ Hout,
              __nv_bfloat16* __restrict__ Qout, __nv_bfloat16* __restrict__ Kout,
              __half* __restrict__ Vout,
              int M, int N, int K, int mode) {
    uint32_t sb = smem_u32(dynsmem);
    int tid = threadIdx.x, lane = tid & 31, wid = tid >> 5;
    int wm = wid >> 2, wn = wid & 3;
    int m0 = blockIdx.y * 128, n0 = blockIdx.x * 128;

    float acc[4][4][4];
    #pragma unroll
    for (int i = 0; i < 4; i++)
        #pragma unroll
        for (int j = 0; j < 4; j++)
            #pragma unroll
            for (int q = 0; q < 4; q++) acc[i][j][q] = 0.f;

    int seg = tid & 7, rb = tid >> 3;
    const __half* gsrc[3];
    gsrc[0] = A  + (size_t)m0 * K;
    gsrc[1] = Bh + (size_t)n0 * K;
    gsrc[2] = Bl + (size_t)n0 * K;

    int lrow = lane & 15, lk16 = (lane >> 4) * 16;
    uint32_t aoff = (uint32_t)((wm*64 + lrow) * PITCHB) + lk16;
    uint32_t boff = (uint32_t)((wn*32 + lrow) * PITCHB) + lk16;

    int nc = K / KC;                       // >= 16 here

    // prologue: chunks 0,1 -> stages 0,1
    #pragma unroll
    for (int s2 = 0; s2 < 2; s2++) {
        #pragma unroll
        for (int t = 0; t < 3; t++)
            #pragma unroll
            for (int i = 0; i < 4; i++) {
                int row = rb + i * 32;
                CP16(sb + s2*STG3F + t*TILEB + (uint32_t)(row * PITCHB + seg * 16),
                     (const char*)(gsrc[t] + (size_t)row * K + s2*KC) + seg * 16);
            }
        CP_COMMIT();
    }

    for (int c = 0; c < nc; c++) {
        if (c + 2 < nc) {
            int ns = (c + 2) % 3;
            int k0 = (c + 2) * KC;
            #pragma unroll
            for (int t = 0; t < 3; t++)
                #pragma unroll
                for (int i = 0; i < 4; i++) {
                    int row = rb + i * 32;
                    CP16(sb + ns*STG3F + t*TILEB + (uint32_t)(row * PITCHB + seg * 16),
                         (const char*)(gsrc[t] + (size_t)row * K + k0) + seg * 16);
                }
            CP_COMMIT();
            CP_WAIT2();
        } else if (c + 1 < nc) {
            CP_WAIT1();
        } else {
            CP_WAIT0();
        }
        __syncthreads();

        uint32_t base = sb + (c % 3) * STG3F;
        #pragma unroll
        for (int kk = 0; kk < KC; kk += 16) {
            uint32_t a4[4][4], bb[2][4];
            #pragma unroll
            for (int mt = 0; mt < 4; mt++)
                LDSM4(a4[mt], base + aoff + mt*(16*PITCHB) + kk*2);
            #pragma unroll
            for (int nt2 = 0; nt2 < 2; nt2++)
                LDSM4(bb[nt2], base + TILEB + boff + nt2*(16*PITCHB) + kk*2);
            #pragma unroll
            for (int mt = 0; mt < 4; mt++)               // A*Bh
                #pragma unroll
                for (int nt = 0; nt < 4; nt++)
                    MMA16816H(acc[mt][nt], a4[mt], bb[nt>>1][nt&1], bb[nt>>1][2+(nt&1)]);
            #pragma unroll
            for (int nt2 = 0; nt2 < 2; nt2++)            // reuse bb for Bl
                LDSM4(bb[nt2], base + 2*TILEB + boff + nt2*(16*PITCHB) + kk*2);
            #pragma unroll
            for (int mt = 0; mt < 4; mt++)               // A*Bl
                #pragma unroll
                for (int nt = 0; nt < 4; nt++)
                    MMA16816H(acc[mt][nt], a4[mt], bb[nt>>1][nt&1], bb[nt>>1][2+(nt&1)]);
        }
        __syncthreads();
    }

    int r0 = lane >> 2, cl = (lane & 3) * 2;
    int msel = n0 >> 10;
    const float* bias = (mode == QKV_MODE)
                      ? (msel == 0 ? bias0 : (msel == 1 ? bias1 : bias2))
                      : bias0;
    #pragma unroll
    for (int nt = 0; nt < 4; nt++) {
        int col  = n0 + wn*32 + nt*8 + cl;
        int ncol = (mode == QKV_MODE) ? (col & 1023) : col;
        float bx = bias[ncol], by = bias[ncol+1];
        #pragma unroll
        for (int mt = 0; mt < 4; mt++) {
            int row = m0 + wm*64 + mt*16 + r0;
            float v0 = acc[mt][nt][0] + bx, v1 = acc[mt][nt][1] + by;
            float v2 = acc[mt][nt][2] + bx, v3 = acc[mt][nt][3] + by;
            if (mode == F32_MODE) {
                *(float2*)(C + (size_t)row * N + col)       = make_float2(v0, v1);
                *(float2*)(C + (size_t)(row + 8) * N + col) = make_float2(v2, v3);
            } else if (mode == RELU_MODE) {
                v0 = fmaxf(v0, 0.f); v1 = fmaxf(v1, 0.f);
                v2 = fmaxf(v2, 0.f); v3 = fmaxf(v3, 0.f);
                *(__half2*)(Hout + (size_t)row * N + col)     = __floats2half2_rn(v0, v1);
                *(__half2*)(Hout + (size_t)(row+8) * N + col) = __floats2half2_rn(v2, v3);
            } else {                                     // QKV head layouts
                int b = row >> 11, sidx = row & 2047;
                int hh = ncol >> 6, dd = ncol & 63;
                size_t base0 = (((size_t)b*H_ + hh)*S_ + sidx)*64 + dd;
                if (msel == 0) {
                    *(__nv_bfloat162*)(Qout + base0) =
                        __nv_bfloat162(__float2bfloat16(v0), __float2bfloat16(v1));
                    *(__nv_bfloat162*)(Qout + base0 + 8*64) =
                        __nv_bfloat162(__float2bfloat16(v2), __float2bfloat16(v3));
                } else if (msel == 1) {
                    *(__nv_bfloat162*)(Kout + base0) =
                        __nv_bfloat162(__float2bfloat16(v0), __float2bfloat16(v1));
                    *(__nv_bfloat162*)(Kout + base0 + 8*64) =
                        __nv_bfloat162(__float2bfloat16(v2), __float2bfloat16(v3));
                } else {
                    *(__half2*)(Vout + base0)        = __floats2half2_rn(v0, v1);
                    *(__half2*)(Vout + base0 + 8*64) = __floats2half2_rn(v2, v3);
                }
            }
        }
    }
}

// ---------------------------------------------------------------------------
// bf16x3 GEMM (O-projection only): C fp32 = (Ah+Al) @ (Bh+Bl)^T + bias.
// 3-stage cp.async, 221KB smem.
// ---------------------------------------------------------------------------
__global__ __launch_bounds__(256, 1)
void gemm_bf3(const __nv_bfloat16* __restrict__ Ah, const __nv_bfloat16* __restrict__ Al,
              const __nv_bfloat16* __restrict__ Bh, const __nv_bfloat16* __restrict__ Bl,
              const float* __restrict__ bias, float* __restrict__ C,
              int M, int N, int K) {
    uint32_t sb = smem_u32(dynsmem);
    int tid = threadIdx.x, lane = tid & 31, wid = tid >> 5;
    int wm = wid >> 2, wn = wid & 3;
    int m0 = blockIdx.y * 128, n0 = blockIdx.x * 128;

    float acc[4][4][4];
    #pragma unroll
    for (int i = 0; i < 4; i++)
        #pragma unroll
        for (int j = 0; j < 4; j++)
            #pragma unroll
            for (int q = 0; q < 4; q++) acc[i][j][q] = 0.f;

    int seg = tid & 7, rb = tid >> 3;
    const __nv_bfloat16* gsrc[4];
    gsrc[0] = Ah + (size_t)m0 * K;
    gsrc[1] = Al + (size_t)m0 * K;
    gsrc[2] = Bh + (size_t)n0 * K;
    gsrc[3] = Bl + (size_t)n0 * K;

    int lrow = lane & 15, lk16 = (lane >> 4) * 16;
    uint32_t aoff = (uint32_t)((wm*64 + lrow) * PITCHB) + lk16;
    uint32_t boff = (uint32_t)((wn*32 + lrow) * PITCHB) + lk16;

    int nc = K / KC;

    #pragma unroll
    for (int s2 = 0; s2 < 2; s2++) {
        #pragma unroll
        for (int t = 0; t < 4; t++)
            #pragma unroll
            for (int i = 0; i < 4; i++) {
                int row = rb + i * 32;
                CP16(sb + s2*STG3B + t*TILEB + (uint32_t)(row * PITCHB + seg * 16),
                     (const char*)(gsrc[t] + (size_t)row * K + s2*KC) + seg * 16);
            }
        CP_COMMIT();
    }

    for (int c = 0; c < nc; c++) {
        if (c + 2 < nc) {
            int ns = (c + 2) % 3;
            int k0 = (c + 2) * KC;
            #pragma unroll
            for (int t = 0; t < 4; t++)
                #pragma unroll
                for (int i = 0; i < 4; i++) {
                    int row = rb + i * 32;
                    CP16(sb + ns*STG3B + t*TILEB + (uint32_t)(row * PITCHB + seg * 16),
                         (const char*)(gsrc[t] + (size_t)row * K + k0) + seg * 16);
                }
            CP_COMMIT();
            CP_WAIT2();
        } else if (c + 1 < nc) {
            CP_WAIT1();
        } else {
            CP_WAIT0();
        }
        __syncthreads();

        uint32_t base = sb + (c % 3) * STG3B;
        #pragma unroll
        for (int kk = 0; kk < KC; kk += 16) {
            uint32_t ah4[4][4], al4[4][4], bb[2][4];
            #pragma unroll
            for (int mt = 0; mt < 4; mt++)
                LDSM4(ah4[mt], base + aoff + mt*(16*PITCHB) + kk*2);
            #pragma unroll
            for (int mt = 0; mt < 4; mt++)
                LDSM4(al4[mt], base + TILEB + aoff + mt*(16*PITCHB) + kk*2);
            #pragma unroll
            for (int nt2 = 0; nt2 < 2; nt2++)
                LDSM4(bb[nt2], base + 2*TILEB + boff + nt2*(16*PITCHB) + kk*2);
            #pragma unroll
            for (int mt = 0; mt < 4; mt++)
                #pragma unroll
                for (int nt = 0; nt < 4; nt++)
                    MMA16816(acc[mt][nt], ah4[mt], bb[nt>>1][nt&1], bb[nt>>1][2+(nt&1)]);
            #pragma unroll
            for (int mt = 0; mt < 4; mt++)
                #pragma unroll
                for (int nt = 0; nt < 4; nt++)
                    MMA16816(acc[mt][nt], al4[mt], bb[nt>>1][nt&1], bb[nt>>1][2+(nt&1)]);
            #pragma unroll
            for (int nt2 = 0; nt2 < 2; nt2++)
                LDSM4(bb[nt2], base + 3*TILEB + boff + nt2*(16*PITCHB) + kk*2);
            #pragma unroll
            for (int mt = 0; mt < 4; mt++)
                #pragma unroll
                for (int nt = 0; nt < 4; nt++)
                    MMA16816(acc[mt][nt], ah4[mt], bb[nt>>1][nt&1], bb[nt>>1][2+(nt&1)]);
        }
        __syncthreads();
    }

    int r0 = lane >> 2, cl = (lane & 3) * 2;
    #pragma unroll
    for (int nt = 0; nt < 4; nt++) {
        int col = n0 + wn*32 + nt*8 + cl;
        float bx = bias[col], by = bias[col+1];
        #pragma unroll
        for (int mt = 0; mt < 4; mt++) {
            int row = m0 + wm*64 + mt*16 + r0;
            *(float2*)(C + (size_t)row * N + col) =
                make_float2(acc[mt][nt][0] + bx, acc[mt][nt][1] + by);
            *(float2*)(C + (size_t)(row + 8) * N + col) =
                make_float2(acc[mt][nt][2] + bx, acc[mt][nt][3] + by);
        }
    }
}

// ---------------------------------------------------------------------------
// V transpose: [BH,S,64] f16 -> [BH,64,S] f16, coalesced both sides.
// ---------------------------------------------------------------------------
__global__ __launch_bounds__(256)
void vtrans(const __half* __restrict__ vh, __half* __restrict__ vt) {
    __shared__ __half sh[64][65];
    int bh = blockIdx.y, s0 = blockIdx.x * 64;
    int tx = threadIdx.x & 31, ty = threadIdx.x >> 5;
    const __half* src = vh + ((size_t)bh*S_ + s0) * 64;
    #pragma unroll
    for (int i = 0; i < 8; i++) {
        int row = ty + i*8;
        __half2 v2 = *(const __half2*)(src + (size_t)row*64 + tx*2);
        sh[row][tx*2]   = __low2half(v2);
        sh[row][tx*2+1] = __high2half(v2);
    }
    __syncthreads();
    __half* dst = vt + (size_t)bh*64*S_ + s0;
    #pragma unroll
    for (int i = 0; i < 8; i++) {
        int dcol = ty + i*8;
        __half2 o = __halves2half2(sh[tx*2][dcol], sh[tx*2+1][dcol]);
        *(__half2*)(dst + (size_t)dcol*S_ + tx*2) = o;
    }
}

// ---------------------------------------------------------------------------
// Fused flash attention (unchanged from R10 pass).
// ---------------------------------------------------------------------------
#define FQP 144
#define QSZ (128*FQP)
#define FVP 272
#define VSZ (64*FVP)
#define MSZ 512
#define STG (QSZ + VSZ + MSZ)
#define FSMEM (QSZ + 2*STG)           // 91136

#define ONES_H2 0x3C003C00u

__global__ __launch_bounds__(256, 1)
void flash_attn(const __nv_bfloat16* __restrict__ qh,
                const __nv_bfloat16* __restrict__ kh,
                const __half* __restrict__ vt,
                const int* __restrict__ mask,
                __nv_bfloat16* __restrict__ Ohi, __nv_bfloat16* __restrict__ Olo) {
    uint32_t sb = smem_u32(dynsmem);
    int tid = threadIdx.x, lane = tid & 31, w = tid >> 5;
    int bh = blockIdx.y, q0 = blockIdx.x * 128;
    int b = bh >> 4, h = bh & 15;

    const __nv_bfloat16* qg = qh + ((size_t)bh*S_ + q0) * 64;
    const __nv_bfloat16* kg = kh + (size_t)bh*S_ * 64;
    const __half*        vg = vt + (size_t)bh*64 * S_;
    const int* mg = mask + b*S_;

    int seg = tid & 7,  rb  = tid >> 3;
    int vseg = tid & 15, vrb = tid >> 4;

    #pragma unroll
    for (int i = 0; i < 4; i++) {
        int row = rb + i * 32;
        CP16(sb + (uint32_t)(row*FQP + seg*16),
             (const char*)(qg + (size_t)row*64) + seg*16);
        CP16(sb + QSZ + (uint32_t)(row*FQP + seg*16),
             (const char*)(kg + (size_t)row*64) + seg*16);
    }
    #pragma unroll
    for (int i = 0; i < 4; i++) {
        int row = vrb + i * 16;
        CP16(sb + QSZ + QSZ + (uint32_t)(row*FVP + vseg*16),
             (const char*)(vg + (size_t)row*S_) + vseg*16);
    }
    if (tid < 32) CP16(sb + QSZ + QSZ + VSZ + tid*16, (const char*)mg + tid*16);
    CP_COMMIT();

    uint32_t aoffQ = (uint32_t)((w*16 + (lane&15))*FQP) + (lane>>4)*16;
    uint32_t koff  = (uint32_t)((lane&15)*FQP) + (lane>>4)*16;
    uint32_t voff  = (uint32_t)((lane&15)*FVP) + (lane>>4)*16;

    float m0 = -INFINITY, m1 = -INFINITY;
    float oacc[8][4], lacc[4];
    #pragma unroll
    for (int i = 0; i < 8; i++)
        #pragma unroll
        for (int q = 0; q < 4; q++) oacc[i][q] = 0.f;
    #pragma unroll
    for (int q = 0; q < 4; q++) lacc[q] = 0.f;

    const float SCALE = 0.0450842201736734f;   // log2(e)/32
    const float MASKNEG = -4.5e7f;

    for (int j = 0; j < S_/128; j++) {
        if (j + 1 < S_/128) {
            uint32_t stg2 = sb + QSZ + ((j+1)&1)*STG;
            const char* ks = (const char*)(kg + (size_t)(j+1)*128*64);
            #pragma unroll
            for (int i = 0; i < 4; i++) {
                int row = rb + i * 32;
                CP16(stg2 + (uint32_t)(row*FQP + seg*16), ks + (size_t)row*128 + seg*16);
            }
            #pragma unroll
            for (int i = 0; i < 4; i++) {
                int row = vrb + i * 16;
                CP16(stg2 + QSZ + (uint32_t)(row*FVP + vseg*16),
                     (const char*)(vg + (size_t)row*S_ + (j+1)*128) + vseg*16);
            }
            if (tid < 32) CP16(stg2 + QSZ + VSZ + tid*16,
                               (const char*)(mg + (j+1)*128) + tid*16);
            CP_COMMIT();
            CP_WAIT1();
        } else {
            CP_WAIT0();
        }
        __syncthreads();

        uint32_t stg = sb + QSZ + (j&1)*STG;
        const int* msk = (const int*)(dynsmem + QSZ + (j&1)*STG + QSZ + VSZ);

        float sacc[16][4];
        #pragma unroll
        for (int i = 0; i < 16; i++)
            #pragma unroll
            for (int q = 0; q < 4; q++) sacc[i][q] = 0.f;

        #pragma unroll
        for (int kk = 0; kk < 64; kk += 16) {
            uint32_t af[4];
            LDSM4(af, sb + aoffQ + kk*2);
            #pragma unroll
            for (int nt2 = 0; nt2 < 8; nt2++) {
                uint32_t bf4[4];
                LDSM4(bf4, stg + koff + nt2*(16*FQP) + kk*2);
                MMA16816(sacc[2*nt2],   af, bf4[0], bf4[2]);
                MMA16816(sacc[2*nt2+1], af, bf4[1], bf4[3]);
            }
        }

        float rm0 = -INFINITY, rm1 = -INFINITY;
        #pragma unroll
        for (int nt = 0; nt < 16; nt++) {
            int col = nt*8 + (lane&3)*2;
            int2 mk = *(const int2*)(msk + col);
            float s0 = mk.x ? sacc[nt][0]*SCALE : MASKNEG;
            float s1 = mk.y ? sacc[nt][1]*SCALE : MASKNEG;
            float s2 = mk.x ? sacc[nt][2]*SCALE : MASKNEG;
            float s3 = mk.y ? sacc[nt][3]*SCALE : MASKNEG;
            sacc[nt][0] = s0; sacc[nt][1] = s1; sacc[nt][2] = s2; sacc[nt][3] = s3;
            rm0 = fmaxf(rm0, fmaxf(s0, s1));
            rm1 = fmaxf(rm1, fmaxf(s2, s3));
        }
        rm0 = fmaxf(rm0, __shfl_xor_sync(0xffffffffu, rm0, 1));
        rm0 = fmaxf(rm0, __shfl_xor_sync(0xffffffffu, rm0, 2));
        rm1 = fmaxf(rm1, __shfl_xor_sync(0xffffffffu, rm1, 1));
        rm1 = fmaxf(rm1, __shfl_xor_sync(0xffffffffu, rm1, 2));

        float mn0 = fmaxf(m0, rm0), mn1 = fmaxf(m1, rm1);
        float f0 = exp2f_fast(m0 - mn0), f1 = exp2f_fast(m1 - mn1);
        m0 = mn0; m1 = mn1;
        lacc[0] *= f0; lacc[1] *= f0; lacc[2] *= f1; lacc[3] *= f1;
        #pragma unroll
        for (int i = 0; i < 8; i++) {
            oacc[i][0] *= f0; oacc[i][1] *= f0;
            oacc[i][2] *= f1; oacc[i][3] *= f1;
        }

        #pragma unroll
        for (int t = 0; t < 8; t++) {
            uint32_t pa[4];
            pa[0] = exp2_f16x2(sacc[2*t][0] - m0,   sacc[2*t][1] - m0);
            pa[1] = exp2_f16x2(sacc[2*t][2] - m1,   sacc[2*t][3] - m1);
            pa[2] = exp2_f16x2(sacc[2*t+1][0] - m0, sacc[2*t+1][1] - m0);
            pa[3] = exp2_f16x2(sacc[2*t+1][2] - m1, sacc[2*t+1][3] - m1);
            MMA16816H(lacc, pa, ONES_H2, ONES_H2);
            #pragma unroll
            for (int nt2 = 0; nt2 < 4; nt2++) {
                uint32_t vf4[4];
                LDSM4(vf4, stg + QSZ + voff + nt2*(16*FVP) + t*32);
                MMA16816H(oacc[2*nt2],   pa, vf4[0], vf4[2]);
                MMA16816H(oacc[2*nt2+1], pa, vf4[1], vf4[3]);
            }
        }
        __syncthreads();
    }

    float il0 = 1.f / lacc[0], il1 = 1.f / lacc[2];
    int r0 = lane >> 2, cl = (lane & 3) * 2;
    int qrow = q0 + w*16 + r0;
    size_t gr0 = (size_t)(b*S_ + qrow) * D_;
    size_t gr1 = gr0 + (size_t)8 * D_;
    #pragma unroll
    for (int nt2 = 0; nt2 < 8; nt2++) {
        int col = h*64 + nt2*8 + cl;
        float o0 = oacc[nt2][0]*il0, o1 = oacc[nt2][1]*il0;
        float o2 = oacc[nt2][2]*il1, o3 = oacc[nt2][3]*il1;
        __nv_bfloat162 lo2;
        __nv_bfloat162 hi2 = split_hi2(o0, o1, &lo2);
        *(__nv_bfloat162*)(Ohi + gr0 + col) = hi2;
        *(__nv_bfloat162*)(Olo + gr0 + col) = lo2;
        hi2 = split_hi2(o2, o3, &lo2);
        *(__nv_bfloat162*)(Ohi + gr1 + col) = hi2;
        *(__nv_bfloat162*)(Olo + gr1 + col) = lo2;
    }
}

// ---------------------------------------------------------------------------
// Weight transpose+split kernels:  W fp32 [K,N] -> [N,K] pairs.
// ---------------------------------------------------------------------------
__global__ void wsplit_t(const float* __restrict__ W,
                         __nv_bfloat16* __restrict__ th,
                         __nv_bfloat16* __restrict__ tl, int K, int N) {
    __shared__ float sh[32][33];
    int n0 = blockIdx.x * 32, k0 = blockIdx.y * 32;
    int tx = threadIdx.x, ty = threadIdx.y;
    #pragma unroll
    for (int i = 0; i < 4; i++)
        sh[ty + i*8][tx] = W[(size_t)(k0 + ty + i*8) * N + n0 + tx];
    __syncthreads();
    #pragma unroll
    for (int i = 0; i < 4; i++) {
        int n = n0 + ty + i*8;
        float v = sh[tx][ty + i*8];
        __nv_bfloat16 hb = __float2bfloat16(v);
        th[(size_t)n * K + k0 + tx] = hb;
        tl[(size_t)n * K + k0 + tx] = __float2bfloat16(v - __bfloat162float(hb));
    }
}

__global__ void wsplit_th(const float* __restrict__ W,
                          __half* __restrict__ th,
                          __half* __restrict__ tl, int K, int N) {
    __shared__ float sh[32][33];
    int n0 = blockIdx.x * 32, k0 = blockIdx.y * 32;
    int tx = threadIdx.x, ty = threadIdx.y;
    #pragma unroll
    for (int i = 0; i < 4; i++)
        sh[ty + i*8][tx] = W[(size_t)(k0 + ty + i*8) * N + n0 + tx];
    __syncthreads();
    #pragma unroll
    for (int i = 0; i < 4; i++) {
        int n = n0 + ty + i*8;
        float v = sh[tx][ty + i*8];
        __half hb = __float2half_rn(v);
        th[(size_t)n * K + k0 + tx] = hb;
        tl[(size_t)n * K + k0 + tx] = __float2half_rn(v - __half2float(hb));
    }
}

// ---------------------------------------------------------------------------
// Reductions
// ---------------------------------------------------------------------------
__device__ __forceinline__ float warpSum(float v) {
    #pragma unroll
    for (int o = 16; o; o >>= 1) v += __shfl_xor_sync(0xffffffffu, v, o);
    return v;
}
__device__ __forceinline__ float blockSum(float v, float* sh) {
    int tid = threadIdx.x, lane = tid & 31, w = tid >> 5;
    v = warpSum(v);
    if (lane == 0) sh[w] = v;
    __syncthreads();
    float t = sh[0];
    #pragma unroll
    for (int i = 1; i < 8; i++) t += sh[i];
    __syncthreads();
    return t;
}

// ---------------------------------------------------------------------------
// PE + fused embed (writes x fp32 and fp16 copy)
// ---------------------------------------------------------------------------
__global__ void pe_kernel(float* __restrict__ pe) {
    int idx = blockIdx.x * blockDim.x + threadIdx.x;
    if (idx >= B_*D_) return;
    int b = idx / D_, d = idx % D_;
    int i = d >> 1;
    double c = -log(10000.0) / (double)D_;
    float divf = (float)exp((double)(2*i) * c);
    float ang  = (float)b / divf;
    double ad  = (double)ang;
    pe[idx] = (d & 1) ? (float)cos(ad) : (float)sin(ad);
}

__global__ void embed_split(const int* __restrict__ src,
                            const float* __restrict__ emb,
                            const float* __restrict__ pe,
                            float* __restrict__ x,
                            __half* __restrict__ xa) {
    int idx = blockIdx.x * blockDim.x + threadIdx.x;
    if (idx >= M_*D_) return;
    int d  = idx & (D_-1);
    int bs = idx >> 10;
    int b  = bs >> 11;
    float v = emb[(size_t)src[bs]*D_ + d] + pe[b*D_ + d];
    x[idx] = v;
    xa[idx] = __float2half_rn(v);
}

// ---------------------------------------------------------------------------
// out = LayerNorm(x + r) * g + be, with fused fp16 copy
// ---------------------------------------------------------------------------
__global__ __launch_bounds__(256)
void add_ln_split(const float* __restrict__ x, const float* __restrict__ rr,
                  const float* __restrict__ g, const float* __restrict__ be,
                  float* __restrict__ out, __half* __restrict__ xa,
                  int do_split) {
    __shared__ float sh[8];
    int m = blockIdx.x, tid = threadIdx.x;
    float4 v = *(const float4*)(x + (size_t)m*D_ + tid*4);
    float4 rv = *(const float4*)(rr + (size_t)m*D_ + tid*4);
    v.x += rv.x; v.y += rv.y; v.z += rv.z; v.w += rv.w;
    float s = v.x + v.y + v.z + v.w;
    s = blockSum(s, sh);
    float mean = s * (1.0f / D_);
    float d0 = v.x - mean, d1 = v.y - mean, d2 = v.z - mean, d3 = v.w - mean;
    float sq = d0*d0 + d1*d1 + d2*d2 + d3*d3;
    sq = blockSum(sq, sh);
    float var = sq * (1.0f / D_);
    float rstd = rsqrtf(var + 1e-5f);
    float4 gg = *(const float4*)(g + tid*4);
    float4 bb = *(const float4*)(be + tid*4);
    float4 o;
    o.x = d0*rstd*gg.x + bb.x;
    o.y = d1*rstd*gg.y + bb.y;
    o.z = d2*rstd*gg.z + bb.z;
    o.w = d3*rstd*gg.w + bb.w;
    *(float4*)(out + (size_t)m*D_ + tid*4) = o;
    if (do_split) {
        size_t p = (size_t)m*D_ + tid*4;
        *(__half2*)(xa + p)     = __floats2half2_rn(o.x, o.y);
        *(__half2*)(xa + p + 2) = __floats2half2_rn(o.z, o.w);
    }
}

// ---------------------------------------------------------------------------
// Launch
// ---------------------------------------------------------------------------
extern "C" void kernel_launch(void* const* d_in, const int* in_sizes, int n_in,
                              void* d_out, int out_size) {
    const int*   src  = (const int*)  d_in[0];
    const int*   mask = (const int*)  d_in[1];
    const float* emb  = (const float*)d_in[2];
    const float* Wq   = (const float*)d_in[3];
    const float* bq   = (const float*)d_in[4];
    const float* Wk   = (const float*)d_in[5];
    const float* bk   = (const float*)d_in[6];
    const float* Wv   = (const float*)d_in[7];
    const float* bv   = (const float*)d_in[8];
    const float* Wo   = (const float*)d_in[9];
    const float* bo   = (const float*)d_in[10];
    const float* W1   = (const float*)d_in[11];
    const float* b1   = (const float*)d_in[12];
    const float* W2   = (const float*)d_in[13];
    const float* b2   = (const float*)d_in[14];
    const float* g1   = (const float*)d_in[15];
    const float* be1  = (const float*)d_in[16];
    const float* g2   = (const float*)d_in[17];
    const float* be2  = (const float*)d_in[18];
    float* out = (float*)d_out;

    float *x, *r, *pe;
    __nv_bfloat16 *wth, *wtl, *oh, *ol, *qh, *kh;
    __half *xa, *ha, *vh, *vt;
    cudaGetSymbolAddress((void**)&x,  g_x);
    cudaGetSymbolAddress((void**)&r,  g_r);
    cudaGetSymbolAddress((void**)&pe, g_pe);
    cudaGetSymbolAddress((void**)&wth, g_wth);
    cudaGetSymbolAddress((void**)&wtl, g_wtl);
    cudaGetSymbolAddress((void**)&xa, g_xa);
    cudaGetSymbolAddress((void**)&ha, g_ha);
    cudaGetSymbolAddress((void**)&oh, g_oh);
    cudaGetSymbolAddress((void**)&ol, g_ol);
    cudaGetSymbolAddress((void**)&qh, g_qh);
    cudaGetSymbolAddress((void**)&kh, g_kh);
    cudaGetSymbolAddress((void**)&vh, g_vh);
    cudaGetSymbolAddress((void**)&vt, g_vt);
    __half* wthh = (__half*)wth;
    __half* wtlh = (__half*)wtl;

    cudaFuncSetAttribute(gemm_f16,   cudaFuncAttributeMaxDynamicSharedMemorySize, F16SMEM);
    cudaFuncSetAttribute(gemm_bf3,   cudaFuncAttributeMaxDynamicSharedMemorySize, BF3SMEM);
    cudaFuncSetAttribute(flash_attn, cudaFuncAttributeMaxDynamicSharedMemorySize, FSMEM);

    pe_kernel<<<(B_*D_ + 255)/256, 256>>>(pe);
    embed_split<<<(M_*D_ + 255)/256, 256>>>(src, emb, pe, x, xa);

    dim3 tb(32, 8);
    dim3 gQKV (3*D_/128, M_/128);
    dim3 gProj(D_/128,   M_/128);
    dim3 gFF1 (FF_/128,  M_/128);
    dim3 gFlash(S_/128, BH_);
    dim3 gVT  (S_/64, BH_);

    for (int l = 0; l < L_; l++) {
        size_t wb = (size_t)l * WL_;
        const float* bq_l = bq + (size_t)l*D_;
        const float* bk_l = bk + (size_t)l*D_;
        const float* bv_l = bv + (size_t)l*D_;
        const float* bo_l = bo + (size_t)l*D_;
        const float* b1_l = b1 + (size_t)l*FF_;
        const float* b2_l = b2 + (size_t)l*D_;
        const float* g1_l = g1 + (size_t)l*D_;
        const float* be1_l= be1+ (size_t)l*D_;
        const float* g2_l = g2 + (size_t)l*D_;
        const float* be2_l= be2+ (size_t)l*D_;

        // QKV weights -> fp16 split
        wsplit_th<<<dim3(D_/32, D_/32), tb>>>(Wq + (size_t)l*D_*D_, wthh + wb,         wtlh + wb,         D_, D_);
        wsplit_th<<<dim3(D_/32, D_/32), tb>>>(Wk + (size_t)l*D_*D_, wthh + wb + MB1,   wtlh + wb + MB1,   D_, D_);
        wsplit_th<<<dim3(D_/32, D_/32), tb>>>(Wv + (size_t)l*D_*D_, wthh + wb + 2*MB1, wtlh + wb + 2*MB1, D_, D_);

        // fused QKV GEMM (fp16 2-pass)
        gemm_f16<<<gQKV, 256, F16SMEM>>>(xa, wthh + wb, wtlh + wb,
                                         bq_l, bk_l, bv_l,
                                         nullptr, nullptr, qh, kh, vh,
                                         M_, 3*D_, D_, QKV_MODE);
        vtrans<<<gVT, 256>>>(vh, vt);
        flash_attn<<<gFlash, 256, FSMEM>>>(qh, kh, vt, mask, oh, ol);

        // O-projection (bf16x3 for precision headroom)
        wsplit_t<<<dim3(D_/32, D_/32), tb>>>(Wo + (size_t)l*D_*D_, wth + wb + 3*MB1, wtl + wb + 3*MB1, D_, D_);
        gemm_bf3<<<gProj, 256, BF3SMEM>>>(oh, ol, wth + wb + 3*MB1, wtl + wb + 3*MB1,
                                          bo_l, r, M_, D_, D_);
        add_ln_split<<<M_, 256>>>(x, r, g1_l, be1_l, x, xa, 1);

        // FF (fp16 2-pass both)
        wsplit_th<<<dim3(FF_/32, D_/32), tb>>>(W1 + (size_t)l*D_*FF_, wthh + wb + 4*MB1, wtlh + wb + 4*MB1, D_, FF_);
        gemm_f16<<<gFF1, 256, F16SMEM>>>(xa, wthh + wb + 4*MB1, wtlh + wb + 4*MB1,
                                         b1_l, nullptr, nullptr,
                                         nullptr, ha, nullptr, nullptr, nullptr,
                                         M_, FF_, D_, RELU_MODE);
        wsplit_th<<<dim3(D_/32, FF_/32), tb>>>(W2 + (size_t)l*FF_*D_, wthh + wb + 8*MB1, wtlh + wb + 8*MB1, FF_, D_);
        gemm_f16<<<gProj, 256, F16SMEM>>>(ha, wthh + wb + 8*MB1, wtlh + wb + 8*MB1,
                                          b2_l, nullptr, nullptr,
                                          r, nullptr, nullptr, nullptr, nullptr,
                                          M_, D_, FF_, F32_MODE);

        float* dst = (l == L_-1) ? out : x;
        add_ln_split<<<M_, 256>>>(x, r, g2_l, be2_l, dst, xa, (l < L_-1) ? 1 : 0);
    }
}

// round 14
// speedup vs baseline: 4.5534x; 1.1216x over previous
#include <cuda_runtime.h>
#include <cuda_bf16.h>
#include <cuda_fp16.h>
#include <math.h>
#include <stdint.h>

// ---------------------------------------------------------------------------
// Problem constants
// ---------------------------------------------------------------------------
#define B_  2
#define S_  2048
#define D_  1024
#define H_  16
#define DK_ 64
#define FF_ 4096
#define L_  6
#define M_  (B_*S_)          // 4096 rows
#define BH_ (B_*H_)          // 32

// ---------------------------------------------------------------------------
// Scratch (device globals — no allocations allowed)
// ---------------------------------------------------------------------------
__device__ float g_x[M_*D_];                 // running activation (fp32)
__device__ float g_r[M_*D_];                 // residual branch (fp32)
__device__ float g_pe[B_*D_];

__device__ __half g_xa[M_*D_];               // x as fp16 (GEMM A input)
__device__ __half g_ha[M_*FF_];              // FF hidden as fp16
__device__ __half g_oa[M_*D_];               // attention output as fp16

__device__ __half g_qh[M_*D_];               // Q  [BH, S, 64] f16
__device__ __half g_kh[M_*D_];               // K  [BH, S, 64] f16
__device__ __half g_vh[M_*D_];               // V  [BH, S, 64] f16
__device__ __half g_vt[M_*D_];               // V^T [BH, 64, S] f16

// fp16 weights, transposed to [N,K]:
//   q:+0 k:+1M v:+2M (single) | o hi:+3M (lo in wtl+3M) | w1:+4M | w2:+8M
#define MB1 (1u<<20)
#define WL_ (12u*MB1)
__device__ __half g_wth[6*12*1024*1024];
__device__ __half g_wtl[6*12*1024*1024];

// ---------------------------------------------------------------------------
// PTX helpers
// ---------------------------------------------------------------------------
__device__ __forceinline__ uint32_t smem_u32(const void* p) {
    return (uint32_t)__cvta_generic_to_shared(p);
}
#define CP16(dst, src) \
    asm volatile("cp.async.cg.shared.global [%0], [%1], 16;" :: "r"(dst), "l"(src) : "memory")
#define CP_COMMIT() asm volatile("cp.async.commit_group;" ::: "memory")
#define CP_WAIT2()  asm volatile("cp.async.wait_group 2;" ::: "memory")
#define CP_WAIT1()  asm volatile("cp.async.wait_group 1;" ::: "memory")
#define CP_WAIT0()  asm volatile("cp.async.wait_group 0;" ::: "memory")

#define LDSM4(r, addr) \
    asm volatile("ldmatrix.sync.aligned.m8n8.x4.shared.b16 {%0,%1,%2,%3}, [%4];" \
        : "=r"((r)[0]), "=r"((r)[1]), "=r"((r)[2]), "=r"((r)[3]) : "r"(addr))

#define MMA16816H(c, a, b0, b1) \
    asm volatile("mma.sync.aligned.m16n8k16.row.col.f32.f16.f16.f32 " \
        "{%0,%1,%2,%3}, {%4,%5,%6,%7}, {%8,%9}, {%0,%1,%2,%3};" \
        : "+f"((c)[0]), "+f"((c)[1]), "+f"((c)[2]), "+f"((c)[3]) \
        : "r"((a)[0]), "r"((a)[1]), "r"((a)[2]), "r"((a)[3]), "r"(b0), "r"(b1))

__device__ __forceinline__ uint32_t exp2_f16x2(float lo, float hi) {
    uint32_t t, d;
    asm("cvt.rn.f16x2.f32 %0, %1, %2;" : "=r"(t) : "f"(hi), "f"(lo));
    asm("ex2.approx.f16x2 %0, %1;" : "=r"(d) : "r"(t));
    return d;
}
__device__ __forceinline__ float exp2f_fast(float x) {
    float y; asm("ex2.approx.f32 %0, %1;" : "=f"(y) : "f"(x)); return y;
}

// ---------------------------------------------------------------------------
// Shared GEMM geometry
// ---------------------------------------------------------------------------
#define KC      64
#define PITCHB  144
#define TILEB   (128*PITCHB)          // 18432
#define STG3F   (3*TILEB)             // 55296  (A, Bh, Bl)
#define F16SMEM (3*STG3F)             // 165888 (3 stages)

extern __shared__ char dynsmem[];

// ---------------------------------------------------------------------------
// fp16 GEMM (1- or 2-pass):  C = A[M,K] @ (Bh[+Bl])^T[N,K] + bias.
// modes: 0 = QKV f16 head layouts (N=3072, 1-pass); 1 = ReLU -> f16; 2 = fp32 C.
// 128x128 tile, 8 warps (64x32), K-chunk 64, 3-stage cp.async.
// ---------------------------------------------------------------------------
#define QKV_MODE  0
#define RELU_MODE 1
#define F32_MODE  2

__global__ __launch_bounds__(256, 1)
void gemm_f16(const __half* __restrict__ A,
              const __half* __restrict__ Bh, const __half* __restrict__ Bl,
              const float* __restrict__ bias0, const float* __restrict__ bias1,
              const float* __restrict__ bias2,
              float* __restrict__ C, __half* __restrict__ Hout,
              __half* __restrict__ Qout, __half* __restrict__ Kout,
              __half* __restrict__ Vout,
              int M, int N, int K, int mode, int twopass) {
    uint32_t sb = smem_u32(dynsmem);
    int tid = threadIdx.x, lane = tid & 31, wid = tid >> 5;
    int wm = wid >> 2, wn = wid & 3;
    int m0 = blockIdx.y * 128, n0 = blockIdx.x * 128;

    float acc[4][4][4];
    #pragma unroll
    for (int i = 0; i < 4; i++)
        #pragma unroll
        for (int j = 0; j < 4; j++)
            #pragma unroll
            for (int q = 0; q < 4; q++) acc[i][j][q] = 0.f;

    int seg = tid & 7, rb = tid >> 3;
    const __half* gsrc[3];
    gsrc[0] = A  + (size_t)m0 * K;
    gsrc[1] = Bh + (size_t)n0 * K;
    gsrc[2] = twopass ? (Bl + (size_t)n0 * K) : gsrc[1];

    int ntile = twopass ? 3 : 2;

    int lrow = lane & 15, lk16 = (lane >> 4) * 16;
    uint32_t aoff = (uint32_t)((wm*64 + lrow) * PITCHB) + lk16;
    uint32_t boff = (uint32_t)((wn*32 + lrow) * PITCHB) + lk16;

    int nc = K / KC;

    // prologue: chunks 0,1 -> stages 0,1
    for (int s2 = 0; s2 < 2; s2++) {
        for (int t = 0; t < ntile; t++)
            #pragma unroll
            for (int i = 0; i < 4; i++) {
                int row = rb + i * 32;
                CP16(sb + s2*STG3F + t*TILEB + (uint32_t)(row * PITCHB + seg * 16),
                     (const char*)(gsrc[t] + (size_t)row * K + s2*KC) + seg * 16);
            }
        CP_COMMIT();
    }

    for (int c = 0; c < nc; c++) {
        if (c + 2 < nc) {
            int ns = (c + 2) % 3;
            int k0 = (c + 2) * KC;
            for (int t = 0; t < ntile; t++)
                #pragma unroll
                for (int i = 0; i < 4; i++) {
                    int row = rb + i * 32;
                    CP16(sb + ns*STG3F + t*TILEB + (uint32_t)(row * PITCHB + seg * 16),
                         (const char*)(gsrc[t] + (size_t)row * K + k0) + seg * 16);
                }
            CP_COMMIT();
            CP_WAIT2();
        } else if (c + 1 < nc) {
            CP_WAIT1();
        } else {
            CP_WAIT0();
        }
        __syncthreads();

        uint32_t base = sb + (c % 3) * STG3F;
        #pragma unroll
        for (int kk = 0; kk < KC; kk += 16) {
            uint32_t a4[4][4], bb[2][4];
            #pragma unroll
            for (int mt = 0; mt < 4; mt++)
                LDSM4(a4[mt], base + aoff + mt*(16*PITCHB) + kk*2);
            #pragma unroll
            for (int nt2 = 0; nt2 < 2; nt2++)
                LDSM4(bb[nt2], base + TILEB + boff + nt2*(16*PITCHB) + kk*2);
            #pragma unroll
            for (int mt = 0; mt < 4; mt++)               // A*Bh
                #pragma unroll
                for (int nt = 0; nt < 4; nt++)
                    MMA16816H(acc[mt][nt], a4[mt], bb[nt>>1][nt&1], bb[nt>>1][2+(nt&1)]);
            if (twopass) {
                #pragma unroll
                for (int nt2 = 0; nt2 < 2; nt2++)        // reuse bb for Bl
                    LDSM4(bb[nt2], base + 2*TILEB + boff + nt2*(16*PITCHB) + kk*2);
                #pragma unroll
                for (int mt = 0; mt < 4; mt++)           // A*Bl
                    #pragma unroll
                    for (int nt = 0; nt < 4; nt++)
                        MMA16816H(acc[mt][nt], a4[mt], bb[nt>>1][nt&1], bb[nt>>1][2+(nt&1)]);
            }
        }
        __syncthreads();
    }

    int r0 = lane >> 2, cl = (lane & 3) * 2;
    int msel = n0 >> 10;
    const float* bias = (mode == QKV_MODE)
                      ? (msel == 0 ? bias0 : (msel == 1 ? bias1 : bias2))
                      : bias0;
    #pragma unroll
    for (int nt = 0; nt < 4; nt++) {
        int col  = n0 + wn*32 + nt*8 + cl;
        int ncol = (mode == QKV_MODE) ? (col & 1023) : col;
        float bx = bias[ncol], by = bias[ncol+1];
        #pragma unroll
        for (int mt = 0; mt < 4; mt++) {
            int row = m0 + wm*64 + mt*16 + r0;
            float v0 = acc[mt][nt][0] + bx, v1 = acc[mt][nt][1] + by;
            float v2 = acc[mt][nt][2] + bx, v3 = acc[mt][nt][3] + by;
            if (mode == F32_MODE) {
                *(float2*)(C + (size_t)row * N + col)       = make_float2(v0, v1);
                *(float2*)(C + (size_t)(row + 8) * N + col) = make_float2(v2, v3);
            } else if (mode == RELU_MODE) {
                v0 = fmaxf(v0, 0.f); v1 = fmaxf(v1, 0.f);
                v2 = fmaxf(v2, 0.f); v3 = fmaxf(v3, 0.f);
                *(__half2*)(Hout + (size_t)row * N + col)     = __floats2half2_rn(v0, v1);
                *(__half2*)(Hout + (size_t)(row+8) * N + col) = __floats2half2_rn(v2, v3);
            } else {                                     // QKV f16 head layouts
                int b = row >> 11, sidx = row & 2047;
                int hh = ncol >> 6, dd = ncol & 63;
                size_t base0 = (((size_t)b*H_ + hh)*S_ + sidx)*64 + dd;
                __half* dst = (msel == 0) ? Qout : ((msel == 1) ? Kout : Vout);
                *(__half2*)(dst + base0)        = __floats2half2_rn(v0, v1);
                *(__half2*)(dst + base0 + 8*64) = __floats2half2_rn(v2, v3);
            }
        }
    }
}

// ---------------------------------------------------------------------------
// V transpose: [BH,S,64] f16 -> [BH,64,S] f16, coalesced both sides.
// ---------------------------------------------------------------------------
__global__ __launch_bounds__(256)
void vtrans(const __half* __restrict__ vh, __half* __restrict__ vt) {
    __shared__ __half sh[64][65];
    int bh = blockIdx.y, s0 = blockIdx.x * 64;
    int tx = threadIdx.x & 31, ty = threadIdx.x >> 5;
    const __half* src = vh + ((size_t)bh*S_ + s0) * 64;
    #pragma unroll
    for (int i = 0; i < 8; i++) {
        int row = ty + i*8;
        __half2 v2 = *(const __half2*)(src + (size_t)row*64 + tx*2);
        sh[row][tx*2]   = __low2half(v2);
        sh[row][tx*2+1] = __high2half(v2);
    }
    __syncthreads();
    __half* dst = vt + (size_t)bh*64*S_ + s0;
    #pragma unroll
    for (int i = 0; i < 8; i++) {
        int dcol = ty + i*8;
        __half2 o = __halves2half2(sh[tx*2][dcol], sh[tx*2+1][dcol]);
        *(__half2*)(dst + (size_t)dcol*S_ + tx*2) = o;
    }
}

// ---------------------------------------------------------------------------
// Fused flash attention.  Q,K: [BH,S,64] f16.  Vt: [BH,64,S] f16.
// Output: fp16 O, layout [M, D].
// ---------------------------------------------------------------------------
#define FQP 144
#define QSZ (128*FQP)
#define FVP 272
#define VSZ (64*FVP)
#define MSZ 512
#define STG (QSZ + VSZ + MSZ)
#define FSMEM (QSZ + 2*STG)           // 91136

#define ONES_H2 0x3C003C00u

__global__ __launch_bounds__(256, 1)
void flash_attn(const __half* __restrict__ qh,
                const __half* __restrict__ kh,
                const __half* __restrict__ vt,
                const int* __restrict__ mask,
                __half* __restrict__ Oa) {
    uint32_t sb = smem_u32(dynsmem);
    int tid = threadIdx.x, lane = tid & 31, w = tid >> 5;
    int bh = blockIdx.y, q0 = blockIdx.x * 128;
    int b = bh >> 4, h = bh & 15;

    const __half* qg = qh + ((size_t)bh*S_ + q0) * 64;
    const __half* kg = kh + (size_t)bh*S_ * 64;
    const __half* vg = vt + (size_t)bh*64 * S_;
    const int* mg = mask + b*S_;

    int seg = tid & 7,  rb  = tid >> 3;
    int vseg = tid & 15, vrb = tid >> 4;

    #pragma unroll
    for (int i = 0; i < 4; i++) {
        int row = rb + i * 32;
        CP16(sb + (uint32_t)(row*FQP + seg*16),
             (const char*)(qg + (size_t)row*64) + seg*16);
        CP16(sb + QSZ + (uint32_t)(row*FQP + seg*16),
             (const char*)(kg + (size_t)row*64) + seg*16);
    }
    #pragma unroll
    for (int i = 0; i < 4; i++) {
        int row = vrb + i * 16;
        CP16(sb + QSZ + QSZ + (uint32_t)(row*FVP + vseg*16),
             (const char*)(vg + (size_t)row*S_) + vseg*16);
    }
    if (tid < 32) CP16(sb + QSZ + QSZ + VSZ + tid*16, (const char*)mg + tid*16);
    CP_COMMIT();

    uint32_t aoffQ = (uint32_t)((w*16 + (lane&15))*FQP) + (lane>>4)*16;
    uint32_t koff  = (uint32_t)((lane&15)*FQP) + (lane>>4)*16;
    uint32_t voff  = (uint32_t)((lane&15)*FVP) + (lane>>4)*16;

    float m0 = -INFINITY, m1 = -INFINITY;
    float oacc[8][4], lacc[4];
    #pragma unroll
    for (int i = 0; i < 8; i++)
        #pragma unroll
        for (int q = 0; q < 4; q++) oacc[i][q] = 0.f;
    #pragma unroll
    for (int q = 0; q < 4; q++) lacc[q] = 0.f;

    const float SCALE = 0.0450842201736734f;   // log2(e)/32
    const float MASKNEG = -4.5e7f;

    for (int j = 0; j < S_/128; j++) {
        if (j + 1 < S_/128) {
            uint32_t stg2 = sb + QSZ + ((j+1)&1)*STG;
            const char* ks = (const char*)(kg + (size_t)(j+1)*128*64);
            #pragma unroll
            for (int i = 0; i < 4; i++) {
                int row = rb + i * 32;
                CP16(stg2 + (uint32_t)(row*FQP + seg*16), ks + (size_t)row*128 + seg*16);
            }
            #pragma unroll
            for (int i = 0; i < 4; i++) {
                int row = vrb + i * 16;
                CP16(stg2 + QSZ + (uint32_t)(row*FVP + vseg*16),
                     (const char*)(vg + (size_t)row*S_ + (j+1)*128) + vseg*16);
            }
            if (tid < 32) CP16(stg2 + QSZ + VSZ + tid*16,
                               (const char*)(mg + (j+1)*128) + tid*16);
            CP_COMMIT();
            CP_WAIT1();
        } else {
            CP_WAIT0();
        }
        __syncthreads();

        uint32_t stg = sb + QSZ + (j&1)*STG;
        const int* msk = (const int*)(dynsmem + QSZ + (j&1)*STG + QSZ + VSZ);

        float sacc[16][4];
        #pragma unroll
        for (int i = 0; i < 16; i++)
            #pragma unroll
            for (int q = 0; q < 4; q++) sacc[i][q] = 0.f;

        #pragma unroll
        for (int kk = 0; kk < 64; kk += 16) {
            uint32_t af[4];
            LDSM4(af, sb + aoffQ + kk*2);
            #pragma unroll
            for (int nt2 = 0; nt2 < 8; nt2++) {
                uint32_t bf4[4];
                LDSM4(bf4, stg + koff + nt2*(16*FQP) + kk*2);
                MMA16816H(sacc[2*nt2],   af, bf4[0], bf4[2]);
                MMA16816H(sacc[2*nt2+1], af, bf4[1], bf4[3]);
            }
        }

        float rm0 = -INFINITY, rm1 = -INFINITY;
        #pragma unroll
        for (int nt = 0; nt < 16; nt++) {
            int col = nt*8 + (lane&3)*2;
            int2 mk = *(const int2*)(msk + col);
            float s0 = mk.x ? sacc[nt][0]*SCALE : MASKNEG;
            float s1 = mk.y ? sacc[nt][1]*SCALE : MASKNEG;
            float s2 = mk.x ? sacc[nt][2]*SCALE : MASKNEG;
            float s3 = mk.y ? sacc[nt][3]*SCALE : MASKNEG;
            sacc[nt][0] = s0; sacc[nt][1] = s1; sacc[nt][2] = s2; sacc[nt][3] = s3;
            rm0 = fmaxf(rm0, fmaxf(s0, s1));
            rm1 = fmaxf(rm1, fmaxf(s2, s3));
        }
        rm0 = fmaxf(rm0, __shfl_xor_sync(0xffffffffu, rm0, 1));
        rm0 = fmaxf(rm0, __shfl_xor_sync(0xffffffffu, rm0, 2));
        rm1 = fmaxf(rm1, __shfl_xor_sync(0xffffffffu, rm1, 1));
        rm1 = fmaxf(rm1, __shfl_xor_sync(0xffffffffu, rm1, 2));

        float mn0 = fmaxf(m0, rm0), mn1 = fmaxf(m1, rm1);
        float f0 = exp2f_fast(m0 - mn0), f1 = exp2f_fast(m1 - mn1);
        m0 = mn0; m1 = mn1;
        lacc[0] *= f0; lacc[1] *= f0; lacc[2] *= f1; lacc[3] *= f1;
        #pragma unroll
        for (int i = 0; i < 8; i++) {
            oacc[i][0] *= f0; oacc[i][1] *= f0;
            oacc[i][2] *= f1; oacc[i][3] *= f1;
        }

        #pragma unroll
        for (int t = 0; t < 8; t++) {
            uint32_t pa[4];
            pa[0] = exp2_f16x2(sacc[2*t][0] - m0,   sacc[2*t][1] - m0);
            pa[1] = exp2_f16x2(sacc[2*t][2] - m1,   sacc[2*t][3] - m1);
            pa[2] = exp2_f16x2(sacc[2*t+1][0] - m0, sacc[2*t+1][1] - m0);
            pa[3] = exp2_f16x2(sacc[2*t+1][2] - m1, sacc[2*t+1][3] - m1);
            MMA16816H(lacc, pa, ONES_H2, ONES_H2);
            #pragma unroll
            for (int nt2 = 0; nt2 < 4; nt2++) {
                uint32_t vf4[4];
                LDSM4(vf4, stg + QSZ + voff + nt2*(16*FVP) + t*32);
                MMA16816H(oacc[2*nt2],   pa, vf4[0], vf4[2]);
                MMA16816H(oacc[2*nt2+1], pa, vf4[1], vf4[3]);
            }
        }
        __syncthreads();
    }

    float il0 = 1.f / lacc[0], il1 = 1.f / lacc[2];
    int r0 = lane >> 2, cl = (lane & 3) * 2;
    int qrow = q0 + w*16 + r0;
    size_t gr0 = (size_t)(b*S_ + qrow) * D_;
    size_t gr1 = gr0 + (size_t)8 * D_;
    #pragma unroll
    for (int nt2 = 0; nt2 < 8; nt2++) {
        int col = h*64 + nt2*8 + cl;
        *(__half2*)(Oa + gr0 + col) =
            __floats2half2_rn(oacc[nt2][0]*il0, oacc[nt2][1]*il0);
        *(__half2*)(Oa + gr1 + col) =
            __floats2half2_rn(oacc[nt2][2]*il1, oacc[nt2][3]*il1);
    }
}

// ---------------------------------------------------------------------------
// Weight transpose kernels:  W fp32 [K,N] -> [N,K] fp16 (single or split pair)
// ---------------------------------------------------------------------------
__global__ void wsplit_th(const float* __restrict__ W,
                          __half* __restrict__ th,
                          __half* __restrict__ tl, int K, int N) {
    __shared__ float sh[32][33];
    int n0 = blockIdx.x * 32, k0 = blockIdx.y * 32;
    int tx = threadIdx.x, ty = threadIdx.y;
    #pragma unroll
    for (int i = 0; i < 4; i++)
        sh[ty + i*8][tx] = W[(size_t)(k0 + ty + i*8) * N + n0 + tx];
    __syncthreads();
    #pragma unroll
    for (int i = 0; i < 4; i++) {
        int n = n0 + ty + i*8;
        float v = sh[tx][ty + i*8];
        __half hb = __float2half_rn(v);
        th[(size_t)n * K + k0 + tx] = hb;
        tl[(size_t)n * K + k0 + tx] = __float2half_rn(v - __half2float(hb));
    }
}

__global__ void wtrans_h1(const float* __restrict__ W,
                          __half* __restrict__ th, int K, int N) {
    __shared__ float sh[32][33];
    int n0 = blockIdx.x * 32, k0 = blockIdx.y * 32;
    int tx = threadIdx.x, ty = threadIdx.y;
    #pragma unroll
    for (int i = 0; i < 4; i++)
        sh[ty + i*8][tx] = W[(size_t)(k0 + ty + i*8) * N + n0 + tx];
    __syncthreads();
    #pragma unroll
    for (int i = 0; i < 4; i++) {
        int n = n0 + ty + i*8;
        th[(size_t)n * K + k0 + tx] = __float2half_rn(sh[tx][ty + i*8]);
    }
}

// ---------------------------------------------------------------------------
// Reductions
// ---------------------------------------------------------------------------
__device__ __forceinline__ float warpSum(float v) {
    #pragma unroll
    for (int o = 16; o; o >>= 1) v += __shfl_xor_sync(0xffffffffu, v, o);
    return v;
}
__device__ __forceinline__ float blockSum(float v, float* sh) {
    int tid = threadIdx.x, lane = tid & 31, w = tid >> 5;
    v = warpSum(v);
    if (lane == 0) sh[w] = v;
    __syncthreads();
    float t = sh[0];
    #pragma unroll
    for (int i = 1; i < 8; i++) t += sh[i];
    __syncthreads();
    return t;
}

// ---------------------------------------------------------------------------
// PE + fused embed (writes x fp32 and fp16 copy)
// ---------------------------------------------------------------------------
__global__ void pe_kernel(float* __restrict__ pe) {
    int idx = blockIdx.x * blockDim.x + threadIdx.x;
    if (idx >= B_*D_) return;
    int b = idx / D_, d = idx % D_;
    int i = d >> 1;
    double c = -log(10000.0) / (double)D_;
    float divf = (float)exp((double)(2*i) * c);
    float ang  = (float)b / divf;
    double ad  = (double)ang;
    pe[idx] = (d & 1) ? (float)cos(ad) : (float)sin(ad);
}

__global__ void embed_split(const int* __restrict__ src,
                            const float* __restrict__ emb,
                            const float* __restrict__ pe,
                            float* __restrict__ x,
                            __half* __restrict__ xa) {
    int idx = blockIdx.x * blockDim.x + threadIdx.x;
    if (idx >= M_*D_) return;
    int d  = idx & (D_-1);
    int bs = idx >> 10;
    int b  = bs >> 11;
    float v = emb[(size_t)src[bs]*D_ + d] + pe[b*D_ + d];
    x[idx] = v;
    xa[idx] = __float2half_rn(v);
}

// ---------------------------------------------------------------------------
// out = LayerNorm(x + r) * g + be, with fused fp16 copy
// ---------------------------------------------------------------------------
__global__ __launch_bounds__(256)
void add_ln_split(const float* __restrict__ x, const float* __restrict__ rr,
                  const float* __restrict__ g, const float* __restrict__ be,
                  float* __restrict__ out, __half* __restrict__ xa,
                  int do_split) {
    __shared__ float sh[8];
    int m = blockIdx.x, tid = threadIdx.x;
    float4 v = *(const float4*)(x + (size_t)m*D_ + tid*4);
    float4 rv = *(const float4*)(rr + (size_t)m*D_ + tid*4);
    v.x += rv.x; v.y += rv.y; v.z += rv.z; v.w += rv.w;
    float s = v.x + v.y + v.z + v.w;
    s = blockSum(s, sh);
    float mean = s * (1.0f / D_);
    float d0 = v.x - mean, d1 = v.y - mean, d2 = v.z - mean, d3 = v.w - mean;
    float sq = d0*d0 + d1*d1 + d2*d2 + d3*d3;
    sq = blockSum(sq, sh);
    float var = sq * (1.0f / D_);
    float rstd = rsqrtf(var + 1e-5f);
    float4 gg = *(const float4*)(g + tid*4);
    float4 bb = *(const float4*)(be + tid*4);
    float4 o;
    o.x = d0*rstd*gg.x + bb.x;
    o.y = d1*rstd*gg.y + bb.y;
    o.z = d2*rstd*gg.z + bb.z;
    o.w = d3*rstd*gg.w + bb.w;
    *(float4*)(out + (size_t)m*D_ + tid*4) = o;
    if (do_split) {
        size_t p = (size_t)m*D_ + tid*4;
        *(__half2*)(xa + p)     = __floats2half2_rn(o.x, o.y);
        *(__half2*)(xa + p + 2) = __floats2half2_rn(o.z, o.w);
    }
}

// ---------------------------------------------------------------------------
// Launch
// ---------------------------------------------------------------------------
extern "C" void kernel_launch(void* const* d_in, const int* in_sizes, int n_in,
                              void* d_out, int out_size) {
    const int*   src  = (const int*)  d_in[0];
    const int*   mask = (const int*)  d_in[1];
    const float* emb  = (const float*)d_in[2];
    const float* Wq   = (const float*)d_in[3];
    const float* bq   = (const float*)d_in[4];
    const float* Wk   = (const float*)d_in[5];
    const float* bk   = (const float*)d_in[6];
    const float* Wv   = (const float*)d_in[7];
    const float* bv   = (const float*)d_in[8];
    const float* Wo   = (const float*)d_in[9];
    const float* bo   = (const float*)d_in[10];
    const float* W1   = (const float*)d_in[11];
    const float* b1   = (const float*)d_in[12];
    const float* W2   = (const float*)d_in[13];
    const float* b2   = (const float*)d_in[14];
    const float* g1   = (const float*)d_in[15];
    const float* be1  = (const float*)d_in[16];
    const float* g2   = (const float*)d_in[17];
    const float* be2  = (const float*)d_in[18];
    float* out = (float*)d_out;

    float *x, *r, *pe;
    __half *wth, *wtl, *xa, *ha, *oa, *qh, *kh, *vh, *vt;
    cudaGetSymbolAddress((void**)&x,  g_x);
    cudaGetSymbolAddress((void**)&r,  g_r);
    cudaGetSymbolAddress((void**)&pe, g_pe);
    cudaGetSymbolAddress((void**)&wth, g_wth);
    cudaGetSymbolAddress((void**)&wtl, g_wtl);
    cudaGetSymbolAddress((void**)&xa, g_xa);
    cudaGetSymbolAddress((void**)&ha, g_ha);
    cudaGetSymbolAddress((void**)&oa, g_oa);
    cudaGetSymbolAddress((void**)&qh, g_qh);
    cudaGetSymbolAddress((void**)&kh, g_kh);
    cudaGetSymbolAddress((void**)&vh, g_vh);
    cudaGetSymbolAddress((void**)&vt, g_vt);

    cudaFuncSetAttribute(gemm_f16,   cudaFuncAttributeMaxDynamicSharedMemorySize, F16SMEM);
    cudaFuncSetAttribute(flash_attn, cudaFuncAttributeMaxDynamicSharedMemorySize, FSMEM);

    pe_kernel<<<(B_*D_ + 255)/256, 256>>>(pe);
    embed_split<<<(M_*D_ + 255)/256, 256>>>(src, emb, pe, x, xa);

    dim3 tb(32, 8);
    dim3 gQKV (3*D_/128, M_/128);
    dim3 gProj(D_/128,   M_/128);
    dim3 gFF1 (FF_/128,  M_/128);
    dim3 gFlash(S_/128, BH_);
    dim3 gVT  (S_/64, BH_);

    for (int l = 0; l < L_; l++) {
        size_t wb = (size_t)l * WL_;
        const float* bq_l = bq + (size_t)l*D_;
        const float* bk_l = bk + (size_t)l*D_;
        const float* bv_l = bv + (size_t)l*D_;
        const float* bo_l = bo + (size_t)l*D_;
        const float* b1_l = b1 + (size_t)l*FF_;
        const float* b2_l = b2 + (size_t)l*D_;
        const float* g1_l = g1 + (size_t)l*D_;
        const float* be1_l= be1+ (size_t)l*D_;
        const float* g2_l = g2 + (size_t)l*D_;
        const float* be2_l= be2+ (size_t)l*D_;

        // QKV weights -> single fp16 transpose (1-pass GEMM)
        wtrans_h1<<<dim3(D_/32, D_/32), tb>>>(Wq + (size_t)l*D_*D_, wth + wb,         D_, D_);
        wtrans_h1<<<dim3(D_/32, D_/32), tb>>>(Wk + (size_t)l*D_*D_, wth + wb + MB1,   D_, D_);
        wtrans_h1<<<dim3(D_/32, D_/32), tb>>>(Wv + (size_t)l*D_*D_, wth + wb + 2*MB1, D_, D_);

        // fused QKV GEMM (fp16 1-pass), outputs f16 head layouts
        gemm_f16<<<gQKV, 256, F16SMEM>>>(xa, wth + wb, nullptr,
                                         bq_l, bk_l, bv_l,
                                         nullptr, nullptr, qh, kh, vh,
                                         M_, 3*D_, D_, QKV_MODE, 0);
        vtrans<<<gVT, 256>>>(vh, vt);
        flash_attn<<<gFlash, 256, FSMEM>>>(qh, kh, vt, mask, oa);

        // O-projection (fp16 2-pass)
        wsplit_th<<<dim3(D_/32, D_/32), tb>>>(Wo + (size_t)l*D_*D_,
                                              wth + wb + 3*MB1, wtl + wb + 3*MB1, D_, D_);
        gemm_f16<<<gProj, 256, F16SMEM>>>(oa, wth + wb + 3*MB1, wtl + wb + 3*MB1,
                                          bo_l, nullptr, nullptr,
                                          r, nullptr, nullptr, nullptr, nullptr,
                                          M_, D_, D_, F32_MODE, 1);
        add_ln_split<<<M_, 256>>>(x, r, g1_l, be1_l, x, xa, 1);

        // FF (fp16 2-pass both)
        wsplit_th<<<dim3(FF_/32, D_/32), tb>>>(W1 + (size_t)l*D_*FF_,
                                               wth + wb + 4*MB1, wtl + wb + 4*MB1, D_, FF_);
        gemm_f16<<<gFF1, 256, F16SMEM>>>(xa, wth + wb + 4*MB1, wtl + wb + 4*MB1,
                                         b1_l, nullptr, nullptr,
                                         nullptr, ha, nullptr, nullptr, nullptr,
                                         M_, FF_, D_, RELU_MODE, 1);
        wsplit_th<<<dim3(D_/32, FF_/32), tb>>>(W2 + (size_t)l*FF_*D_,
                                               wth + wb + 8*MB1, wtl + wb + 8*MB1, FF_, D_);
        gemm_f16<<<gProj, 256, F16SMEM>>>(ha, wth + wb + 8*MB1, wtl + wb + 8*MB1,
                                          b2_l, nullptr, nullptr,
                                          r, nullptr, nullptr, nullptr, nullptr,
                                          M_, D_, FF_, F32_MODE, 1);

        float* dst = (l == L_-1) ? out : x;
        add_ln_split<<<M_, 256>>>(x, r, g2_l, be2_l, dst, xa, (l < L_-1) ? 1 : 0);
    }
}

// round 15
// speedup vs baseline: 5.1488x; 1.1308x over previous
#include <cuda_runtime.h>
#include <cuda_bf16.h>
#include <cuda_fp16.h>
#include <math.h>
#include <stdint.h>

// ---------------------------------------------------------------------------
// Problem constants
// ---------------------------------------------------------------------------
#define B_  2
#define S_  2048
#define D_  1024
#define H_  16
#define DK_ 64
#define FF_ 4096
#define L_  6
#define M_  (B_*S_)          // 4096 rows
#define BH_ (B_*H_)          // 32

// ---------------------------------------------------------------------------
// Scratch (device globals — no allocations allowed)
// ---------------------------------------------------------------------------
__device__ float g_x[M_*D_];                 // running activation (fp32)
__device__ float g_r[M_*D_];                 // residual branch (fp32)
__device__ float g_pe[B_*D_];

__device__ __half g_xa[M_*D_];               // x as fp16 (GEMM A input)
__device__ __half g_ha[M_*FF_];              // FF hidden as fp16
__device__ __half g_oa[M_*D_];               // attention output as fp16

__device__ __half g_qh[M_*D_];               // Q  [BH, S, 64] f16
__device__ __half g_kh[M_*D_];               // K  [BH, S, 64] f16
__device__ __half g_vh[M_*D_];               // V  [BH, S, 64] f16
__device__ __half g_vt[M_*D_];               // V^T [BH, 64, S] f16

// fp16 weights, transposed to [N,K]:
//   q:+0 k:+1M v:+2M (single) | o hi:+3M (lo in wtl+3M) | w1:+4M (single) | w2:+8M
#define MB1 (1u<<20)
#define WL_ (12u*MB1)
__device__ __half g_wth[6*12*1024*1024];
__device__ __half g_wtl[6*12*1024*1024];

// ---------------------------------------------------------------------------
// PTX helpers
// ---------------------------------------------------------------------------
__device__ __forceinline__ uint32_t smem_u32(const void* p) {
    return (uint32_t)__cvta_generic_to_shared(p);
}
#define CP16(dst, src) \
    asm volatile("cp.async.cg.shared.global [%0], [%1], 16;" :: "r"(dst), "l"(src) : "memory")
#define CP_COMMIT() asm volatile("cp.async.commit_group;" ::: "memory")
#define CP_WAIT2()  asm volatile("cp.async.wait_group 2;" ::: "memory")
#define CP_WAIT1()  asm volatile("cp.async.wait_group 1;" ::: "memory")
#define CP_WAIT0()  asm volatile("cp.async.wait_group 0;" ::: "memory")

#define LDSM4(r, addr) \
    asm volatile("ldmatrix.sync.aligned.m8n8.x4.shared.b16 {%0,%1,%2,%3}, [%4];" \
        : "=r"((r)[0]), "=r"((r)[1]), "=r"((r)[2]), "=r"((r)[3]) : "r"(addr))

#define MMA16816H(c, a, b0, b1) \
    asm volatile("mma.sync.aligned.m16n8k16.row.col.f32.f16.f16.f32 " \
        "{%0,%1,%2,%3}, {%4,%5,%6,%7}, {%8,%9}, {%0,%1,%2,%3};" \
        : "+f"((c)[0]), "+f"((c)[1]), "+f"((c)[2]), "+f"((c)[3]) \
        : "r"((a)[0]), "r"((a)[1]), "r"((a)[2]), "r"((a)[3]), "r"(b0), "r"(b1))

__device__ __forceinline__ uint32_t exp2_f16x2(float lo, float hi) {
    uint32_t t, d;
    asm("cvt.rn.f16x2.f32 %0, %1, %2;" : "=r"(t) : "f"(hi), "f"(lo));
    asm("ex2.approx.f16x2 %0, %1;" : "=r"(d) : "r"(t));
    return d;
}
__device__ __forceinline__ float exp2f_fast(float x) {
    float y; asm("ex2.approx.f32 %0, %1;" : "=f"(y) : "f"(x)); return y;
}

// ---------------------------------------------------------------------------
// Shared GEMM geometry
// ---------------------------------------------------------------------------
#define KC      64
#define PITCHB  144
#define TILEB   (128*PITCHB)          // 18432
#define STG3F   (3*TILEB)             // 55296  (A, Bh, Bl)
#define F16SMEM (3*STG3F)             // 165888 (3 stages)

extern __shared__ char dynsmem[];

// ---------------------------------------------------------------------------
// fp16 GEMM (1- or 2-pass):  C = A[M,K] @ (Bh[+Bl])^T[N,K] + bias.
// modes: 0 = QKV f16 head layouts (N=3072); 1 = ReLU -> f16; 2 = fp32 C.
// 128x128 tile, 8 warps (64x32), K-chunk 64, 3-stage cp.async.
// ---------------------------------------------------------------------------
#define QKV_MODE  0
#define RELU_MODE 1
#define F32_MODE  2

__global__ __launch_bounds__(256, 1)
void gemm_f16(const __half* __restrict__ A,
              const __half* __restrict__ Bh, const __half* __restrict__ Bl,
              const float* __restrict__ bias0, const float* __restrict__ bias1,
              const float* __restrict__ bias2,
              float* __restrict__ C, __half* __restrict__ Hout,
              __half* __restrict__ Qout, __half* __restrict__ Kout,
              __half* __restrict__ Vout,
              int M, int N, int K, int mode, int twopass) {
    uint32_t sb = smem_u32(dynsmem);
    int tid = threadIdx.x, lane = tid & 31, wid = tid >> 5;
    int wm = wid >> 2, wn = wid & 3;
    int m0 = blockIdx.y * 128, n0 = blockIdx.x * 128;

    float acc[4][4][4];
    #pragma unroll
    for (int i = 0; i < 4; i++)
        #pragma unroll
        for (int j = 0; j < 4; j++)
            #pragma unroll
            for (int q = 0; q < 4; q++) acc[i][j][q] = 0.f;

    int seg = tid & 7, rb = tid >> 3;
    const __half* gsrc[3];
    gsrc[0] = A  + (size_t)m0 * K;
    gsrc[1] = Bh + (size_t)n0 * K;
    gsrc[2] = twopass ? (Bl + (size_t)n0 * K) : gsrc[1];

    int ntile = twopass ? 3 : 2;

    int lrow = lane & 15, lk16 = (lane >> 4) * 16;
    uint32_t aoff = (uint32_t)((wm*64 + lrow) * PITCHB) + lk16;
    uint32_t boff = (uint32_t)((wn*32 + lrow) * PITCHB) + lk16;

    int nc = K / KC;

    // prologue: chunks 0,1 -> stages 0,1
    for (int s2 = 0; s2 < 2; s2++) {
        for (int t = 0; t < ntile; t++)
            #pragma unroll
            for (int i = 0; i < 4; i++) {
                int row = rb + i * 32;
                CP16(sb + s2*STG3F + t*TILEB + (uint32_t)(row * PITCHB + seg * 16),
                     (const char*)(gsrc[t] + (size_t)row * K + s2*KC) + seg * 16);
            }
        CP_COMMIT();
    }

    for (int c = 0; c < nc; c++) {
        if (c + 2 < nc) {
            int ns = (c + 2) % 3;
            int k0 = (c + 2) * KC;
            for (int t = 0; t < ntile; t++)
                #pragma unroll
                for (int i = 0; i < 4; i++) {
                    int row = rb + i * 32;
                    CP16(sb + ns*STG3F + t*TILEB + (uint32_t)(row * PITCHB + seg * 16),
                         (const char*)(gsrc[t] + (size_t)row * K + k0) + seg * 16);
                }
            CP_COMMIT();
            CP_WAIT2();
        } else if (c + 1 < nc) {
            CP_WAIT1();
        } else {
            CP_WAIT0();
        }
        __syncthreads();

        uint32_t base = sb + (c % 3) * STG3F;
        #pragma unroll
        for (int kk = 0; kk < KC; kk += 16) {
            uint32_t a4[4][4], bb[2][4];
            #pragma unroll
            for (int mt = 0; mt < 4; mt++)
                LDSM4(a4[mt], base + aoff + mt*(16*PITCHB) + kk*2);
            #pragma unroll
            for (int nt2 = 0; nt2 < 2; nt2++)
                LDSM4(bb[nt2], base + TILEB + boff + nt2*(16*PITCHB) + kk*2);
            #pragma unroll
            for (int mt = 0; mt < 4; mt++)               // A*Bh
                #pragma unroll
                for (int nt = 0; nt < 4; nt++)
                    MMA16816H(acc[mt][nt], a4[mt], bb[nt>>1][nt&1], bb[nt>>1][2+(nt&1)]);
            if (twopass) {
                #pragma unroll
                for (int nt2 = 0; nt2 < 2; nt2++)        // reuse bb for Bl
                    LDSM4(bb[nt2], base + 2*TILEB + boff + nt2*(16*PITCHB) + kk*2);
                #pragma unroll
                for (int mt = 0; mt < 4; mt++)           // A*Bl
                    #pragma unroll
                    for (int nt = 0; nt < 4; nt++)
                        MMA16816H(acc[mt][nt], a4[mt], bb[nt>>1][nt&1], bb[nt>>1][2+(nt&1)]);
            }
        }
        __syncthreads();
    }

    int r0 = lane >> 2, cl = (lane & 3) * 2;
    int msel = n0 >> 10;
    const float* bias = (mode == QKV_MODE)
                      ? (msel == 0 ? bias0 : (msel == 1 ? bias1 : bias2))
                      : bias0;
    #pragma unroll
    for (int nt = 0; nt < 4; nt++) {
        int col  = n0 + wn*32 + nt*8 + cl;
        int ncol = (mode == QKV_MODE) ? (col & 1023) : col;
        float bx = bias[ncol], by = bias[ncol+1];
        #pragma unroll
        for (int mt = 0; mt < 4; mt++) {
            int row = m0 + wm*64 + mt*16 + r0;
            float v0 = acc[mt][nt][0] + bx, v1 = acc[mt][nt][1] + by;
            float v2 = acc[mt][nt][2] + bx, v3 = acc[mt][nt][3] + by;
            if (mode == F32_MODE) {
                *(float2*)(C + (size_t)row * N + col)       = make_float2(v0, v1);
                *(float2*)(C + (size_t)(row + 8) * N + col) = make_float2(v2, v3);
            } else if (mode == RELU_MODE) {
                v0 = fmaxf(v0, 0.f); v1 = fmaxf(v1, 0.f);
                v2 = fmaxf(v2, 0.f); v3 = fmaxf(v3, 0.f);
                *(__half2*)(Hout + (size_t)row * N + col)     = __floats2half2_rn(v0, v1);
                *(__half2*)(Hout + (size_t)(row+8) * N + col) = __floats2half2_rn(v2, v3);
            } else {                                     // QKV f16 head layouts
                int b = row >> 11, sidx = row & 2047;
                int hh = ncol >> 6, dd = ncol & 63;
                size_t base0 = (((size_t)b*H_ + hh)*S_ + sidx)*64 + dd;
                __half* dst = (msel == 0) ? Qout : ((msel == 1) ? Kout : Vout);
                *(__half2*)(dst + base0)        = __floats2half2_rn(v0, v1);
                *(__half2*)(dst + base0 + 8*64) = __floats2half2_rn(v2, v3);
            }
        }
    }
}

// ---------------------------------------------------------------------------
// V transpose: [BH,S,64] f16 -> [BH,64,S] f16, coalesced both sides.
// ---------------------------------------------------------------------------
__global__ __launch_bounds__(256)
void vtrans(const __half* __restrict__ vh, __half* __restrict__ vt) {
    __shared__ __half sh[64][65];
    int bh = blockIdx.y, s0 = blockIdx.x * 64;
    int tx = threadIdx.x & 31, ty = threadIdx.x >> 5;
    const __half* src = vh + ((size_t)bh*S_ + s0) * 64;
    #pragma unroll
    for (int i = 0; i < 8; i++) {
        int row = ty + i*8;
        __half2 v2 = *(const __half2*)(src + (size_t)row*64 + tx*2);
        sh[row][tx*2]   = __low2half(v2);
        sh[row][tx*2+1] = __high2half(v2);
    }
    __syncthreads();
    __half* dst = vt + (size_t)bh*64*S_ + s0;
    #pragma unroll
    for (int i = 0; i < 8; i++) {
        int dcol = ty + i*8;
        __half2 o = __halves2half2(sh[tx*2][dcol], sh[tx*2+1][dcol]);
        *(__half2*)(dst + (size_t)dcol*S_ + tx*2) = o;
    }
}

// ---------------------------------------------------------------------------
// Fused flash attention.  Q,K: [BH,S,64] f16.  Vt: [BH,64,S] f16.
// Output: fp16 O, layout [M, D].
// ---------------------------------------------------------------------------
#define FQP 144
#define QSZ (128*FQP)
#define FVP 272
#define VSZ (64*FVP)
#define MSZ 512
#define STG (QSZ + VSZ + MSZ)
#define FSMEM (QSZ + 2*STG)           // 91136

#define ONES_H2 0x3C003C00u

__global__ __launch_bounds__(256, 1)
void flash_attn(const __half* __restrict__ qh,
                const __half* __restrict__ kh,
                const __half* __restrict__ vt,
                const int* __restrict__ mask,
                __half* __restrict__ Oa) {
    uint32_t sb = smem_u32(dynsmem);
    int tid = threadIdx.x, lane = tid & 31, w = tid >> 5;
    int bh = blockIdx.y, q0 = blockIdx.x * 128;
    int b = bh >> 4, h = bh & 15;

    const __half* qg = qh + ((size_t)bh*S_ + q0) * 64;
    const __half* kg = kh + (size_t)bh*S_ * 64;
    const __half* vg = vt + (size_t)bh*64 * S_;
    const int* mg = mask + b*S_;

    int seg = tid & 7,  rb  = tid >> 3;
    int vseg = tid & 15, vrb = tid >> 4;

    #pragma unroll
    for (int i = 0; i < 4; i++) {
        int row = rb + i * 32;
        CP16(sb + (uint32_t)(row*FQP + seg*16),
             (const char*)(qg + (size_t)row*64) + seg*16);
        CP16(sb + QSZ + (uint32_t)(row*FQP + seg*16),
             (const char*)(kg + (size_t)row*64) + seg*16);
    }
    #pragma unroll
    for (int i = 0; i < 4; i++) {
        int row = vrb + i * 16;
        CP16(sb + QSZ + QSZ + (uint32_t)(row*FVP + vseg*16),
             (const char*)(vg + (size_t)row*S_) + vseg*16);
    }
    if (tid < 32) CP16(sb + QSZ + QSZ + VSZ + tid*16, (const char*)mg + tid*16);
    CP_COMMIT();

    uint32_t aoffQ = (uint32_t)((w*16 + (lane&15))*FQP) + (lane>>4)*16;
    uint32_t koff  = (uint32_t)((lane&15)*FQP) + (lane>>4)*16;
    uint32_t voff  = (uint32_t)((lane&15)*FVP) + (lane>>4)*16;

    float m0 = -INFINITY, m1 = -INFINITY;
    float oacc[8][4], lacc[4];
    #pragma unroll
    for (int i = 0; i < 8; i++)
        #pragma unroll
        for (int q = 0; q < 4; q++) oacc[i][q] = 0.f;
    #pragma unroll
    for (int q = 0; q < 4; q++) lacc[q] = 0.f;

    const float SCALE = 0.0450842201736734f;   // log2(e)/32
    const float MASKNEG = -4.5e7f;

    for (int j = 0; j < S_/128; j++) {
        if (j + 1 < S_/128) {
            uint32_t stg2 = sb + QSZ + ((j+1)&1)*STG;
            const char* ks = (const char*)(kg + (size_t)(j+1)*128*64);
            #pragma unroll
            for (int i = 0; i < 4; i++) {
                int row = rb + i * 32;
                CP16(stg2 + (uint32_t)(row*FQP + seg*16), ks + (size_t)row*128 + seg*16);
            }
            #pragma unroll
            for (int i = 0; i < 4; i++) {
                int row = vrb + i * 16;
                CP16(stg2 + QSZ + (uint32_t)(row*FVP + vseg*16),
                     (const char*)(vg + (size_t)row*S_ + (j+1)*128) + vseg*16);
            }
            if (tid < 32) CP16(stg2 + QSZ + VSZ + tid*16,
                               (const char*)(mg + (j+1)*128) + tid*16);
            CP_COMMIT();
            CP_WAIT1();
        } else {
            CP_WAIT0();
        }
        __syncthreads();

        uint32_t stg = sb + QSZ + (j&1)*STG;
        const int* msk = (const int*)(dynsmem + QSZ + (j&1)*STG + QSZ + VSZ);

        float sacc[16][4];
        #pragma unroll
        for (int i = 0; i < 16; i++)
            #pragma unroll
            for (int q = 0; q < 4; q++) sacc[i][q] = 0.f;

        #pragma unroll
        for (int kk = 0; kk < 64; kk += 16) {
            uint32_t af[4];
            LDSM4(af, sb + aoffQ + kk*2);
            #pragma unroll
            for (int nt2 = 0; nt2 < 8; nt2++) {
                uint32_t bf4[4];
                LDSM4(bf4, stg + koff + nt2*(16*FQP) + kk*2);
                MMA16816H(sacc[2*nt2],   af, bf4[0], bf4[2]);
                MMA16816H(sacc[2*nt2+1], af, bf4[1], bf4[3]);
            }
        }

        float rm0 = -INFINITY, rm1 = -INFINITY;
        #pragma unroll
        for (int nt = 0; nt < 16; nt++) {
            int col = nt*8 + (lane&3)*2;
            int2 mk = *(const int2*)(msk + col);
            float s0 = mk.x ? sacc[nt][0]*SCALE : MASKNEG;
            float s1 = mk.y ? sacc[nt][1]*SCALE : MASKNEG;
            float s2 = mk.x ? sacc[nt][2]*SCALE : MASKNEG;
            float s3 = mk.y ? sacc[nt][3]*SCALE : MASKNEG;
            sacc[nt][0] = s0; sacc[nt][1] = s1; sacc[nt][2] = s2; sacc[nt][3] = s3;
            rm0 = fmaxf(rm0, fmaxf(s0, s1));
            rm1 = fmaxf(rm1, fmaxf(s2, s3));
        }
        rm0 = fmaxf(rm0, __shfl_xor_sync(0xffffffffu, rm0, 1));
        rm0 = fmaxf(rm0, __shfl_xor_sync(0xffffffffu, rm0, 2));
        rm1 = fmaxf(rm1, __shfl_xor_sync(0xffffffffu, rm1, 1));
        rm1 = fmaxf(rm1, __shfl_xor_sync(0xffffffffu, rm1, 2));

        float mn0 = fmaxf(m0, rm0), mn1 = fmaxf(m1, rm1);
        float f0 = exp2f_fast(m0 - mn0), f1 = exp2f_fast(m1 - mn1);
        m0 = mn0; m1 = mn1;
        lacc[0] *= f0; lacc[1] *= f0; lacc[2] *= f1; lacc[3] *= f1;
        #pragma unroll
        for (int i = 0; i < 8; i++) {
            oacc[i][0] *= f0; oacc[i][1] *= f0;
            oacc[i][2] *= f1; oacc[i][3] *= f1;
        }

        #pragma unroll
        for (int t = 0; t < 8; t++) {
            uint32_t pa[4];
            pa[0] = exp2_f16x2(sacc[2*t][0] - m0,   sacc[2*t][1] - m0);
            pa[1] = exp2_f16x2(sacc[2*t][2] - m1,   sacc[2*t][3] - m1);
            pa[2] = exp2_f16x2(sacc[2*t+1][0] - m0, sacc[2*t+1][1] - m0);
            pa[3] = exp2_f16x2(sacc[2*t+1][2] - m1, sacc[2*t+1][3] - m1);
            MMA16816H(lacc, pa, ONES_H2, ONES_H2);
            #pragma unroll
            for (int nt2 = 0; nt2 < 4; nt2++) {
                uint32_t vf4[4];
                LDSM4(vf4, stg + QSZ + voff + nt2*(16*FVP) + t*32);
                MMA16816H(oacc[2*nt2],   pa, vf4[0], vf4[2]);
                MMA16816H(oacc[2*nt2+1], pa, vf4[1], vf4[3]);
            }
        }
        __syncthreads();
    }

    float il0 = 1.f / lacc[0], il1 = 1.f / lacc[2];
    int r0 = lane >> 2, cl = (lane & 3) * 2;
    int qrow = q0 + w*16 + r0;
    size_t gr0 = (size_t)(b*S_ + qrow) * D_;
    size_t gr1 = gr0 + (size_t)8 * D_;
    #pragma unroll
    for (int nt2 = 0; nt2 < 8; nt2++) {
        int col = h*64 + nt2*8 + cl;
        *(__half2*)(Oa + gr0 + col) =
            __floats2half2_rn(oacc[nt2][0]*il0, oacc[nt2][1]*il0);
        *(__half2*)(Oa + gr1 + col) =
            __floats2half2_rn(oacc[nt2][2]*il1, oacc[nt2][3]*il1);
    }
}

// ---------------------------------------------------------------------------
// Weight transpose kernels:  W fp32 [K,N] -> [N,K] fp16 (single or split pair)
// ---------------------------------------------------------------------------
__global__ void wsplit_th(const float* __restrict__ W,
                          __half* __restrict__ th,
                          __half* __restrict__ tl, int K, int N) {
    __shared__ float sh[32][33];
    int n0 = blockIdx.x * 32, k0 = blockIdx.y * 32;
    int tx = threadIdx.x, ty = threadIdx.y;
    #pragma unroll
    for (int i = 0; i < 4; i++)
        sh[ty + i*8][tx] = W[(size_t)(k0 + ty + i*8) * N + n0 + tx];
    __syncthreads();
    #pragma unroll
    for (int i = 0; i < 4; i++) {
        int n = n0 + ty + i*8;
        float v = sh[tx][ty + i*8];
        __half hb = __float2half_rn(v);
        th[(size_t)n * K + k0 + tx] = hb;
        tl[(size_t)n * K + k0 + tx] = __float2half_rn(v - __half2float(hb));
    }
}

__global__ void wtrans_h1(const float* __restrict__ W,
                          __half* __restrict__ th, int K, int N) {
    __shared__ float sh[32][33];
    int n0 = blockIdx.x * 32, k0 = blockIdx.y * 32;
    int tx = threadIdx.x, ty = threadIdx.y;
    #pragma unroll
    for (int i = 0; i < 4; i++)
        sh[ty + i*8][tx] = W[(size_t)(k0 + ty + i*8) * N + n0 + tx];
    __syncthreads();
    #pragma unroll
    for (int i = 0; i < 4; i++) {
        int n = n0 + ty + i*8;
        th[(size_t)n * K + k0 + tx] = __float2half_rn(sh[tx][ty + i*8]);
    }
}

// Combined QKV transpose: grid.z selects Wq/Wk/Wv; writes th + z*MB1.
__global__ void wtrans_qkv(const float* __restrict__ Wq, const float* __restrict__ Wk,
                           const float* __restrict__ Wv, __half* __restrict__ th) {
    __shared__ float sh[32][33];
    const float* W = (blockIdx.z == 0) ? Wq : ((blockIdx.z == 1) ? Wk : Wv);
    __half* dst = th + (size_t)blockIdx.z * MB1;
    int n0 = blockIdx.x * 32, k0 = blockIdx.y * 32;
    int tx = threadIdx.x, ty = threadIdx.y;
    #pragma unroll
    for (int i = 0; i < 4; i++)
        sh[ty + i*8][tx] = W[(size_t)(k0 + ty + i*8) * D_ + n0 + tx];
    __syncthreads();
    #pragma unroll
    for (int i = 0; i < 4; i++) {
        int n = n0 + ty + i*8;
        dst[(size_t)n * D_ + k0 + tx] = __float2half_rn(sh[tx][ty + i*8]);
    }
}

// ---------------------------------------------------------------------------
// Reductions
// ---------------------------------------------------------------------------
__device__ __forceinline__ float warpSum(float v) {
    #pragma unroll
    for (int o = 16; o; o >>= 1) v += __shfl_xor_sync(0xffffffffu, v, o);
    return v;
}
__device__ __forceinline__ float blockSum(float v, float* sh) {
    int tid = threadIdx.x, lane = tid & 31, w = tid >> 5;
    v = warpSum(v);
    if (lane == 0) sh[w] = v;
    __syncthreads();
    float t = sh[0];
    #pragma unroll
    for (int i = 1; i < 8; i++) t += sh[i];
    __syncthreads();
    return t;
}

// ---------------------------------------------------------------------------
// PE + fused embed (writes x fp32 and fp16 copy)
// ---------------------------------------------------------------------------
__global__ void pe_kernel(float* __restrict__ pe) {
    int idx = blockIdx.x * blockDim.x + threadIdx.x;
    if (idx >= B_*D_) return;
    int b = idx / D_, d = idx % D_;
    int i = d >> 1;
    double c = -log(10000.0) / (double)D_;
    float divf = (float)exp((double)(2*i) * c);
    float ang  = (float)b / divf;
    double ad  = (double)ang;
    pe[idx] = (d & 1) ? (float)cos(ad) : (float)sin(ad);
}

__global__ void embed_split(const int* __restrict__ src,
                            const float* __restrict__ emb,
                            const float* __restrict__ pe,
                            float* __restrict__ x,
                            __half* __restrict__ xa) {
    int idx = blockIdx.x * blockDim.x + threadIdx.x;
    if (idx >= M_*D_) return;
    int d  = idx & (D_-1);
    int bs = idx >> 10;
    int b  = bs >> 11;
    float v = emb[(size_t)src[bs]*D_ + d] + pe[b*D_ + d];
    x[idx] = v;
    xa[idx] = __float2half_rn(v);
}

// ---------------------------------------------------------------------------
// out = LayerNorm(x + r) * g + be, with fused fp16 copy
// ---------------------------------------------------------------------------
__global__ __launch_bounds__(256)
void add_ln_split(const float* __restrict__ x, const float* __restrict__ rr,
                  const float* __restrict__ g, const float* __restrict__ be,
                  float* __restrict__ out, __half* __restrict__ xa,
                  int do_split) {
    __shared__ float sh[8];
    int m = blockIdx.x, tid = threadIdx.x;
    float4 v = *(const float4*)(x + (size_t)m*D_ + tid*4);
    float4 rv = *(const float4*)(rr + (size_t)m*D_ + tid*4);
    v.x += rv.x; v.y += rv.y; v.z += rv.z; v.w += rv.w;
    float s = v.x + v.y + v.z + v.w;
    s = blockSum(s, sh);
    float mean = s * (1.0f / D_);
    float d0 = v.x - mean, d1 = v.y - mean, d2 = v.z - mean, d3 = v.w - mean;
    float sq = d0*d0 + d1*d1 + d2*d2 + d3*d3;
    sq = blockSum(sq, sh);
    float var = sq * (1.0f / D_);
    float rstd = rsqrtf(var + 1e-5f);
    float4 gg = *(const float4*)(g + tid*4);
    float4 bb = *(const float4*)(be + tid*4);
    float4 o;
    o.x = d0*rstd*gg.x + bb.x;
    o.y = d1*rstd*gg.y + bb.y;
    o.z = d2*rstd*gg.z + bb.z;
    o.w = d3*rstd*gg.w + bb.w;
    *(float4*)(out + (size_t)m*D_ + tid*4) = o;
    if (do_split) {
        size_t p = (size_t)m*D_ + tid*4;
        *(__half2*)(xa + p)     = __floats2half2_rn(o.x, o.y);
        *(__half2*)(xa + p + 2) = __floats2half2_rn(o.z, o.w);
    }
}

// ---------------------------------------------------------------------------
// Launch
// ---------------------------------------------------------------------------
extern "C" void kernel_launch(void* const* d_in, const int* in_sizes, int n_in,
                              void* d_out, int out_size) {
    const int*   src  = (const int*)  d_in[0];
    const int*   mask = (const int*)  d_in[1];
    const float* emb  = (const float*)d_in[2];
    const float* Wq   = (const float*)d_in[3];
    const float* bq   = (const float*)d_in[4];
    const float* Wk   = (const float*)d_in[5];
    const float* bk   = (const float*)d_in[6];
    const float* Wv   = (const float*)d_in[7];
    const float* bv   = (const float*)d_in[8];
    const float* Wo   = (const float*)d_in[9];
    const float* bo   = (const float*)d_in[10];
    const float* W1   = (const float*)d_in[11];
    const float* b1   = (const float*)d_in[12];
    const float* W2   = (const float*)d_in[13];
    const float* b2   = (const float*)d_in[14];
    const float* g1   = (const float*)d_in[15];
    const float* be1  = (const float*)d_in[16];
    const float* g2   = (const float*)d_in[17];
    const float* be2  = (const float*)d_in[18];
    float* out = (float*)d_out;

    float *x, *r, *pe;
    __half *wth, *wtl, *xa, *ha, *oa, *qh, *kh, *vh, *vt;
    cudaGetSymbolAddress((void**)&x,  g_x);
    cudaGetSymbolAddress((void**)&r,  g_r);
    cudaGetSymbolAddress((void**)&pe, g_pe);
    cudaGetSymbolAddress((void**)&wth, g_wth);
    cudaGetSymbolAddress((void**)&wtl, g_wtl);
    cudaGetSymbolAddress((void**)&xa, g_xa);
    cudaGetSymbolAddress((void**)&ha, g_ha);
    cudaGetSymbolAddress((void**)&oa, g_oa);
    cudaGetSymbolAddress((void**)&qh, g_qh);
    cudaGetSymbolAddress((void**)&kh, g_kh);
    cudaGetSymbolAddress((void**)&vh, g_vh);
    cudaGetSymbolAddress((void**)&vt, g_vt);

    cudaFuncSetAttribute(gemm_f16,   cudaFuncAttributeMaxDynamicSharedMemorySize, F16SMEM);
    cudaFuncSetAttribute(flash_attn, cudaFuncAttributeMaxDynamicSharedMemorySize, FSMEM);

    pe_kernel<<<(B_*D_ + 255)/256, 256>>>(pe);
    embed_split<<<(M_*D_ + 255)/256, 256>>>(src, emb, pe, x, xa);

    dim3 tb(32, 8);
    dim3 gQKV (3*D_/128, M_/128);
    dim3 gProj(D_/128,   M_/128);
    dim3 gFF1 (FF_/128,  M_/128);
    dim3 gFlash(S_/128, BH_);
    dim3 gVT  (S_/64, BH_);

    for (int l = 0; l < L_; l++) {
        size_t wb = (size_t)l * WL_;
        const float* bq_l = bq + (size_t)l*D_;
        const float* bk_l = bk + (size_t)l*D_;
        const float* bv_l = bv + (size_t)l*D_;
        const float* bo_l = bo + (size_t)l*D_;
        const float* b1_l = b1 + (size_t)l*FF_;
        const float* b2_l = b2 + (size_t)l*D_;
        const float* g1_l = g1 + (size_t)l*D_;
        const float* be1_l= be1+ (size_t)l*D_;
        const float* g2_l = g2 + (size_t)l*D_;
        const float* be2_l= be2+ (size_t)l*D_;

        // QKV weights -> single fp16 transpose (one launch, grid.z = 3)
        wtrans_qkv<<<dim3(D_/32, D_/32, 3), tb>>>(Wq + (size_t)l*D_*D_,
                                                  Wk + (size_t)l*D_*D_,
                                                  Wv + (size_t)l*D_*D_, wth + wb);

        // fused QKV GEMM (fp16 1-pass), outputs f16 head layouts
        gemm_f16<<<gQKV, 256, F16SMEM>>>(xa, wth + wb, nullptr,
                                         bq_l, bk_l, bv_l,
                                         nullptr, nullptr, qh, kh, vh,
                                         M_, 3*D_, D_, QKV_MODE, 0);
        vtrans<<<gVT, 256>>>(vh, vt);
        flash_attn<<<gFlash, 256, FSMEM>>>(qh, kh, vt, mask, oa);

        // O-projection (fp16 2-pass — residual-trunk precision headroom)
        wsplit_th<<<dim3(D_/32, D_/32), tb>>>(Wo + (size_t)l*D_*D_,
                                              wth + wb + 3*MB1, wtl + wb + 3*MB1, D_, D_);
        gemm_f16<<<gProj, 256, F16SMEM>>>(oa, wth + wb + 3*MB1, wtl + wb + 3*MB1,
                                          bo_l, nullptr, nullptr,
                                          r, nullptr, nullptr, nullptr, nullptr,
                                          M_, D_, D_, F32_MODE, 1);
        add_ln_split<<<M_, 256>>>(x, r, g1_l, be1_l, x, xa, 1);

        // FF1 (fp16 1-pass: h is fp16-rounded anyway), FF2 (2-pass)
        wtrans_h1<<<dim3(FF_/32, D_/32), tb>>>(W1 + (size_t)l*D_*FF_,
                                               wth + wb + 4*MB1, D_, FF_);
        gemm_f16<<<gFF1, 256, F16SMEM>>>(xa, wth + wb + 4*MB1, nullptr,
                                         b1_l, nullptr, nullptr,
                                         nullptr, ha, nullptr, nullptr, nullptr,
                                         M_, FF_, D_, RELU_MODE, 0);
        wsplit_th<<<dim3(D_/32, FF_/32), tb>>>(W2 + (size_t)l*FF_*D_,
                                               wth + wb + 8*MB1, wtl + wb + 8*MB1, FF_, D_);
        gemm_f16<<<gProj, 256, F16SMEM>>>(ha, wth + wb + 8*MB1, wtl + wb + 8*MB1,
                                          b2_l, nullptr, nullptr,
                                          r, nullptr, nullptr, nullptr, nullptr,
                                          M_, D_, FF_, F32_MODE, 1);

        float* dst = (l == L_-1) ? out : x;
        add_ln_split<<<M_, 256>>>(x, r, g2_l, be2_l, dst, xa, (l < L_-1) ? 1 : 0);
    }
}

// round 16
// speedup vs baseline: 5.5002x; 1.0682x over previous
#include <cuda_runtime.h>
#include <cuda_bf16.h>
#include <cuda_fp16.h>
#include <math.h>
#include <stdint.h>

// ---------------------------------------------------------------------------
// Problem constants
// ---------------------------------------------------------------------------
#define B_  2
#define S_  2048
#define D_  1024
#define H_  16
#define DK_ 64
#define FF_ 4096
#define L_  6
#define M_  (B_*S_)          // 4096 rows
#define BH_ (B_*H_)          // 32

// ---------------------------------------------------------------------------
// Scratch (device globals — no allocations allowed)
// ---------------------------------------------------------------------------
__device__ float g_x[M_*D_];                 // running activation (fp32)
__device__ float g_r[M_*D_];                 // residual branch (fp32)
__device__ float g_pe[B_*D_];

__device__ __half g_xa[M_*D_];               // x as fp16 (GEMM A input)
__device__ __half g_ha[M_*FF_];              // FF hidden as fp16
__device__ __half g_oa[M_*D_];               // attention output as fp16

__device__ __half g_qh[M_*D_];               // Q  [BH, S, 64] f16
__device__ __half g_kh[M_*D_];               // K  [BH, S, 64] f16
__device__ __half g_vh[M_*D_];               // V  [BH, S, 64] f16
__device__ __half g_vt[M_*D_];               // V^T [BH, 64, S] f16

// fp16 weights, transposed to [N,K]:
//   q:+0 k:+1M v:+2M (single) | o hi:+3M (lo in wtl+3M) | w1:+4M (single) | w2:+8M
#define MB1 (1u<<20)
#define WL_ (12u*MB1)
__device__ __half g_wth[6*12*1024*1024];
__device__ __half g_wtl[6*12*1024*1024];

// ---------------------------------------------------------------------------
// PTX helpers
// ---------------------------------------------------------------------------
__device__ __forceinline__ uint32_t smem_u32(const void* p) {
    return (uint32_t)__cvta_generic_to_shared(p);
}
#define CP16(dst, src) \
    asm volatile("cp.async.cg.shared.global [%0], [%1], 16;" :: "r"(dst), "l"(src) : "memory")
#define CP_COMMIT() asm volatile("cp.async.commit_group;" ::: "memory")
#define CP_WAIT2()  asm volatile("cp.async.wait_group 2;" ::: "memory")
#define CP_WAIT1()  asm volatile("cp.async.wait_group 1;" ::: "memory")
#define CP_WAIT0()  asm volatile("cp.async.wait_group 0;" ::: "memory")

#define LDSM4(r, addr) \
    asm volatile("ldmatrix.sync.aligned.m8n8.x4.shared.b16 {%0,%1,%2,%3}, [%4];" \
        : "=r"((r)[0]), "=r"((r)[1]), "=r"((r)[2]), "=r"((r)[3]) : "r"(addr))

#define MMA16816H(c, a, b0, b1) \
    asm volatile("mma.sync.aligned.m16n8k16.row.col.f32.f16.f16.f32 " \
        "{%0,%1,%2,%3}, {%4,%5,%6,%7}, {%8,%9}, {%0,%1,%2,%3};" \
        : "+f"((c)[0]), "+f"((c)[1]), "+f"((c)[2]), "+f"((c)[3]) \
        : "r"((a)[0]), "r"((a)[1]), "r"((a)[2]), "r"((a)[3]), "r"(b0), "r"(b1))

__device__ __forceinline__ uint32_t exp2_f16x2(float lo, float hi) {
    uint32_t t, d;
    asm("cvt.rn.f16x2.f32 %0, %1, %2;" : "=r"(t) : "f"(hi), "f"(lo));
    asm("ex2.approx.f16x2 %0, %1;" : "=r"(d) : "r"(t));
    return d;
}
__device__ __forceinline__ float exp2f_fast(float x) {
    float y; asm("ex2.approx.f32 %0, %1;" : "=f"(y) : "f"(x)); return y;
}

// ---------------------------------------------------------------------------
// Shared GEMM geometry
// ---------------------------------------------------------------------------
#define KC      64
#define PITCHB  144
#define TILEB   (128*PITCHB)          // 18432
// 2 CTAs/SM: per-CTA smem = 108 KB.
//   1-pass: 3 stages x 2 tiles = 6*TILEB = 110592
//   2-pass: 2 stages x 3 tiles = 6*TILEB = 110592
#define F16SMEM (6*TILEB)             // 110592

extern __shared__ char dynsmem[];

// ---------------------------------------------------------------------------
// fp16 GEMM (1- or 2-pass):  C = A[M,K] @ (Bh[+Bl])^T[N,K] + bias.
// modes: 0 = QKV f16 head layouts (N=3072); 1 = ReLU -> f16; 2 = fp32 C.
// 128x128 tile, 8 warps (64x32), K-chunk 64, adaptive pipeline, 2 CTAs/SM.
// ---------------------------------------------------------------------------
#define QKV_MODE  0
#define RELU_MODE 1
#define F32_MODE  2

__global__ __launch_bounds__(256, 2)
void gemm_f16(const __half* __restrict__ A,
              const __half* __restrict__ Bh, const __half* __restrict__ Bl,
              const float* __restrict__ bias0, const float* __restrict__ bias1,
              const float* __restrict__ bias2,
              float* __restrict__ C, __half* __restrict__ Hout,
              __half* __restrict__ Qout, __half* __restrict__ Kout,
              __half* __restrict__ Vout,
              int M, int N, int K, int mode, int twopass) {
    uint32_t sb = smem_u32(dynsmem);
    int tid = threadIdx.x, lane = tid & 31, wid = tid >> 5;
    int wm = wid >> 2, wn = wid & 3;
    int m0 = blockIdx.y * 128, n0 = blockIdx.x * 128;

    float acc[4][4][4];
    #pragma unroll
    for (int i = 0; i < 4; i++)
        #pragma unroll
        for (int j = 0; j < 4; j++)
            #pragma unroll
            for (int q = 0; q < 4; q++) acc[i][j][q] = 0.f;

    int seg = tid & 7, rb = tid >> 3;
    const __half* gsrc[3];
    gsrc[0] = A  + (size_t)m0 * K;
    gsrc[1] = Bh + (size_t)n0 * K;
    gsrc[2] = twopass ? (Bl + (size_t)n0 * K) : gsrc[1];

    const int ntile = twopass ? 3 : 2;
    const int NS    = twopass ? 2 : 3;       // pipeline stages
    const int stgsz = ntile * TILEB;         // 55296 or 36864

    int lrow = lane & 15, lk16 = (lane >> 4) * 16;
    uint32_t aoff = (uint32_t)((wm*64 + lrow) * PITCHB) + lk16;
    uint32_t boff = (uint32_t)((wn*32 + lrow) * PITCHB) + lk16;

    int nc = K / KC;

    // prologue: chunks 0..NS-2
    for (int s2 = 0; s2 < NS-1; s2++) {
        for (int t = 0; t < ntile; t++)
            #pragma unroll
            for (int i = 0; i < 4; i++) {
                int row = rb + i * 32;
                CP16(sb + s2*stgsz + t*TILEB + (uint32_t)(row * PITCHB + seg * 16),
                     (const char*)(gsrc[t] + (size_t)row * K + s2*KC) + seg * 16);
            }
        CP_COMMIT();
    }

    for (int c = 0; c < nc; c++) {
        if (c + NS - 1 < nc) {
            int ns = (c + NS - 1) % NS;
            int k0 = (c + NS - 1) * KC;
            for (int t = 0; t < ntile; t++)
                #pragma unroll
                for (int i = 0; i < 4; i++) {
                    int row = rb + i * 32;
                    CP16(sb + ns*stgsz + t*TILEB + (uint32_t)(row * PITCHB + seg * 16),
                         (const char*)(gsrc[t] + (size_t)row * K + k0) + seg * 16);
                }
            CP_COMMIT();
        }
        // pending groups after chunk c completes
        int last = (c + NS - 1 < nc) ? (c + NS - 1) : (nc - 1);
        int pend = last - c;
        if (pend <= 0)      CP_WAIT0();
        else if (pend == 1) CP_WAIT1();
        else                CP_WAIT2();
        __syncthreads();

        uint32_t base = sb + (c % NS) * stgsz;
        #pragma unroll
        for (int kk = 0; kk < KC; kk += 16) {
            uint32_t a4[4][4], bb[2][4];
            #pragma unroll
            for (int mt = 0; mt < 4; mt++)
                LDSM4(a4[mt], base + aoff + mt*(16*PITCHB) + kk*2);
            #pragma unroll
            for (int nt2 = 0; nt2 < 2; nt2++)
                LDSM4(bb[nt2], base + TILEB + boff + nt2*(16*PITCHB) + kk*2);
            #pragma unroll
            for (int mt = 0; mt < 4; mt++)               // A*Bh
                #pragma unroll
                for (int nt = 0; nt < 4; nt++)
                    MMA16816H(acc[mt][nt], a4[mt], bb[nt>>1][nt&1], bb[nt>>1][2+(nt&1)]);
            if (twopass) {
                #pragma unroll
                for (int nt2 = 0; nt2 < 2; nt2++)        // reuse bb for Bl
                    LDSM4(bb[nt2], base + 2*TILEB + boff + nt2*(16*PITCHB) + kk*2);
                #pragma unroll
                for (int mt = 0; mt < 4; mt++)           // A*Bl
                    #pragma unroll
                    for (int nt = 0; nt < 4; nt++)
                        MMA16816H(acc[mt][nt], a4[mt], bb[nt>>1][nt&1], bb[nt>>1][2+(nt&1)]);
            }
        }
        __syncthreads();
    }

    int r0 = lane >> 2, cl = (lane & 3) * 2;
    int msel = n0 >> 10;
    const float* bias = (mode == QKV_MODE)
                      ? (msel == 0 ? bias0 : (msel == 1 ? bias1 : bias2))
                      : bias0;
    #pragma unroll
    for (int nt = 0; nt < 4; nt++) {
        int col  = n0 + wn*32 + nt*8 + cl;
        int ncol = (mode == QKV_MODE) ? (col & 1023) : col;
        float bx = bias[ncol], by = bias[ncol+1];
        #pragma unroll
        for (int mt = 0; mt < 4; mt++) {
            int row = m0 + wm*64 + mt*16 + r0;
            float v0 = acc[mt][nt][0] + bx, v1 = acc[mt][nt][1] + by;
            float v2 = acc[mt][nt][2] + bx, v3 = acc[mt][nt][3] + by;
            if (mode == F32_MODE) {
                *(float2*)(C + (size_t)row * N + col)       = make_float2(v0, v1);
                *(float2*)(C + (size_t)(row + 8) * N + col) = make_float2(v2, v3);
            } else if (mode == RELU_MODE) {
                v0 = fmaxf(v0, 0.f); v1 = fmaxf(v1, 0.f);
                v2 = fmaxf(v2, 0.f); v3 = fmaxf(v3, 0.f);
                *(__half2*)(Hout + (size_t)row * N + col)     = __floats2half2_rn(v0, v1);
                *(__half2*)(Hout + (size_t)(row+8) * N + col) = __floats2half2_rn(v2, v3);
            } else {                                     // QKV f16 head layouts
                int b = row >> 11, sidx = row & 2047;
                int hh = ncol >> 6, dd = ncol & 63;
                size_t base0 = (((size_t)b*H_ + hh)*S_ + sidx)*64 + dd;
                __half* dst = (msel == 0) ? Qout : ((msel == 1) ? Kout : Vout);
                *(__half2*)(dst + base0)        = __floats2half2_rn(v0, v1);
                *(__half2*)(dst + base0 + 8*64) = __floats2half2_rn(v2, v3);
            }
        }
    }
}

// ---------------------------------------------------------------------------
// V transpose: [BH,S,64] f16 -> [BH,64,S] f16, coalesced both sides.
// ---------------------------------------------------------------------------
__global__ __launch_bounds__(256)
void vtrans(const __half* __restrict__ vh, __half* __restrict__ vt) {
    __shared__ __half sh[64][65];
    int bh = blockIdx.y, s0 = blockIdx.x * 64;
    int tx = threadIdx.x & 31, ty = threadIdx.x >> 5;
    const __half* src = vh + ((size_t)bh*S_ + s0) * 64;
    #pragma unroll
    for (int i = 0; i < 8; i++) {
        int row = ty + i*8;
        __half2 v2 = *(const __half2*)(src + (size_t)row*64 + tx*2);
        sh[row][tx*2]   = __low2half(v2);
        sh[row][tx*2+1] = __high2half(v2);
    }
    __syncthreads();
    __half* dst = vt + (size_t)bh*64*S_ + s0;
    #pragma unroll
    for (int i = 0; i < 8; i++) {
        int dcol = ty + i*8;
        __half2 o = __halves2half2(sh[tx*2][dcol], sh[tx*2+1][dcol]);
        *(__half2*)(dst + (size_t)dcol*S_ + tx*2) = o;
    }
}

// ---------------------------------------------------------------------------
// Fused flash attention.  Q,K: [BH,S,64] f16.  Vt: [BH,64,S] f16.
// Output: fp16 O, layout [M, D].
// ---------------------------------------------------------------------------
#define FQP 144
#define QSZ (128*FQP)
#define FVP 272
#define VSZ (64*FVP)
#define MSZ 512
#define STG (QSZ + VSZ + MSZ)
#define FSMEM (QSZ + 2*STG)           // 91136

#define ONES_H2 0x3C003C00u

__global__ __launch_bounds__(256, 1)
void flash_attn(const __half* __restrict__ qh,
                const __half* __restrict__ kh,
                const __half* __restrict__ vt,
                const int* __restrict__ mask,
                __half* __restrict__ Oa) {
    uint32_t sb = smem_u32(dynsmem);
    int tid = threadIdx.x, lane = tid & 31, w = tid >> 5;
    int bh = blockIdx.y, q0 = blockIdx.x * 128;
    int b = bh >> 4, h = bh & 15;

    const __half* qg = qh + ((size_t)bh*S_ + q0) * 64;
    const __half* kg = kh + (size_t)bh*S_ * 64;
    const __half* vg = vt + (size_t)bh*64 * S_;
    const int* mg = mask + b*S_;

    int seg = tid & 7,  rb  = tid >> 3;
    int vseg = tid & 15, vrb = tid >> 4;

    #pragma unroll
    for (int i = 0; i < 4; i++) {
        int row = rb + i * 32;
        CP16(sb + (uint32_t)(row*FQP + seg*16),
             (const char*)(qg + (size_t)row*64) + seg*16);
        CP16(sb + QSZ + (uint32_t)(row*FQP + seg*16),
             (const char*)(kg + (size_t)row*64) + seg*16);
    }
    #pragma unroll
    for (int i = 0; i < 4; i++) {
        int row = vrb + i * 16;
        CP16(sb + QSZ + QSZ + (uint32_t)(row*FVP + vseg*16),
             (const char*)(vg + (size_t)row*S_) + vseg*16);
    }
    if (tid < 32) CP16(sb + QSZ + QSZ + VSZ + tid*16, (const char*)mg + tid*16);
    CP_COMMIT();

    uint32_t aoffQ = (uint32_t)((w*16 + (lane&15))*FQP) + (lane>>4)*16;
    uint32_t koff  = (uint32_t)((lane&15)*FQP) + (lane>>4)*16;
    uint32_t voff  = (uint32_t)((lane&15)*FVP) + (lane>>4)*16;

    float m0 = -INFINITY, m1 = -INFINITY;
    float oacc[8][4], lacc[4];
    #pragma unroll
    for (int i = 0; i < 8; i++)
        #pragma unroll
        for (int q = 0; q < 4; q++) oacc[i][q] = 0.f;
    #pragma unroll
    for (int q = 0; q < 4; q++) lacc[q] = 0.f;

    const float SCALE = 0.0450842201736734f;   // log2(e)/32
    const float MASKNEG = -4.5e7f;

    for (int j = 0; j < S_/128; j++) {
        if (j + 1 < S_/128) {
            uint32_t stg2 = sb + QSZ + ((j+1)&1)*STG;
            const char* ks = (const char*)(kg + (size_t)(j+1)*128*64);
            #pragma unroll
            for (int i = 0; i < 4; i++) {
                int row = rb + i * 32;
                CP16(stg2 + (uint32_t)(row*FQP + seg*16), ks + (size_t)row*128 + seg*16);
            }
            #pragma unroll
            for (int i = 0; i < 4; i++) {
                int row = vrb + i * 16;
                CP16(stg2 + QSZ + (uint32_t)(row*FVP + vseg*16),
                     (const char*)(vg + (size_t)row*S_ + (j+1)*128) + vseg*16);
            }
            if (tid < 32) CP16(stg2 + QSZ + VSZ + tid*16,
                               (const char*)(mg + (j+1)*128) + tid*16);
            CP_COMMIT();
            CP_WAIT1();
        } else {
            CP_WAIT0();
        }
        __syncthreads();

        uint32_t stg = sb + QSZ + (j&1)*STG;
        const int* msk = (const int*)(dynsmem + QSZ + (j&1)*STG + QSZ + VSZ);

        float sacc[16][4];
        #pragma unroll
        for (int i = 0; i < 16; i++)
            #pragma unroll
            for (int q = 0; q < 4; q++) sacc[i][q] = 0.f;

        #pragma unroll
        for (int kk = 0; kk < 64; kk += 16) {
            uint32_t af[4];
            LDSM4(af, sb + aoffQ + kk*2);
            #pragma unroll
            for (int nt2 = 0; nt2 < 8; nt2++) {
                uint32_t bf4[4];
                LDSM4(bf4, stg + koff + nt2*(16*FQP) + kk*2);
                MMA16816H(sacc[2*nt2],   af, bf4[0], bf4[2]);
                MMA16816H(sacc[2*nt2+1], af, bf4[1], bf4[3]);
            }
        }

        float rm0 = -INFINITY, rm1 = -INFINITY;
        #pragma unroll
        for (int nt = 0; nt < 16; nt++) {
            int col = nt*8 + (lane&3)*2;
            int2 mk = *(const int2*)(msk + col);
            float s0 = mk.x ? sacc[nt][0]*SCALE : MASKNEG;
            float s1 = mk.y ? sacc[nt][1]*SCALE : MASKNEG;
            float s2 = mk.x ? sacc[nt][2]*SCALE : MASKNEG;
            float s3 = mk.y ? sacc[nt][3]*SCALE : MASKNEG;
            sacc[nt][0] = s0; sacc[nt][1] = s1; sacc[nt][2] = s2; sacc[nt][3] = s3;
            rm0 = fmaxf(rm0, fmaxf(s0, s1));
            rm1 = fmaxf(rm1, fmaxf(s2, s3));
        }
        rm0 = fmaxf(rm0, __shfl_xor_sync(0xffffffffu, rm0, 1));
        rm0 = fmaxf(rm0, __shfl_xor_sync(0xffffffffu, rm0, 2));
        rm1 = fmaxf(rm1, __shfl_xor_sync(0xffffffffu, rm1, 1));
        rm1 = fmaxf(rm1, __shfl_xor_sync(0xffffffffu, rm1, 2));

        float mn0 = fmaxf(m0, rm0), mn1 = fmaxf(m1, rm1);
        float f0 = exp2f_fast(m0 - mn0), f1 = exp2f_fast(m1 - mn1);
        m0 = mn0; m1 = mn1;
        lacc[0] *= f0; lacc[1] *= f0; lacc[2] *= f1; lacc[3] *= f1;
        #pragma unroll
        for (int i = 0; i < 8; i++) {
            oacc[i][0] *= f0; oacc[i][1] *= f0;
            oacc[i][2] *= f1; oacc[i][3] *= f1;
        }

        #pragma unroll
        for (int t = 0; t < 8; t++) {
            uint32_t pa[4];
            pa[0] = exp2_f16x2(sacc[2*t][0] - m0,   sacc[2*t][1] - m0);
            pa[1] = exp2_f16x2(sacc[2*t][2] - m1,   sacc[2*t][3] - m1);
            pa[2] = exp2_f16x2(sacc[2*t+1][0] - m0, sacc[2*t+1][1] - m0);
            pa[3] = exp2_f16x2(sacc[2*t+1][2] - m1, sacc[2*t+1][3] - m1);
            MMA16816H(lacc, pa, ONES_H2, ONES_H2);
            #pragma unroll
            for (int nt2 = 0; nt2 < 4; nt2++) {
                uint32_t vf4[4];
                LDSM4(vf4, stg + QSZ + voff + nt2*(16*FVP) + t*32);
                MMA16816H(oacc[2*nt2],   pa, vf4[0], vf4[2]);
                MMA16816H(oacc[2*nt2+1], pa, vf4[1], vf4[3]);
            }
        }
        __syncthreads();
    }

    float il0 = 1.f / lacc[0], il1 = 1.f / lacc[2];
    int r0 = lane >> 2, cl = (lane & 3) * 2;
    int qrow = q0 + w*16 + r0;
    size_t gr0 = (size_t)(b*S_ + qrow) * D_;
    size_t gr1 = gr0 + (size_t)8 * D_;
    #pragma unroll
    for (int nt2 = 0; nt2 < 8; nt2++) {
        int col = h*64 + nt2*8 + cl;
        *(__half2*)(Oa + gr0 + col) =
            __floats2half2_rn(oacc[nt2][0]*il0, oacc[nt2][1]*il0);
        *(__half2*)(Oa + gr1 + col) =
            __floats2half2_rn(oacc[nt2][2]*il1, oacc[nt2][3]*il1);
    }
}

// ---------------------------------------------------------------------------
// Weight transpose kernels:  W fp32 [K,N] -> [N,K] fp16 (single or split pair)
// ---------------------------------------------------------------------------
__global__ void wsplit_th(const float* __restrict__ W,
                          __half* __restrict__ th,
                          __half* __restrict__ tl, int K, int N) {
    __shared__ float sh[32][33];
    int n0 = blockIdx.x * 32, k0 = blockIdx.y * 32;
    int tx = threadIdx.x, ty = threadIdx.y;
    #pragma unroll
    for (int i = 0; i < 4; i++)
        sh[ty + i*8][tx] = W[(size_t)(k0 + ty + i*8) * N + n0 + tx];
    __syncthreads();
    #pragma unroll
    for (int i = 0; i < 4; i++) {
        int n = n0 + ty + i*8;
        float v = sh[tx][ty + i*8];
        __half hb = __float2half_rn(v);
        th[(size_t)n * K + k0 + tx] = hb;
        tl[(size_t)n * K + k0 + tx] = __float2half_rn(v - __half2float(hb));
    }
}

__global__ void wtrans_h1(const float* __restrict__ W,
                          __half* __restrict__ th, int K, int N) {
    __shared__ float sh[32][33];
    int n0 = blockIdx.x * 32, k0 = blockIdx.y * 32;
    int tx = threadIdx.x, ty = threadIdx.y;
    #pragma unroll
    for (int i = 0; i < 4; i++)
        sh[ty + i*8][tx] = W[(size_t)(k0 + ty + i*8) * N + n0 + tx];
    __syncthreads();
    #pragma unroll
    for (int i = 0; i < 4; i++) {
        int n = n0 + ty + i*8;
        th[(size_t)n * K + k0 + tx] = __float2half_rn(sh[tx][ty + i*8]);
    }
}

// Combined QKV transpose: grid.z selects Wq/Wk/Wv; writes th + z*MB1.
__global__ void wtrans_qkv(const float* __restrict__ Wq, const float* __restrict__ Wk,
                           const float* __restrict__ Wv, __half* __restrict__ th) {
    __shared__ float sh[32][33];
    const float* W = (blockIdx.z == 0) ? Wq : ((blockIdx.z == 1) ? Wk : Wv);
    __half* dst = th + (size_t)blockIdx.z * MB1;
    int n0 = blockIdx.x * 32, k0 = blockIdx.y * 32;
    int tx = threadIdx.x, ty = threadIdx.y;
    #pragma unroll
    for (int i = 0; i < 4; i++)
        sh[ty + i*8][tx] = W[(size_t)(k0 + ty + i*8) * D_ + n0 + tx];
    __syncthreads();
    #pragma unroll
    for (int i = 0; i < 4; i++) {
        int n = n0 + ty + i*8;
        dst[(size_t)n * D_ + k0 + tx] = __float2half_rn(sh[tx][ty + i*8]);
    }
}

// ---------------------------------------------------------------------------
// Reductions
// ---------------------------------------------------------------------------
__device__ __forceinline__ float warpSum(float v) {
    #pragma unroll
    for (int o = 16; o; o >>= 1) v += __shfl_xor_sync(0xffffffffu, v, o);
    return v;
}
__device__ __forceinline__ float blockSum(float v, float* sh) {
    int tid = threadIdx.x, lane = tid & 31, w = tid >> 5;
    v = warpSum(v);
    if (lane == 0) sh[w] = v;
    __syncthreads();
    float t = sh[0];
    #pragma unroll
    for (int i = 1; i < 8; i++) t += sh[i];
    __syncthreads();
    return t;
}

// ---------------------------------------------------------------------------
// PE + fused embed (writes x fp32 and fp16 copy)
// ---------------------------------------------------------------------------
__global__ void pe_kernel(float* __restrict__ pe) {
    int idx = blockIdx.x * blockDim.x + threadIdx.x;
    if (idx >= B_*D_) return;
    int b = idx / D_, d = idx % D_;
    int i = d >> 1;
    double c = -log(10000.0) / (double)D_;
    float divf = (float)exp((double)(2*i) * c);
    float ang  = (float)b / divf;
    double ad  = (double)ang;
    pe[idx] = (d & 1) ? (float)cos(ad) : (float)sin(ad);
}

__global__ void embed_split(const int* __restrict__ src,
                            const float* __restrict__ emb,
                            const float* __restrict__ pe,
                            float* __restrict__ x,
                            __half* __restrict__ xa) {
    int idx = blockIdx.x * blockDim.x + threadIdx.x;
    if (idx >= M_*D_) return;
    int d  = idx & (D_-1);
    int bs = idx >> 10;
    int b  = bs >> 11;
    float v = emb[(size_t)src[bs]*D_ + d] + pe[b*D_ + d];
    x[idx] = v;
    xa[idx] = __float2half_rn(v);
}

// ---------------------------------------------------------------------------
// out = LayerNorm(x + r) * g + be, with fused fp16 copy
// ---------------------------------------------------------------------------
__global__ __launch_bounds__(256)
void add_ln_split(const float* __restrict__ x, const float* __restrict__ rr,
                  const float* __restrict__ g, const float* __restrict__ be,
                  float* __restrict__ out, __half* __restrict__ xa,
                  int do_split) {
    __shared__ float sh[8];
    int m = blockIdx.x, tid = threadIdx.x;
    float4 v = *(const float4*)(x + (size_t)m*D_ + tid*4);
    float4 rv = *(const float4*)(rr + (size_t)m*D_ + tid*4);
    v.x += rv.x; v.y += rv.y; v.z += rv.z; v.w += rv.w;
    float s = v.x + v.y + v.z + v.w;
    s = blockSum(s, sh);
    float mean = s * (1.0f / D_);
    float d0 = v.x - mean, d1 = v.y - mean, d2 = v.z - mean, d3 = v.w - mean;
    float sq = d0*d0 + d1*d1 + d2*d2 + d3*d3;
    sq = blockSum(sq, sh);
    float var = sq * (1.0f / D_);
    float rstd = rsqrtf(var + 1e-5f);
    float4 gg = *(const float4*)(g + tid*4);
    float4 bb = *(const float4*)(be + tid*4);
    float4 o;
    o.x = d0*rstd*gg.x + bb.x;
    o.y = d1*rstd*gg.y + bb.y;
    o.z = d2*rstd*gg.z + bb.z;
    o.w = d3*rstd*gg.w + bb.w;
    *(float4*)(out + (size_t)m*D_ + tid*4) = o;
    if (do_split) {
        size_t p = (size_t)m*D_ + tid*4;
        *(__half2*)(xa + p)     = __floats2half2_rn(o.x, o.y);
        *(__half2*)(xa + p + 2) = __floats2half2_rn(o.z, o.w);
    }
}

// ---------------------------------------------------------------------------
// Launch
// ---------------------------------------------------------------------------
extern "C" void kernel_launch(void* const* d_in, const int* in_sizes, int n_in,
                              void* d_out, int out_size) {
    const int*   src  = (const int*)  d_in[0];
    const int*   mask = (const int*)  d_in[1];
    const float* emb  = (const float*)d_in[2];
    const float* Wq   = (const float*)d_in[3];
    const float* bq   = (const float*)d_in[4];
    const float* Wk   = (const float*)d_in[5];
    const float* bk   = (const float*)d_in[6];
    const float* Wv   = (const float*)d_in[7];
    const float* bv   = (const float*)d_in[8];
    const float* Wo   = (const float*)d_in[9];
    const float* bo   = (const float*)d_in[10];
    const float* W1   = (const float*)d_in[11];
    const float* b1   = (const float*)d_in[12];
    const float* W2   = (const float*)d_in[13];
    const float* b2   = (const float*)d_in[14];
    const float* g1   = (const float*)d_in[15];
    const float* be1  = (const float*)d_in[16];
    const float* g2   = (const float*)d_in[17];
    const float* be2  = (const float*)d_in[18];
    float* out = (float*)d_out;

    float *x, *r, *pe;
    __half *wth, *wtl, *xa, *ha, *oa, *qh, *kh, *vh, *vt;
    cudaGetSymbolAddress((void**)&x,  g_x);
    cudaGetSymbolAddress((void**)&r,  g_r);
    cudaGetSymbolAddress((void**)&pe, g_pe);
    cudaGetSymbolAddress((void**)&wth, g_wth);
    cudaGetSymbolAddress((void**)&wtl, g_wtl);
    cudaGetSymbolAddress((void**)&xa, g_xa);
    cudaGetSymbolAddress((void**)&ha, g_ha);
    cudaGetSymbolAddress((void**)&oa, g_oa);
    cudaGetSymbolAddress((void**)&qh, g_qh);
    cudaGetSymbolAddress((void**)&kh, g_kh);
    cudaGetSymbolAddress((void**)&vh, g_vh);
    cudaGetSymbolAddress((void**)&vt, g_vt);

    cudaFuncSetAttribute(gemm_f16,   cudaFuncAttributeMaxDynamicSharedMemorySize, F16SMEM);
    cudaFuncSetAttribute(flash_attn, cudaFuncAttributeMaxDynamicSharedMemorySize, FSMEM);

    pe_kernel<<<(B_*D_ + 255)/256, 256>>>(pe);
    embed_split<<<(M_*D_ + 255)/256, 256>>>(src, emb, pe, x, xa);

    dim3 tb(32, 8);
    dim3 gQKV (3*D_/128, M_/128);
    dim3 gProj(D_/128,   M_/128);
    dim3 gFF1 (FF_/128,  M_/128);
    dim3 gFlash(S_/128, BH_);
    dim3 gVT  (S_/64, BH_);

    for (int l = 0; l < L_; l++) {
        size_t wb = (size_t)l * WL_;
        const float* bq_l = bq + (size_t)l*D_;
        const float* bk_l = bk + (size_t)l*D_;
        const float* bv_l = bv + (size_t)l*D_;
        const float* bo_l = bo + (size_t)l*D_;
        const float* b1_l = b1 + (size_t)l*FF_;
        const float* b2_l = b2 + (size_t)l*D_;
        const float* g1_l = g1 + (size_t)l*D_;
        const float* be1_l= be1+ (size_t)l*D_;
        const float* g2_l = g2 + (size_t)l*D_;
        const float* be2_l= be2+ (size_t)l*D_;

        // QKV weights -> single fp16 transpose (one launch, grid.z = 3)
        wtrans_qkv<<<dim3(D_/32, D_/32, 3), tb>>>(Wq + (size_t)l*D_*D_,
                                                  Wk + (size_t)l*D_*D_,
                                                  Wv + (size_t)l*D_*D_, wth + wb);

        // fused QKV GEMM (fp16 1-pass), outputs f16 head layouts
        gemm_f16<<<gQKV, 256, F16SMEM>>>(xa, wth + wb, nullptr,
                                         bq_l, bk_l, bv_l,
                                         nullptr, nullptr, qh, kh, vh,
                                         M_, 3*D_, D_, QKV_MODE, 0);
        vtrans<<<gVT, 256>>>(vh, vt);
        flash_attn<<<gFlash, 256, FSMEM>>>(qh, kh, vt, mask, oa);

        // O-projection (fp16 2-pass — residual-trunk precision headroom)
        wsplit_th<<<dim3(D_/32, D_/32), tb>>>(Wo + (size_t)l*D_*D_,
                                              wth + wb + 3*MB1, wtl + wb + 3*MB1, D_, D_);
        gemm_f16<<<gProj, 256, F16SMEM>>>(oa, wth + wb + 3*MB1, wtl + wb + 3*MB1,
                                          bo_l, nullptr, nullptr,
                                          r, nullptr, nullptr, nullptr, nullptr,
                                          M_, D_, D_, F32_MODE, 1);
        add_ln_split<<<M_, 256>>>(x, r, g1_l, be1_l, x, xa, 1);

        // FF1 (fp16 1-pass: h is fp16-rounded anyway), FF2 (2-pass)
        wtrans_h1<<<dim3(FF_/32, D_/32), tb>>>(W1 + (size_t)l*D_*FF_,
                                               wth + wb + 4*MB1, D_, FF_);
        gemm_f16<<<gFF1, 256, F16SMEM>>>(xa, wth + wb + 4*MB1, nullptr,
                                         b1_l, nullptr, nullptr,
                                         nullptr, ha, nullptr, nullptr, nullptr,
                                         M_, FF_, D_, RELU_MODE, 0);
        wsplit_th<<<dim3(D_/32, FF_/32), tb>>>(W2 + (size_t)l*FF_*D_,
                                               wth + wb + 8*MB1, wtl + wb + 8*MB1, FF_, D_);
        gemm_f16<<<gProj, 256, F16SMEM>>>(ha, wth + wb + 8*MB1, wtl + wb + 8*MB1,
                                          b2_l, nullptr, nullptr,
                                          r, nullptr, nullptr, nullptr, nullptr,
                                          M_, D_, FF_, F32_MODE, 1);

        float* dst = (l == L_-1) ? out : x;
        add_ln_split<<<M_, 256>>>(x, r, g2_l, be2_l, dst, xa, (l < L_-1) ? 1 : 0);
    }
}